// round 5
// baseline (speedup 1.0000x reference)
#include <cuda_runtime.h>
#include <cuda_bf16.h>
#include <math.h>
#include <stdint.h>

// ---------------- problem constants ----------------
#define BB 4
#define SS 1024
#define LL 12
#define DD 768
#define HH 12
#define DKK 64
#define DFF 3072
#define VV 50257
#define NTOK (BB*SS)          // 4096

// ---------------- scratch (device globals; no allocs allowed) --------------
__device__ float g_x  [(size_t)NTOK * DD];
__device__ float g_h  [(size_t)NTOK * DD];
__device__ float g_q  [(size_t)NTOK * DD];
__device__ float g_k  [(size_t)NTOK * DD];
__device__ float g_v  [(size_t)NTOK * DD];
__device__ float g_tmp[(size_t)NTOK * DD];
__device__ float g_ff [(size_t)NTOK * DFF];

// ---------------- helpers ----------------
__device__ __forceinline__ uint32_t smem_u32(const void* p) {
    uint32_t a;
    asm("{ .reg .u64 t; cvta.to.shared.u64 t, %1; cvt.u32.u64 %0, t; }"
        : "=r"(a) : "l"(p));
    return a;
}
__device__ __forceinline__ unsigned f2tf(float f) {
    unsigned u;
    asm("cvt.rna.tf32.f32 %0, %1;" : "=r"(u) : "f"(f));
    return u;
}
__device__ __forceinline__ void mma8(float* d, const unsigned* a, const unsigned* b) {
    asm volatile(
        "mma.sync.aligned.m16n8k8.row.col.f32.tf32.tf32.f32 "
        "{%0,%1,%2,%3},{%4,%5,%6,%7},{%8,%9},{%0,%1,%2,%3};"
        : "+f"(d[0]), "+f"(d[1]), "+f"(d[2]), "+f"(d[3])
        : "r"(a[0]), "r"(a[1]), "r"(a[2]), "r"(a[3]), "r"(b[0]), "r"(b[1]));
}
__device__ __forceinline__ void cp16(uint32_t d, const void* g) {
    asm volatile("cp.async.cg.shared.global [%0], [%1], 16;" :: "r"(d), "l"(g));
}
__device__ __forceinline__ void cp16g(uint32_t d, const void* g, int sz) {
    asm volatile("cp.async.cg.shared.global [%0], [%1], 16, %2;"
                 :: "r"(d), "l"(g), "r"(sz));
}

// ---------------- tf32 tensor-core GEMM, 3-stage cp.async pipeline ---------
// C[4096 x N] = A[4096 x K] @ B (+ epilogue)
// BT=false: B row-major [K,N].  BT=true: B row-major [N,K] (C = A @ B^T).
// EPI: 0 none, 1 +Cin, 2 exact GELU
// 128x128 CTA tile, BK=16, 8 warps (4x2), warp tile 32x64.
// smem per stage: A [128][20] f32 | B [16][136] f32 (or [128][20] for BT)
#define AST 20
#define BST 136
#define A_WORDS (128 * AST)                 // 2560

template<int EPI, bool BT>
__global__ __launch_bounds__(256, 2)
void mma_gemm(const float* __restrict__ A,
              const float* __restrict__ B0, const float* __restrict__ B1,
              const float* __restrict__ B2,
              const float* __restrict__ Cin,
              float* __restrict__ C0, float* __restrict__ C1, float* __restrict__ C2,
              int N, int K)
{
    extern __shared__ float gsm[];
    constexpr int B_WORDS = BT ? (128 * AST) : (16 * BST);
    constexpr int STG = A_WORDS + B_WORDS;

    const float* B = (blockIdx.z == 0) ? B0 : ((blockIdx.z == 1) ? B1 : B2);
    float*       C = (blockIdx.z == 0) ? C0 : ((blockIdx.z == 1) ? C1 : C2);

    const int tid  = threadIdx.x;
    const int lane = tid & 31;
    const int warp = tid >> 5;
    const int wm = warp >> 1, wn = warp & 1;      // 4x2 warp grid
    const int lr = lane >> 2, lq = lane & 3;
    const int m0 = blockIdx.y * 128;
    const int n0 = blockIdx.x * 128;

    const uint32_t sbase = smem_u32(gsm);

    float acc[2][8][4];
    #pragma unroll
    for (int i = 0; i < 2; i++)
        #pragma unroll
        for (int j = 0; j < 8; j++)
            #pragma unroll
            for (int t = 0; t < 4; t++) acc[i][j][t] = 0.0f;

    const int nIter = K >> 4;

    // ---- stage loader: 2 float4 for A, 2 for B per thread ----
    auto load_stage = [&](int stg) {
        const int slot = stg % 3;
        const uint32_t sa = sbase + (uint32_t)(slot * STG) * 4u;
        const uint32_t sb = sa + (uint32_t)A_WORDS * 4u;
        const int k0 = stg * 16;
        #pragma unroll
        for (int p = 0; p < 2; p++) {
            int s   = tid * 2 + p;              // 0..511
            int row = s >> 2, kq = (s & 3) * 4;
            cp16(sa + (uint32_t)(row * AST + kq) * 4u,
                 A + (size_t)(m0 + row) * K + k0 + kq);
        }
        if (!BT) {
            #pragma unroll
            for (int p = 0; p < 2; p++) {
                int s  = tid * 2 + p;
                int kr = s >> 5, n4 = (s & 31) * 4;
                cp16(sb + (uint32_t)(kr * BST + n4) * 4u,
                     B + (size_t)(k0 + kr) * N + n0 + n4);
            }
        } else {
            #pragma unroll
            for (int p = 0; p < 2; p++) {
                int s   = tid * 2 + p;
                int row = s >> 2, kq = (s & 3) * 4;
                int n   = n0 + row;
                int ok  = (n < N);
                const float* g = B + (size_t)(ok ? n : 0) * K + k0 + kq;
                cp16g(sb + (uint32_t)(row * AST + kq) * 4u, g, ok ? 16 : 0);
            }
        }
        asm volatile("cp.async.commit_group;" ::: "memory");
    };

    auto compute = [&](int slot) {
        const float* pa = gsm + slot * STG;
        const float* pb = pa + A_WORDS;
        #pragma unroll
        for (int ks = 0; ks < 2; ks++) {
            const int kk = ks * 8;
            unsigned af[2][4];
            #pragma unroll
            for (int mt = 0; mt < 2; mt++) {
                const float* p0 = pa + (wm * 32 + mt * 16 + lr) * AST + kk + lq;
                af[mt][0] = f2tf(p0[0]);
                af[mt][1] = f2tf(p0[8 * AST]);
                af[mt][2] = f2tf(p0[4]);
                af[mt][3] = f2tf(p0[8 * AST + 4]);
            }
            unsigned bf[8][2];
            #pragma unroll
            for (int nt = 0; nt < 8; nt++) {
                if (!BT) {
                    const float* q = pb + (kk + lq) * BST + wn * 64 + nt * 8 + lr;
                    bf[nt][0] = f2tf(q[0]);
                    bf[nt][1] = f2tf(q[4 * BST]);
                } else {
                    const float* q = pb + (wn * 64 + nt * 8 + lr) * AST + kk + lq;
                    bf[nt][0] = f2tf(q[0]);
                    bf[nt][1] = f2tf(q[4]);
                }
            }
            #pragma unroll
            for (int mt = 0; mt < 2; mt++)
                #pragma unroll
                for (int nt = 0; nt < 8; nt++)
                    mma8(acc[mt][nt], af[mt], bf[nt]);
        }
    };

    // ---- pipeline ----
    load_stage(0);
    if (nIter > 1) load_stage(1);
    for (int it = 0; it < nIter; it++) {
        if (it + 1 < nIter) asm volatile("cp.async.wait_group 1;" ::: "memory");
        else                asm volatile("cp.async.wait_group 0;" ::: "memory");
        __syncthreads();
        if (it + 2 < nIter) load_stage(it + 2);
        compute(it % 3);
    }

    // ---- epilogue ----
    #pragma unroll
    for (int mt = 0; mt < 2; mt++) {
        int r0 = m0 + wm * 32 + mt * 16 + lr;
        #pragma unroll
        for (int nt = 0; nt < 8; nt++) {
            int col = n0 + wn * 64 + nt * 8 + lq * 2;
            float* a4 = acc[mt][nt];
            float v00 = a4[0], v01 = a4[1], v10 = a4[2], v11 = a4[3];
            size_t o0 = (size_t)r0 * N + col;
            size_t o1 = (size_t)(r0 + 8) * N + col;
            if (EPI == 1) {
                if (!BT || col + 1 < N) {
                    float2 c0 = *(const float2*)(Cin + o0);
                    float2 c1 = *(const float2*)(Cin + o1);
                    v00 += c0.x; v01 += c0.y; v10 += c1.x; v11 += c1.y;
                }
            }
            if (EPI == 2) {
                v00 = 0.5f * v00 * (1.0f + erff(v00 * 0.70710678118654752f));
                v01 = 0.5f * v01 * (1.0f + erff(v01 * 0.70710678118654752f));
                v10 = 0.5f * v10 * (1.0f + erff(v10 * 0.70710678118654752f));
                v11 = 0.5f * v11 * (1.0f + erff(v11 * 0.70710678118654752f));
            }
            if (!BT) {
                *(float2*)(C + o0) = make_float2(v00, v01);
                *(float2*)(C + o1) = make_float2(v10, v11);
            } else {
                if (col < N)     { C[o0] = v00; C[o1] = v10; }
                if (col + 1 < N) { C[o0 + 1] = v01; C[o1 + 1] = v11; }
            }
        }
    }
}

// ---------------- embedding ----------------
__global__ void embed_kernel(const int* __restrict__ idx,
                             const float* __restrict__ wte,
                             const float* __restrict__ wpe,
                             float* __restrict__ x)
{
    int row = blockIdx.x;
    int s   = row & (SS - 1);
    int tok = idx[row];
    int tid = threadIdx.x;
    #pragma unroll
    for (int l = 0; l < 3; l++) {
        int d = tid + l * 256;
        x[(size_t)row * DD + d] = wte[(size_t)tok * DD + d] + wpe[(size_t)s * DD + d];
    }
}

// ---------------- layernorm ----------------
__global__ void layernorm_kernel(const float* __restrict__ x,
                                 const float* __restrict__ w,
                                 const float* __restrict__ b,
                                 float* __restrict__ y)
{
    int row = blockIdx.x;
    const float* p = x + (size_t)row * DD;
    int tid = threadIdx.x;
    float v0 = p[tid], v1 = p[tid + 256], v2 = p[tid + 512];
    __shared__ float red[256];
    red[tid] = v0 + v1 + v2;
    __syncthreads();
    for (int st = 128; st > 0; st >>= 1) {
        if (tid < st) red[tid] += red[tid + st];
        __syncthreads();
    }
    float mean = red[0] * (1.0f / DD);
    __syncthreads();
    float d0 = v0 - mean, d1 = v1 - mean, d2 = v2 - mean;
    red[tid] = d0 * d0 + d1 * d1 + d2 * d2;
    __syncthreads();
    for (int st = 128; st > 0; st >>= 1) {
        if (tid < st) red[tid] += red[tid + st];
        __syncthreads();
    }
    float rstd = rsqrtf(red[0] * (1.0f / DD) + 1e-5f);
    float* q = y + (size_t)row * DD;
    q[tid]       = d0 * rstd * w[tid]       + b[tid];
    q[tid + 256] = d1 * rstd * w[tid + 256] + b[tid + 256];
    q[tid + 512] = d2 * rstd * w[tid + 512] + b[tid + 512];
}

// ---------------- fused flash attention (tf32 tensor cores, as in R3) ------
#define FA_SQ   0
#define FA_SK   (64*68)
#define FA_SVH  (2*64*68)
#define FA_SVL  (2*64*68 + 64*72)
#define FA_SPST (2*64*68 + 2*64*72)
#define FA_SMEM_WORDS (2*64*68 + 2*64*72 + 4*256)

__global__ __launch_bounds__(128, 2)
void flash_attn_kernel(const float* __restrict__ Q, const float* __restrict__ K,
                       const float* __restrict__ V, float* __restrict__ O)
{
    extern __shared__ unsigned fsm[];
    unsigned* sQ  = fsm + FA_SQ;
    unsigned* sK  = fsm + FA_SK;
    unsigned* sVh = fsm + FA_SVH;
    unsigned* sVl = fsm + FA_SVL;

    const int tid  = threadIdx.x;
    const int lane = tid & 31;
    const int w    = tid >> 5;
    const int lr   = lane >> 2;
    const int lq   = lane & 3;
    const int it   = (SS / 64 - 1) - blockIdx.x;
    const int bh   = blockIdx.y;
    const int b    = bh / HH, h = bh % HH;
    const int i0   = it * 64;

    unsigned* myP = fsm + FA_SPST + w * 256;

    const float* Qb = Q + (size_t)(b * SS + i0) * DD + h * DKK;
    #pragma unroll
    for (int p = 0; p < 8; p++) {
        int idx = tid + p * 128;
        int r = idx >> 4, c4 = (idx & 15) * 4;
        float4 v = *(const float4*)(Qb + (size_t)r * DD + c4);
        unsigned* d = sQ + r * 68 + c4;
        d[0] = f2tf(v.x); d[1] = f2tf(v.y); d[2] = f2tf(v.z); d[3] = f2tf(v.w);
    }

    float oacc[8][4];
    #pragma unroll
    for (int nt = 0; nt < 8; nt++)
        #pragma unroll
        for (int e = 0; e < 4; e++) oacc[nt][e] = 0.0f;
    float m0 = -1e30f, m1 = -1e30f, l0 = 0.0f, l1 = 0.0f;

    for (int j0 = 0; j0 <= i0; j0 += 64) {
        __syncthreads();
        const float* Kb = K + (size_t)(b * SS + j0) * DD + h * DKK;
        const float* Vb = V + (size_t)(b * SS + j0) * DD + h * DKK;
        #pragma unroll
        for (int p = 0; p < 8; p++) {
            int idx = tid + p * 128;
            int r = idx >> 4, c4 = (idx & 15) * 4;
            float4 kv = *(const float4*)(Kb + (size_t)r * DD + c4);
            unsigned* dk = sK + r * 68 + c4;
            dk[0] = f2tf(kv.x); dk[1] = f2tf(kv.y); dk[2] = f2tf(kv.z); dk[3] = f2tf(kv.w);
            float4 vv = *(const float4*)(Vb + (size_t)r * DD + c4);
            unsigned* dh = sVh + r * 72 + c4;
            unsigned* dl = sVl + r * 72 + c4;
            unsigned h0 = f2tf(vv.x); dh[0] = h0; dl[0] = f2tf(vv.x - __uint_as_float(h0));
            unsigned h1 = f2tf(vv.y); dh[1] = h1; dl[1] = f2tf(vv.y - __uint_as_float(h1));
            unsigned h2 = f2tf(vv.z); dh[2] = h2; dl[2] = f2tf(vv.z - __uint_as_float(h2));
            unsigned h3 = f2tf(vv.w); dh[3] = h3; dl[3] = f2tf(vv.w - __uint_as_float(h3));
        }
        __syncthreads();

        float sacc[8][4];
        #pragma unroll
        for (int nt = 0; nt < 8; nt++)
            #pragma unroll
            for (int e = 0; e < 4; e++) sacc[nt][e] = 0.0f;

        #pragma unroll
        for (int kk = 0; kk < 8; kk++) {
            unsigned a[4];
            const unsigned* pa = sQ + (w * 16 + lr) * 68 + kk * 8 + lq;
            a[0] = pa[0]; a[1] = pa[8 * 68]; a[2] = pa[4]; a[3] = pa[8 * 68 + 4];
            #pragma unroll
            for (int nt = 0; nt < 8; nt++) {
                unsigned bf[2];
                const unsigned* pb = sK + (nt * 8 + lr) * 68 + kk * 8 + lq;
                bf[0] = pb[0]; bf[1] = pb[4];
                mma8(sacc[nt], a, bf);
            }
        }

        #pragma unroll
        for (int nt = 0; nt < 8; nt++)
            #pragma unroll
            for (int e = 0; e < 4; e++) sacc[nt][e] *= 0.125f;
        if (j0 == i0) {
            int ii0 = w * 16 + lr, ii1 = ii0 + 8;
            #pragma unroll
            for (int nt = 0; nt < 8; nt++) {
                int jj = nt * 8 + 2 * lq;
                if (jj     > ii0) sacc[nt][0] = -1e30f;
                if (jj + 1 > ii0) sacc[nt][1] = -1e30f;
                if (jj     > ii1) sacc[nt][2] = -1e30f;
                if (jj + 1 > ii1) sacc[nt][3] = -1e30f;
            }
        }

        float rm0 = -1e30f, rm1 = -1e30f;
        #pragma unroll
        for (int nt = 0; nt < 8; nt++) {
            rm0 = fmaxf(rm0, fmaxf(sacc[nt][0], sacc[nt][1]));
            rm1 = fmaxf(rm1, fmaxf(sacc[nt][2], sacc[nt][3]));
        }
        rm0 = fmaxf(rm0, __shfl_xor_sync(0xffffffffu, rm0, 1));
        rm0 = fmaxf(rm0, __shfl_xor_sync(0xffffffffu, rm0, 2));
        rm1 = fmaxf(rm1, __shfl_xor_sync(0xffffffffu, rm1, 1));
        rm1 = fmaxf(rm1, __shfl_xor_sync(0xffffffffu, rm1, 2));
        float mn0 = fmaxf(m0, rm0), mn1 = fmaxf(m1, rm1);
        float f0 = __expf(m0 - mn0), f1 = __expf(m1 - mn1);
        float ps0 = 0.0f, ps1 = 0.0f;
        #pragma unroll
        for (int nt = 0; nt < 8; nt++) {
            float p0 = __expf(sacc[nt][0] - mn0); sacc[nt][0] = p0; ps0 += p0;
            float p1 = __expf(sacc[nt][1] - mn0); sacc[nt][1] = p1; ps0 += p1;
            float p2 = __expf(sacc[nt][2] - mn1); sacc[nt][2] = p2; ps1 += p2;
            float p3 = __expf(sacc[nt][3] - mn1); sacc[nt][3] = p3; ps1 += p3;
        }
        ps0 += __shfl_xor_sync(0xffffffffu, ps0, 1);
        ps0 += __shfl_xor_sync(0xffffffffu, ps0, 2);
        ps1 += __shfl_xor_sync(0xffffffffu, ps1, 1);
        ps1 += __shfl_xor_sync(0xffffffffu, ps1, 2);
        l0 = l0 * f0 + ps0;
        l1 = l1 * f1 + ps1;
        m0 = mn0; m1 = mn1;
        #pragma unroll
        for (int nt = 0; nt < 8; nt++) {
            oacc[nt][0] *= f0; oacc[nt][1] *= f0;
            oacc[nt][2] *= f1; oacc[nt][3] *= f1;
        }

        #pragma unroll
        for (int kk = 0; kk < 8; kk++) {
            float p0 = sacc[kk][0], p1 = sacc[kk][1], p2 = sacc[kk][2], p3 = sacc[kk][3];
            unsigned h0 = f2tf(p0), h1 = f2tf(p1), h2 = f2tf(p2), h3 = f2tf(p3);
            unsigned e0 = f2tf(p0 - __uint_as_float(h0));
            unsigned e1 = f2tf(p1 - __uint_as_float(h1));
            unsigned e2 = f2tf(p2 - __uint_as_float(h2));
            unsigned e3 = f2tf(p3 - __uint_as_float(h3));
            myP[lr * 8 + 2 * lq]             = h0;
            myP[lr * 8 + 2 * lq + 1]         = h1;
            myP[(lr + 8) * 8 + 2 * lq]       = h2;
            myP[(lr + 8) * 8 + 2 * lq + 1]   = h3;
            myP[128 + lr * 8 + 2 * lq]           = e0;
            myP[128 + lr * 8 + 2 * lq + 1]       = e1;
            myP[128 + (lr + 8) * 8 + 2 * lq]     = e2;
            myP[128 + (lr + 8) * 8 + 2 * lq + 1] = e3;
            __syncwarp();
            unsigned ah[4], al[4];
            ah[0] = myP[lr * 8 + lq];
            ah[1] = myP[(lr + 8) * 8 + lq];
            ah[2] = myP[lr * 8 + lq + 4];
            ah[3] = myP[(lr + 8) * 8 + lq + 4];
            al[0] = myP[128 + lr * 8 + lq];
            al[1] = myP[128 + (lr + 8) * 8 + lq];
            al[2] = myP[128 + lr * 8 + lq + 4];
            al[3] = myP[128 + (lr + 8) * 8 + lq + 4];
            __syncwarp();
            #pragma unroll
            for (int nt = 0; nt < 8; nt++) {
                unsigned bhv[2], blv[2];
                const unsigned* pvh = sVh + (kk * 8 + lq) * 72 + nt * 8 + lr;
                bhv[0] = pvh[0]; bhv[1] = pvh[4 * 72];
                const unsigned* pvl = sVl + (kk * 8 + lq) * 72 + nt * 8 + lr;
                blv[0] = pvl[0]; blv[1] = pvl[4 * 72];
                mma8(oacc[nt], ah, bhv);
                mma8(oacc[nt], al, bhv);
                mma8(oacc[nt], ah, blv);
            }
        }
    }

    float inv0 = 1.0f / l0, inv1 = 1.0f / l1;
    int row0 = b * SS + i0 + w * 16 + lr;
    float* Ob = O + (size_t)row0 * DD + h * DKK;
    #pragma unroll
    for (int nt = 0; nt < 8; nt++) {
        int col = nt * 8 + 2 * lq;
        *(float2*)(Ob + col) = make_float2(oacc[nt][0] * inv0, oacc[nt][1] * inv0);
        *(float2*)(Ob + (size_t)8 * DD + col) =
            make_float2(oacc[nt][2] * inv1, oacc[nt][3] * inv1);
    }
}

// ---------------- host launcher ----------------
extern "C" void kernel_launch(void* const* d_in, const int* in_sizes, int n_in,
                              void* d_out, int out_size)
{
    const int*   idx   = (const int*)  d_in[0];
    const float* wte   = (const float*)d_in[1];
    const float* wpe   = (const float*)d_in[2];
    const float* ln1_w = (const float*)d_in[3];
    const float* ln1_b = (const float*)d_in[4];
    const float* wq    = (const float*)d_in[5];
    const float* wk    = (const float*)d_in[6];
    const float* wv    = (const float*)d_in[7];
    const float* wo    = (const float*)d_in[8];
    const float* ln2_w = (const float*)d_in[9];
    const float* ln2_b = (const float*)d_in[10];
    const float* fc1   = (const float*)d_in[11];
    const float* fc2   = (const float*)d_in[12];
    const float* lnf_w = (const float*)d_in[13];
    const float* lnf_b = (const float*)d_in[14];
    float* out = (float*)d_out;

    float *x, *h, *q, *k, *v, *tmp, *ff;
    cudaGetSymbolAddress((void**)&x,   g_x);
    cudaGetSymbolAddress((void**)&h,   g_h);
    cudaGetSymbolAddress((void**)&q,   g_q);
    cudaGetSymbolAddress((void**)&k,   g_k);
    cudaGetSymbolAddress((void**)&v,   g_v);
    cudaGetSymbolAddress((void**)&tmp, g_tmp);
    cudaGetSymbolAddress((void**)&ff,  g_ff);

    const int faSmem = FA_SMEM_WORDS * 4;
    const int gemmSmemN = 3 * (A_WORDS + 16 * BST) * 4;   // 56832
    const int gemmSmemT = 3 * (A_WORDS + 128 * AST) * 4;  // 61440
    cudaFuncSetAttribute(flash_attn_kernel,
                         cudaFuncAttributeMaxDynamicSharedMemorySize, faSmem);
    cudaFuncSetAttribute(mma_gemm<0,false>, cudaFuncAttributeMaxDynamicSharedMemorySize, gemmSmemN);
    cudaFuncSetAttribute(mma_gemm<1,false>, cudaFuncAttributeMaxDynamicSharedMemorySize, gemmSmemN);
    cudaFuncSetAttribute(mma_gemm<2,false>, cudaFuncAttributeMaxDynamicSharedMemorySize, gemmSmemN);
    cudaFuncSetAttribute(mma_gemm<0,true>,  cudaFuncAttributeMaxDynamicSharedMemorySize, gemmSmemT);

    embed_kernel<<<NTOK, 256>>>(idx, wte, wpe, x);

    dim3 gQKV(DD / 128, NTOK / 128, 3);
    dim3 gD  (DD / 128, NTOK / 128, 1);
    dim3 gF  (DFF / 128, NTOK / 128, 1);

    for (int l = 0; l < LL; l++) {
        const float* Wq = wq + (size_t)l * DD * DD;
        const float* Wk = wk + (size_t)l * DD * DD;
        const float* Wv = wv + (size_t)l * DD * DD;
        const float* Wo = wo + (size_t)l * DD * DD;
        const float* W1 = fc1 + (size_t)l * DD * DFF;
        const float* W2 = fc2 + (size_t)l * DFF * DD;

        layernorm_kernel<<<NTOK, 256>>>(x, ln1_w + l * DD, ln1_b + l * DD, h);

        mma_gemm<0,false><<<gQKV, 256, gemmSmemN>>>(h, Wq, Wk, Wv, nullptr,
                                                    q, k, v, DD, DD);

        flash_attn_kernel<<<dim3(SS / 64, BB * HH), 128, faSmem>>>(q, k, v, tmp);

        mma_gemm<1,false><<<gD, 256, gemmSmemN>>>(tmp, Wo, Wo, Wo, x, x, x, x, DD, DD);

        layernorm_kernel<<<NTOK, 256>>>(x, ln2_w + l * DD, ln2_b + l * DD, h);
        mma_gemm<2,false><<<gF, 256, gemmSmemN>>>(h, W1, W1, W1, nullptr,
                                                  ff, ff, ff, DFF, DD);
        mma_gemm<1,false><<<gD, 256, gemmSmemN>>>(ff, W2, W2, W2, x, x, x, x, DD, DFF);
    }

    layernorm_kernel<<<NTOK, 256>>>(x, lnf_w, lnf_b, h);
    mma_gemm<0,true><<<dim3((VV + 127) / 128, NTOK / 128, 1), 256, gemmSmemT>>>(
        h, wte, wte, wte, nullptr, out, out, out, VV, DD);
}

// round 6
// speedup vs baseline: 1.4070x; 1.4070x over previous
#include <cuda_runtime.h>
#include <cuda_bf16.h>
#include <cuda_fp16.h>
#include <math.h>
#include <stdint.h>

// ---------------- problem constants ----------------
#define BB 4
#define SS 1024
#define LL 12
#define DD 768
#define HH 12
#define DKK 64
#define DFF 3072
#define VV 50257
#define NTOK (BB*SS)          // 4096

// ---------------- scratch (device globals; no allocs allowed) --------------
__device__ float g_x  [(size_t)NTOK * DD];
__device__ float g_h  [(size_t)NTOK * DD];
__device__ float g_q  [(size_t)NTOK * DD];
__device__ float g_k  [(size_t)NTOK * DD];
__device__ float g_v  [(size_t)NTOK * DD];
__device__ float g_tmp[(size_t)NTOK * DD];
__device__ float g_ff [(size_t)NTOK * DFF];

// ---------------- helpers ----------------
__device__ __forceinline__ unsigned f2tf(float f) {
    unsigned u;
    asm("cvt.rna.tf32.f32 %0, %1;" : "=r"(u) : "f"(f));
    return u;
}
__device__ __forceinline__ void mma8(float* d, const unsigned* a, const unsigned* b) {
    asm volatile(
        "mma.sync.aligned.m16n8k8.row.col.f32.tf32.tf32.f32 "
        "{%0,%1,%2,%3},{%4,%5,%6,%7},{%8,%9},{%0,%1,%2,%3};"
        : "+f"(d[0]), "+f"(d[1]), "+f"(d[2]), "+f"(d[3])
        : "r"(a[0]), "r"(a[1]), "r"(a[2]), "r"(a[3]), "r"(b[0]), "r"(b[1]));
}
__device__ __forceinline__ void mma16(float* d, const unsigned* a, const unsigned* b) {
    asm volatile(
        "mma.sync.aligned.m16n8k16.row.col.f32.f16.f16.f32 "
        "{%0,%1,%2,%3},{%4,%5,%6,%7},{%8,%9},{%0,%1,%2,%3};"
        : "+f"(d[0]), "+f"(d[1]), "+f"(d[2]), "+f"(d[3])
        : "r"(a[0]), "r"(a[1]), "r"(a[2]), "r"(a[3]), "r"(b[0]), "r"(b[1]));
}
__device__ __forceinline__ unsigned packh2(float lo, float hi) {
    __half2 h = __floats2half2_rn(lo, hi);
    return *reinterpret_cast<unsigned*>(&h);
}

// ---------------- fp16 tensor-core GEMM (tf32-equivalent mantissa) ---------
// C[4096 x N] = A[4096 x K] @ B (+ epilogue), 128x128 CTA tile, BK=16.
// 4 warps (2x2), warp tile 64x64, one m16n8k16 mma per (mt,nt) per slice.
// smem tile layout: uint32[128][12], word (r,kp) at r*12 + (kp ^ ((r>>3)&7));
// kp = k-pair index 0..7, packed half2 (k even in low bits).
// BT=false: B row-major [K,N] (transposing staging). BT=true: B [N,K].
// EPI: 0 none, 1 +Cin, 2 exact GELU
#define TPAD 12
#define TILE_WORDS (128 * TPAD)

__device__ __forceinline__ int tidx(int r, int kp) {
    return r * TPAD + (kp ^ ((r >> 3) & 7));
}

template<int EPI, bool BT>
__global__ __launch_bounds__(128, 2)
void mma_gemm(const float* __restrict__ A,
              const float* __restrict__ B0, const float* __restrict__ B1,
              const float* __restrict__ B2,
              const float* __restrict__ Cin,
              float* __restrict__ C0, float* __restrict__ C1, float* __restrict__ C2,
              int N, int K)
{
    const float* B = (blockIdx.z == 0) ? B0 : ((blockIdx.z == 1) ? B1 : B2);
    float*       C = (blockIdx.z == 0) ? C0 : ((blockIdx.z == 1) ? C1 : C2);

    __shared__ unsigned sA[2][TILE_WORDS];
    __shared__ unsigned sB[2][TILE_WORDS];

    const int tid  = threadIdx.x;
    const int lane = tid & 31;
    const int warp = tid >> 5;
    const int wm = warp >> 1, wn = warp & 1;
    const int lr = lane >> 2, lq = lane & 3;
    const int m0 = blockIdx.y * 128;
    const int n0 = blockIdx.x * 128;

    float acc[4][8][4];
    #pragma unroll
    for (int i = 0; i < 4; i++)
        #pragma unroll
        for (int j = 0; j < 8; j++)
            #pragma unroll
            for (int t = 0; t < 4; t++) acc[i][j][t] = 0.0f;

    float4 ar[4], br[4];

    auto gload = [&](int it) {
        const int k0 = it * 16;
        const float* ag = A + (size_t)(m0 + (tid >> 2)) * K + k0 + (tid & 3) * 4;
        #pragma unroll
        for (int p = 0; p < 4; p++)
            ar[p] = *(const float4*)(ag + (size_t)(p * 32) * K);
        if (!BT) {
            int kp = tid >> 4;              // 0..7
            int nb = (tid & 15) * 8;        // 0..120
            const float* bg = B + (size_t)(k0 + 2 * kp) * N + n0 + nb;
            br[0] = *(const float4*)(bg);
            br[1] = *(const float4*)(bg + 4);
            br[2] = *(const float4*)(bg + N);
            br[3] = *(const float4*)(bg + N + 4);
        } else {
            #pragma unroll
            for (int p = 0; p < 4; p++) {
                int n = n0 + (tid >> 2) + p * 32;
                br[p] = (n < N)
                      ? *(const float4*)(B + (size_t)n * K + k0 + (tid & 3) * 4)
                      : make_float4(0.f, 0.f, 0.f, 0.f);
            }
        }
    };

    auto cstore = [&](int buf) {
        #pragma unroll
        for (int p = 0; p < 4; p++) {
            int r  = (tid >> 2) + p * 32;
            int kp = (tid & 3) * 2;
            sA[buf][tidx(r, kp)]     = packh2(ar[p].x, ar[p].y);
            sA[buf][tidx(r, kp + 1)] = packh2(ar[p].z, ar[p].w);
        }
        if (!BT) {
            int kp = tid >> 4;
            int nb = (tid & 15) * 8;
            sB[buf][tidx(nb + 0, kp)] = packh2(br[0].x, br[2].x);
            sB[buf][tidx(nb + 1, kp)] = packh2(br[0].y, br[2].y);
            sB[buf][tidx(nb + 2, kp)] = packh2(br[0].z, br[2].z);
            sB[buf][tidx(nb + 3, kp)] = packh2(br[0].w, br[2].w);
            sB[buf][tidx(nb + 4, kp)] = packh2(br[1].x, br[3].x);
            sB[buf][tidx(nb + 5, kp)] = packh2(br[1].y, br[3].y);
            sB[buf][tidx(nb + 6, kp)] = packh2(br[1].z, br[3].z);
            sB[buf][tidx(nb + 7, kp)] = packh2(br[1].w, br[3].w);
        } else {
            #pragma unroll
            for (int p = 0; p < 4; p++) {
                int r  = (tid >> 2) + p * 32;
                int kp = (tid & 3) * 2;
                sB[buf][tidx(r, kp)]     = packh2(br[p].x, br[p].y);
                sB[buf][tidx(r, kp + 1)] = packh2(br[p].z, br[p].w);
            }
        }
    };

    auto compute = [&](int buf) {
        unsigned af[4][4];
        #pragma unroll
        for (int mt = 0; mt < 4; mt++) {
            int r = wm * 64 + mt * 16 + lr;
            af[mt][0] = sA[buf][tidx(r,     lq)];
            af[mt][1] = sA[buf][tidx(r + 8, lq)];
            af[mt][2] = sA[buf][tidx(r,     lq + 4)];
            af[mt][3] = sA[buf][tidx(r + 8, lq + 4)];
        }
        unsigned bf[8][2];
        #pragma unroll
        for (int nt = 0; nt < 8; nt++) {
            int n = wn * 64 + nt * 8 + lr;
            bf[nt][0] = sB[buf][tidx(n, lq)];
            bf[nt][1] = sB[buf][tidx(n, lq + 4)];
        }
        #pragma unroll
        for (int mt = 0; mt < 4; mt++)
            #pragma unroll
            for (int nt = 0; nt < 8; nt++)
                mma16(acc[mt][nt], af[mt], bf[nt]);
    };

    const int nIter = K >> 4;
    gload(0);
    cstore(0);
    __syncthreads();
    for (int it = 0; it < nIter; it++) {
        int cur = it & 1;
        if (it + 1 < nIter) gload(it + 1);
        compute(cur);
        if (it + 1 < nIter) cstore(cur ^ 1);
        __syncthreads();
    }

    // ---- epilogue ----
    #pragma unroll
    for (int mt = 0; mt < 4; mt++) {
        int r0 = m0 + wm * 64 + mt * 16 + lr;
        #pragma unroll
        for (int nt = 0; nt < 8; nt++) {
            int col = n0 + wn * 64 + nt * 8 + lq * 2;
            float* a4 = acc[mt][nt];
            float v00 = a4[0], v01 = a4[1], v10 = a4[2], v11 = a4[3];
            size_t o0 = (size_t)r0 * N + col;
            size_t o1 = (size_t)(r0 + 8) * N + col;
            if (EPI == 1) {
                float2 c0 = *(const float2*)(Cin + o0);
                float2 c1 = *(const float2*)(Cin + o1);
                v00 += c0.x; v01 += c0.y; v10 += c1.x; v11 += c1.y;
            }
            if (EPI == 2) {
                v00 = 0.5f * v00 * (1.0f + erff(v00 * 0.70710678118654752f));
                v01 = 0.5f * v01 * (1.0f + erff(v01 * 0.70710678118654752f));
                v10 = 0.5f * v10 * (1.0f + erff(v10 * 0.70710678118654752f));
                v11 = 0.5f * v11 * (1.0f + erff(v11 * 0.70710678118654752f));
            }
            if (!BT) {
                *(float2*)(C + o0) = make_float2(v00, v01);
                *(float2*)(C + o1) = make_float2(v10, v11);
            } else {
                if (col < N)     { C[o0] = v00;     C[o1] = v10; }
                if (col + 1 < N) { C[o0 + 1] = v01; C[o1 + 1] = v11; }
            }
        }
    }
}

// ---------------- embedding ----------------
__global__ void embed_kernel(const int* __restrict__ idx,
                             const float* __restrict__ wte,
                             const float* __restrict__ wpe,
                             float* __restrict__ x)
{
    int row = blockIdx.x;
    int s   = row & (SS - 1);
    int tok = idx[row];
    int tid = threadIdx.x;
    #pragma unroll
    for (int l = 0; l < 3; l++) {
        int d = tid + l * 256;
        x[(size_t)row * DD + d] = wte[(size_t)tok * DD + d] + wpe[(size_t)s * DD + d];
    }
}

// ---------------- layernorm ----------------
__global__ void layernorm_kernel(const float* __restrict__ x,
                                 const float* __restrict__ w,
                                 const float* __restrict__ b,
                                 float* __restrict__ y)
{
    int row = blockIdx.x;
    const float* p = x + (size_t)row * DD;
    int tid = threadIdx.x;
    float v0 = p[tid], v1 = p[tid + 256], v2 = p[tid + 512];
    __shared__ float red[256];
    red[tid] = v0 + v1 + v2;
    __syncthreads();
    for (int st = 128; st > 0; st >>= 1) {
        if (tid < st) red[tid] += red[tid + st];
        __syncthreads();
    }
    float mean = red[0] * (1.0f / DD);
    __syncthreads();
    float d0 = v0 - mean, d1 = v1 - mean, d2 = v2 - mean;
    red[tid] = d0 * d0 + d1 * d1 + d2 * d2;
    __syncthreads();
    for (int st = 128; st > 0; st >>= 1) {
        if (tid < st) red[tid] += red[tid + st];
        __syncthreads();
    }
    float rstd = rsqrtf(red[0] * (1.0f / DD) + 1e-5f);
    float* q = y + (size_t)row * DD;
    q[tid]       = d0 * rstd * w[tid]       + b[tid];
    q[tid + 256] = d1 * rstd * w[tid + 256] + b[tid + 256];
    q[tid + 512] = d2 * rstd * w[tid + 512] + b[tid + 512];
}

// ---------------- fused flash attention (tf32 tensor cores, as in R3) ------
#define FA_SQ   0
#define FA_SK   (64*68)
#define FA_SVH  (2*64*68)
#define FA_SVL  (2*64*68 + 64*72)
#define FA_SPST (2*64*68 + 2*64*72)
#define FA_SMEM_WORDS (2*64*68 + 2*64*72 + 4*256)

__global__ __launch_bounds__(128, 2)
void flash_attn_kernel(const float* __restrict__ Q, const float* __restrict__ K,
                       const float* __restrict__ V, float* __restrict__ O)
{
    extern __shared__ unsigned fsm[];
    unsigned* sQ  = fsm + FA_SQ;
    unsigned* sK  = fsm + FA_SK;
    unsigned* sVh = fsm + FA_SVH;
    unsigned* sVl = fsm + FA_SVL;

    const int tid  = threadIdx.x;
    const int lane = tid & 31;
    const int w    = tid >> 5;
    const int lr   = lane >> 2;
    const int lq   = lane & 3;
    const int it   = (SS / 64 - 1) - blockIdx.x;
    const int bh   = blockIdx.y;
    const int b    = bh / HH, h = bh % HH;
    const int i0   = it * 64;

    unsigned* myP = fsm + FA_SPST + w * 256;

    const float* Qb = Q + (size_t)(b * SS + i0) * DD + h * DKK;
    #pragma unroll
    for (int p = 0; p < 8; p++) {
        int idx = tid + p * 128;
        int r = idx >> 4, c4 = (idx & 15) * 4;
        float4 v = *(const float4*)(Qb + (size_t)r * DD + c4);
        unsigned* d = sQ + r * 68 + c4;
        d[0] = f2tf(v.x); d[1] = f2tf(v.y); d[2] = f2tf(v.z); d[3] = f2tf(v.w);
    }

    float oacc[8][4];
    #pragma unroll
    for (int nt = 0; nt < 8; nt++)
        #pragma unroll
        for (int e = 0; e < 4; e++) oacc[nt][e] = 0.0f;
    float m0 = -1e30f, m1 = -1e30f, l0 = 0.0f, l1 = 0.0f;

    for (int j0 = 0; j0 <= i0; j0 += 64) {
        __syncthreads();
        const float* Kb = K + (size_t)(b * SS + j0) * DD + h * DKK;
        const float* Vb = V + (size_t)(b * SS + j0) * DD + h * DKK;
        #pragma unroll
        for (int p = 0; p < 8; p++) {
            int idx = tid + p * 128;
            int r = idx >> 4, c4 = (idx & 15) * 4;
            float4 kv = *(const float4*)(Kb + (size_t)r * DD + c4);
            unsigned* dk = sK + r * 68 + c4;
            dk[0] = f2tf(kv.x); dk[1] = f2tf(kv.y); dk[2] = f2tf(kv.z); dk[3] = f2tf(kv.w);
            float4 vv = *(const float4*)(Vb + (size_t)r * DD + c4);
            unsigned* dh = sVh + r * 72 + c4;
            unsigned* dl = sVl + r * 72 + c4;
            unsigned h0 = f2tf(vv.x); dh[0] = h0; dl[0] = f2tf(vv.x - __uint_as_float(h0));
            unsigned h1 = f2tf(vv.y); dh[1] = h1; dl[1] = f2tf(vv.y - __uint_as_float(h1));
            unsigned h2 = f2tf(vv.z); dh[2] = h2; dl[2] = f2tf(vv.z - __uint_as_float(h2));
            unsigned h3 = f2tf(vv.w); dh[3] = h3; dl[3] = f2tf(vv.w - __uint_as_float(h3));
        }
        __syncthreads();

        float sacc[8][4];
        #pragma unroll
        for (int nt = 0; nt < 8; nt++)
            #pragma unroll
            for (int e = 0; e < 4; e++) sacc[nt][e] = 0.0f;

        #pragma unroll
        for (int kk = 0; kk < 8; kk++) {
            unsigned a[4];
            const unsigned* pa = sQ + (w * 16 + lr) * 68 + kk * 8 + lq;
            a[0] = pa[0]; a[1] = pa[8 * 68]; a[2] = pa[4]; a[3] = pa[8 * 68 + 4];
            #pragma unroll
            for (int nt = 0; nt < 8; nt++) {
                unsigned bf[2];
                const unsigned* pb = sK + (nt * 8 + lr) * 68 + kk * 8 + lq;
                bf[0] = pb[0]; bf[1] = pb[4];
                mma8(sacc[nt], a, bf);
            }
        }

        #pragma unroll
        for (int nt = 0; nt < 8; nt++)
            #pragma unroll
            for (int e = 0; e < 4; e++) sacc[nt][e] *= 0.125f;
        if (j0 == i0) {
            int ii0 = w * 16 + lr, ii1 = ii0 + 8;
            #pragma unroll
            for (int nt = 0; nt < 8; nt++) {
                int jj = nt * 8 + 2 * lq;
                if (jj     > ii0) sacc[nt][0] = -1e30f;
                if (jj + 1 > ii0) sacc[nt][1] = -1e30f;
                if (jj     > ii1) sacc[nt][2] = -1e30f;
                if (jj + 1 > ii1) sacc[nt][3] = -1e30f;
            }
        }

        float rm0 = -1e30f, rm1 = -1e30f;
        #pragma unroll
        for (int nt = 0; nt < 8; nt++) {
            rm0 = fmaxf(rm0, fmaxf(sacc[nt][0], sacc[nt][1]));
            rm1 = fmaxf(rm1, fmaxf(sacc[nt][2], sacc[nt][3]));
        }
        rm0 = fmaxf(rm0, __shfl_xor_sync(0xffffffffu, rm0, 1));
        rm0 = fmaxf(rm0, __shfl_xor_sync(0xffffffffu, rm0, 2));
        rm1 = fmaxf(rm1, __shfl_xor_sync(0xffffffffu, rm1, 1));
        rm1 = fmaxf(rm1, __shfl_xor_sync(0xffffffffu, rm1, 2));
        float mn0 = fmaxf(m0, rm0), mn1 = fmaxf(m1, rm1);
        float f0 = __expf(m0 - mn0), f1 = __expf(m1 - mn1);
        float ps0 = 0.0f, ps1 = 0.0f;
        #pragma unroll
        for (int nt = 0; nt < 8; nt++) {
            float p0 = __expf(sacc[nt][0] - mn0); sacc[nt][0] = p0; ps0 += p0;
            float p1 = __expf(sacc[nt][1] - mn0); sacc[nt][1] = p1; ps0 += p1;
            float p2 = __expf(sacc[nt][2] - mn1); sacc[nt][2] = p2; ps1 += p2;
            float p3 = __expf(sacc[nt][3] - mn1); sacc[nt][3] = p3; ps1 += p3;
        }
        ps0 += __shfl_xor_sync(0xffffffffu, ps0, 1);
        ps0 += __shfl_xor_sync(0xffffffffu, ps0, 2);
        ps1 += __shfl_xor_sync(0xffffffffu, ps1, 1);
        ps1 += __shfl_xor_sync(0xffffffffu, ps1, 2);
        l0 = l0 * f0 + ps0;
        l1 = l1 * f1 + ps1;
        m0 = mn0; m1 = mn1;
        #pragma unroll
        for (int nt = 0; nt < 8; nt++) {
            oacc[nt][0] *= f0; oacc[nt][1] *= f0;
            oacc[nt][2] *= f1; oacc[nt][3] *= f1;
        }

        #pragma unroll
        for (int kk = 0; kk < 8; kk++) {
            float p0 = sacc[kk][0], p1 = sacc[kk][1], p2 = sacc[kk][2], p3 = sacc[kk][3];
            unsigned h0 = f2tf(p0), h1 = f2tf(p1), h2 = f2tf(p2), h3 = f2tf(p3);
            unsigned e0 = f2tf(p0 - __uint_as_float(h0));
            unsigned e1 = f2tf(p1 - __uint_as_float(h1));
            unsigned e2 = f2tf(p2 - __uint_as_float(h2));
            unsigned e3 = f2tf(p3 - __uint_as_float(h3));
            myP[lr * 8 + 2 * lq]             = h0;
            myP[lr * 8 + 2 * lq + 1]         = h1;
            myP[(lr + 8) * 8 + 2 * lq]       = h2;
            myP[(lr + 8) * 8 + 2 * lq + 1]   = h3;
            myP[128 + lr * 8 + 2 * lq]           = e0;
            myP[128 + lr * 8 + 2 * lq + 1]       = e1;
            myP[128 + (lr + 8) * 8 + 2 * lq]     = e2;
            myP[128 + (lr + 8) * 8 + 2 * lq + 1] = e3;
            __syncwarp();
            unsigned ah[4], al[4];
            ah[0] = myP[lr * 8 + lq];
            ah[1] = myP[(lr + 8) * 8 + lq];
            ah[2] = myP[lr * 8 + lq + 4];
            ah[3] = myP[(lr + 8) * 8 + lq + 4];
            al[0] = myP[128 + lr * 8 + lq];
            al[1] = myP[128 + (lr + 8) * 8 + lq];
            al[2] = myP[128 + lr * 8 + lq + 4];
            al[3] = myP[128 + (lr + 8) * 8 + lq + 4];
            __syncwarp();
            #pragma unroll
            for (int nt = 0; nt < 8; nt++) {
                unsigned bhv[2], blv[2];
                const unsigned* pvh = sVh + (kk * 8 + lq) * 72 + nt * 8 + lr;
                bhv[0] = pvh[0]; bhv[1] = pvh[4 * 72];
                const unsigned* pvl = sVl + (kk * 8 + lq) * 72 + nt * 8 + lr;
                blv[0] = pvl[0]; blv[1] = pvl[4 * 72];
                mma8(oacc[nt], ah, bhv);
                mma8(oacc[nt], al, bhv);
                mma8(oacc[nt], ah, blv);
            }
        }
    }

    float inv0 = 1.0f / l0, inv1 = 1.0f / l1;
    int row0 = b * SS + i0 + w * 16 + lr;
    float* Ob = O + (size_t)row0 * DD + h * DKK;
    #pragma unroll
    for (int nt = 0; nt < 8; nt++) {
        int col = nt * 8 + 2 * lq;
        *(float2*)(Ob + col) = make_float2(oacc[nt][0] * inv0, oacc[nt][1] * inv0);
        *(float2*)(Ob + (size_t)8 * DD + col) =
            make_float2(oacc[nt][2] * inv1, oacc[nt][3] * inv1);
    }
}

// ---------------- host launcher ----------------
extern "C" void kernel_launch(void* const* d_in, const int* in_sizes, int n_in,
                              void* d_out, int out_size)
{
    const int*   idx   = (const int*)  d_in[0];
    const float* wte   = (const float*)d_in[1];
    const float* wpe   = (const float*)d_in[2];
    const float* ln1_w = (const float*)d_in[3];
    const float* ln1_b = (const float*)d_in[4];
    const float* wq    = (const float*)d_in[5];
    const float* wk    = (const float*)d_in[6];
    const float* wv    = (const float*)d_in[7];
    const float* wo    = (const float*)d_in[8];
    const float* ln2_w = (const float*)d_in[9];
    const float* ln2_b = (const float*)d_in[10];
    const float* fc1   = (const float*)d_in[11];
    const float* fc2   = (const float*)d_in[12];
    const float* lnf_w = (const float*)d_in[13];
    const float* lnf_b = (const float*)d_in[14];
    float* out = (float*)d_out;

    float *x, *h, *q, *k, *v, *tmp, *ff;
    cudaGetSymbolAddress((void**)&x,   g_x);
    cudaGetSymbolAddress((void**)&h,   g_h);
    cudaGetSymbolAddress((void**)&q,   g_q);
    cudaGetSymbolAddress((void**)&k,   g_k);
    cudaGetSymbolAddress((void**)&v,   g_v);
    cudaGetSymbolAddress((void**)&tmp, g_tmp);
    cudaGetSymbolAddress((void**)&ff,  g_ff);

    const int faSmem = FA_SMEM_WORDS * 4;
    cudaFuncSetAttribute(flash_attn_kernel,
                         cudaFuncAttributeMaxDynamicSharedMemorySize, faSmem);

    embed_kernel<<<NTOK, 256>>>(idx, wte, wpe, x);

    dim3 gQKV(DD / 128, NTOK / 128, 3);
    dim3 gD  (DD / 128, NTOK / 128, 1);
    dim3 gF  (DFF / 128, NTOK / 128, 1);

    for (int l = 0; l < LL; l++) {
        const float* Wq = wq + (size_t)l * DD * DD;
        const float* Wk = wk + (size_t)l * DD * DD;
        const float* Wv = wv + (size_t)l * DD * DD;
        const float* Wo = wo + (size_t)l * DD * DD;
        const float* W1 = fc1 + (size_t)l * DD * DFF;
        const float* W2 = fc2 + (size_t)l * DFF * DD;

        layernorm_kernel<<<NTOK, 256>>>(x, ln1_w + l * DD, ln1_b + l * DD, h);

        mma_gemm<0,false><<<gQKV, 128>>>(h, Wq, Wk, Wv, nullptr, q, k, v, DD, DD);

        flash_attn_kernel<<<dim3(SS / 64, BB * HH), 128, faSmem>>>(q, k, v, tmp);

        mma_gemm<1,false><<<gD, 128>>>(tmp, Wo, Wo, Wo, x, x, x, x, DD, DD);

        layernorm_kernel<<<NTOK, 256>>>(x, ln2_w + l * DD, ln2_b + l * DD, h);
        mma_gemm<2,false><<<gF, 128>>>(h, W1, W1, W1, nullptr, ff, ff, ff, DFF, DD);
        mma_gemm<1,false><<<gD, 128>>>(ff, W2, W2, W2, x, x, x, x, DD, DFF);
    }

    layernorm_kernel<<<NTOK, 256>>>(x, lnf_w, lnf_b, h);
    mma_gemm<0,true><<<dim3((VV + 127) / 128, NTOK / 128, 1), 128>>>(
        h, wte, wte, wte, nullptr, out, out, out, VV, DD);
}

// round 7
// speedup vs baseline: 1.6926x; 1.2030x over previous
#include <cuda_runtime.h>
#include <cuda_bf16.h>
#include <cuda_fp16.h>
#include <math.h>
#include <stdint.h>

// ---------------- problem constants ----------------
#define BB 4
#define SS 1024
#define LL 12
#define DD 768
#define HH 12
#define DKK 64
#define DFF 3072
#define VV 50257
#define NTOK (BB*SS)          // 4096
#define KPD (DD/2)            // 384
#define KPF (DFF/2)           // 1536

// ---------------- scratch (device globals; no allocs allowed) --------------
__device__ float g_x [(size_t)NTOK * DD];
__device__ float g_q [(size_t)NTOK * DD];
__device__ float g_k [(size_t)NTOK * DD];
__device__ float g_v [(size_t)NTOK * DD];
__device__ unsigned g_h16  [(size_t)NTOK * KPD];
__device__ unsigned g_tmp16[(size_t)NTOK * KPD];
__device__ unsigned g_ff16 [(size_t)NTOK * KPF];
// packed fp16 weights (half2 along K)
__device__ unsigned g_wq16 [(size_t)LL * KPD * DD];
__device__ unsigned g_wk16 [(size_t)LL * KPD * DD];
__device__ unsigned g_wv16 [(size_t)LL * KPD * DD];
__device__ unsigned g_wo16 [(size_t)LL * KPD * DD];
__device__ unsigned g_fc116[(size_t)LL * KPD * DFF];
__device__ unsigned g_fc216[(size_t)LL * KPF * DD];
__device__ unsigned g_wte16[(size_t)VV * KPD];

// ---------------- helpers ----------------
__device__ __forceinline__ uint32_t smem_u32(const void* p) {
    uint32_t a;
    asm("{ .reg .u64 t; cvta.to.shared.u64 t, %1; cvt.u32.u64 %0, t; }"
        : "=r"(a) : "l"(p));
    return a;
}
__device__ __forceinline__ unsigned f2tf(float f) {
    unsigned u;
    asm("cvt.rna.tf32.f32 %0, %1;" : "=r"(u) : "f"(f));
    return u;
}
__device__ __forceinline__ void mma8(float* d, const unsigned* a, const unsigned* b) {
    asm volatile(
        "mma.sync.aligned.m16n8k8.row.col.f32.tf32.tf32.f32 "
        "{%0,%1,%2,%3},{%4,%5,%6,%7},{%8,%9},{%0,%1,%2,%3};"
        : "+f"(d[0]), "+f"(d[1]), "+f"(d[2]), "+f"(d[3])
        : "r"(a[0]), "r"(a[1]), "r"(a[2]), "r"(a[3]), "r"(b[0]), "r"(b[1]));
}
__device__ __forceinline__ void mma16(float* d, const unsigned* a, const unsigned* b) {
    asm volatile(
        "mma.sync.aligned.m16n8k16.row.col.f32.f16.f16.f32 "
        "{%0,%1,%2,%3},{%4,%5,%6,%7},{%8,%9},{%0,%1,%2,%3};"
        : "+f"(d[0]), "+f"(d[1]), "+f"(d[2]), "+f"(d[3])
        : "r"(a[0]), "r"(a[1]), "r"(a[2]), "r"(a[3]), "r"(b[0]), "r"(b[1]));
}
__device__ __forceinline__ unsigned packh2(float lo, float hi) {
    __half2 h = __floats2half2_rn(lo, hi);
    return *reinterpret_cast<unsigned*>(&h);
}
__device__ __forceinline__ void cp16(uint32_t d, const void* g) {
    asm volatile("cp.async.cg.shared.global [%0], [%1], 16;" :: "r"(d), "l"(g));
}
__device__ __forceinline__ void cp16g(uint32_t d, const void* g, int sz) {
    asm volatile("cp.async.cg.shared.global [%0], [%1], 16, %2;"
                 :: "r"(d), "l"(g), "r"(sz));
}

// ---------------- weight packing (once per launch) ----------------
// W [L][K][N] f32 -> out [L][K/2][N] half2 words
__global__ void pack_kn(const float* __restrict__ W, unsigned* __restrict__ out,
                        int KP, int N, int total)
{
    int i = blockIdx.x * 256 + threadIdx.x;
    if (i >= total) return;
    int l  = i / (KP * N);
    int r  = i - l * KP * N;
    int kp = r / N;
    int n  = r - kp * N;
    const float* src = W + ((size_t)l * 2 * KP + 2 * kp) * N + n;
    out[i] = packh2(src[0], src[N]);
}
// wte [V][K] f32 -> [V][K/2] half2 words
__global__ void pack_nk(const float* __restrict__ W, unsigned* __restrict__ out,
                        int total)
{
    int i = blockIdx.x * 256 + threadIdx.x;
    if (i >= total) return;
    int v = i / KPD, kp = i - v * KPD;
    float2 f = *(const float2*)(W + (size_t)v * DD + 2 * kp);
    out[i] = packh2(f.x, f.y);
}

// ---------------- fp16 GEMM, pure cp.async pipeline ----------------
// C[4096 x N] = A16[M][K/2] @ B16 (+ epilogue)
// BT=false: B16 [K/2][N].  BT=true: B16 [N][K/2].
// EPI: 0 none->f32, 1 +Cin->f32, 2 GELU->packed fp16
// 256 threads, 8 warps (2x4), warp tile 64x32, BK=32, 3-stage cp.async.
#define APAD 20     // words per A row (16 used + 4)
#define BPAD 136    // words per B kp-row (128 used + 8)
#define AW (128 * APAD)             // 2560
#define BWN (16 * BPAD)             // 2176
#define STG_N (AW + BWN)            // 4736 words
#define STG_T (AW + AW)             // 5120 words

template<int EPI, bool BT>
__global__ __launch_bounds__(256, 2)
void mma_gemm(const unsigned* __restrict__ A,
              const unsigned* __restrict__ B0, const unsigned* __restrict__ B1,
              const unsigned* __restrict__ B2,
              const float* __restrict__ Cin, void* __restrict__ Cv,
              float* __restrict__ C1f, float* __restrict__ C2f,
              int N, int K)
{
    extern __shared__ unsigned gsm[];
    constexpr int STG = BT ? STG_T : STG_N;

    const unsigned* B = (blockIdx.z == 0) ? B0 : ((blockIdx.z == 1) ? B1 : B2);
    float* Cf = (blockIdx.z == 0) ? (float*)Cv : ((blockIdx.z == 1) ? C1f : C2f);
    unsigned* C16 = (unsigned*)Cv;

    const int tid  = threadIdx.x;
    const int lane = tid & 31;
    const int warp = tid >> 5;
    const int wm = warp >> 2, wn = warp & 3;       // 2 x 4
    const int lr = lane >> 2, lq = lane & 3;
    const int m0 = blockIdx.y * 128;
    const int n0 = blockIdx.x * 128;
    const int KA = K >> 1;                         // words per A row

    const uint32_t sbase = smem_u32(gsm);

    float acc[4][4][4];
    #pragma unroll
    for (int i = 0; i < 4; i++)
        #pragma unroll
        for (int j = 0; j < 4; j++)
            #pragma unroll
            for (int t = 0; t < 4; t++) acc[i][j][t] = 0.0f;

    auto load_stage = [&](int stg) {
        const int slot = stg % 3;
        const uint32_t sa = sbase + (uint32_t)(slot * STG) * 4u;
        const uint32_t sb = sa + (uint32_t)AW * 4u;
        const int kp0 = stg * 16;
        #pragma unroll
        for (int p = 0; p < 2; p++) {
            int s = tid * 2 + p;                   // 0..511
            int r = s >> 2, c4 = (s & 3) * 4;
            cp16(sa + (uint32_t)(r * APAD + c4) * 4u,
                 A + (size_t)(m0 + r) * KA + kp0 + c4);
        }
        if (!BT) {
            #pragma unroll
            for (int p = 0; p < 2; p++) {
                int s  = tid * 2 + p;
                int kp = s >> 5, n4 = (s & 31) * 4;
                cp16(sb + (uint32_t)(kp * BPAD + n4) * 4u,
                     B + (size_t)(kp0 + kp) * N + n0 + n4);
            }
        } else {
            #pragma unroll
            for (int p = 0; p < 2; p++) {
                int s = tid * 2 + p;
                int r = s >> 2, c4 = (s & 3) * 4;
                int n = n0 + r;
                int ok = (n < N);
                const unsigned* g = B + (size_t)(ok ? n : 0) * KA + kp0 + c4;
                cp16g(sb + (uint32_t)(r * APAD + c4) * 4u, g, ok ? 16 : 0);
            }
        }
        asm volatile("cp.async.commit_group;" ::: "memory");
    };

    auto compute = [&](int slot) {
        const unsigned* pa = gsm + slot * STG;
        const unsigned* pb = pa + AW;
        #pragma unroll
        for (int ks = 0; ks < 2; ks++) {
            const int kb = ks * 8;
            unsigned af[4][4];
            #pragma unroll
            for (int mt = 0; mt < 4; mt++) {
                int r = wm * 64 + mt * 16 + lr;
                af[mt][0] = pa[r * APAD + kb + lq];
                af[mt][1] = pa[(r + 8) * APAD + kb + lq];
                af[mt][2] = pa[r * APAD + kb + lq + 4];
                af[mt][3] = pa[(r + 8) * APAD + kb + lq + 4];
            }
            unsigned bf[4][2];
            #pragma unroll
            for (int nt = 0; nt < 4; nt++) {
                int n = wn * 32 + nt * 8 + lr;
                if (!BT) {
                    bf[nt][0] = pb[(kb + lq) * BPAD + n];
                    bf[nt][1] = pb[(kb + lq + 4) * BPAD + n];
                } else {
                    bf[nt][0] = pb[n * APAD + kb + lq];
                    bf[nt][1] = pb[n * APAD + kb + lq + 4];
                }
            }
            #pragma unroll
            for (int mt = 0; mt < 4; mt++)
                #pragma unroll
                for (int nt = 0; nt < 4; nt++)
                    mma16(acc[mt][nt], af[mt], bf[nt]);
        }
    };

    const int nIter = K >> 5;
    load_stage(0);
    load_stage(1);
    for (int it = 0; it < nIter; it++) {
        if (it + 1 < nIter) asm volatile("cp.async.wait_group 1;" ::: "memory");
        else                asm volatile("cp.async.wait_group 0;" ::: "memory");
        __syncthreads();
        if (it + 2 < nIter) load_stage(it + 2);
        compute(it % 3);
    }

    // ---- epilogue ----
    #pragma unroll
    for (int mt = 0; mt < 4; mt++) {
        int r0 = m0 + wm * 64 + mt * 16 + lr;
        #pragma unroll
        for (int nt = 0; nt < 4; nt++) {
            int col = n0 + wn * 32 + nt * 8 + lq * 2;
            float* a4 = acc[mt][nt];
            float v00 = a4[0], v01 = a4[1], v10 = a4[2], v11 = a4[3];
            if (EPI == 2) {
                v00 = 0.5f * v00 * (1.0f + erff(v00 * 0.70710678118654752f));
                v01 = 0.5f * v01 * (1.0f + erff(v01 * 0.70710678118654752f));
                v10 = 0.5f * v10 * (1.0f + erff(v10 * 0.70710678118654752f));
                v11 = 0.5f * v11 * (1.0f + erff(v11 * 0.70710678118654752f));
                int nw = N >> 1;
                C16[(size_t)r0 * nw + (col >> 1)]       = packh2(v00, v01);
                C16[(size_t)(r0 + 8) * nw + (col >> 1)] = packh2(v10, v11);
            } else {
                size_t o0 = (size_t)r0 * N + col;
                size_t o1 = (size_t)(r0 + 8) * N + col;
                if (EPI == 1) {
                    float2 c0 = *(const float2*)(Cin + o0);
                    float2 c1 = *(const float2*)(Cin + o1);
                    v00 += c0.x; v01 += c0.y; v10 += c1.x; v11 += c1.y;
                }
                if (!BT) {
                    *(float2*)(Cf + o0) = make_float2(v00, v01);
                    *(float2*)(Cf + o1) = make_float2(v10, v11);
                } else {
                    if (col < N)     { Cf[o0] = v00;     Cf[o1] = v10; }
                    if (col + 1 < N) { Cf[o0 + 1] = v01; Cf[o1 + 1] = v11; }
                }
            }
        }
    }
}

// ---------------- embedding ----------------
__global__ void embed_kernel(const int* __restrict__ idx,
                             const float* __restrict__ wte,
                             const float* __restrict__ wpe,
                             float* __restrict__ x)
{
    int row = blockIdx.x;
    int s   = row & (SS - 1);
    int tok = idx[row];
    int tid = threadIdx.x;
    #pragma unroll
    for (int l = 0; l < 3; l++) {
        int d = tid + l * 256;
        x[(size_t)row * DD + d] = wte[(size_t)tok * DD + d] + wpe[(size_t)s * DD + d];
    }
}

// ---------------- layernorm -> packed fp16 ----------------
__global__ void layernorm_kernel(const float* __restrict__ x,
                                 const float* __restrict__ w,
                                 const float* __restrict__ b,
                                 unsigned* __restrict__ y16)
{
    int row = blockIdx.x;
    const float2* p2 = (const float2*)(x + (size_t)row * DD);
    int tid = threadIdx.x;                 // 256
    float2 f1 = p2[tid];
    float2 f2 = (tid < 128) ? p2[tid + 256] : make_float2(0.f, 0.f);
    __shared__ float red[256];
    red[tid] = f1.x + f1.y + f2.x + f2.y;
    __syncthreads();
    for (int st = 128; st > 0; st >>= 1) {
        if (tid < st) red[tid] += red[tid + st];
        __syncthreads();
    }
    float mean = red[0] * (1.0f / DD);
    __syncthreads();
    float a0 = f1.x - mean, a1 = f1.y - mean;
    float a2 = f2.x - mean, a3 = f2.y - mean;
    red[tid] = a0 * a0 + a1 * a1 + ((tid < 128) ? (a2 * a2 + a3 * a3) : 0.f);
    __syncthreads();
    for (int st = 128; st > 0; st >>= 1) {
        if (tid < st) red[tid] += red[tid + st];
        __syncthreads();
    }
    float rstd = rsqrtf(red[0] * (1.0f / DD) + 1e-5f);
    const float2* w2 = (const float2*)w;
    const float2* b2 = (const float2*)b;
    unsigned* yr = y16 + (size_t)row * KPD;
    {
        float2 ww = w2[tid], bb = b2[tid];
        yr[tid] = packh2(a0 * rstd * ww.x + bb.x, a1 * rstd * ww.y + bb.y);
    }
    if (tid < 128) {
        float2 ww = w2[tid + 256], bb = b2[tid + 256];
        yr[tid + 256] = packh2(a2 * rstd * ww.x + bb.x, a3 * rstd * ww.y + bb.y);
    }
}

// ---------------- fused flash attention (tf32; fp16-packed output) ---------
#define FA_SQ   0
#define FA_SK   (64*68)
#define FA_SVH  (2*64*68)
#define FA_SVL  (2*64*68 + 64*72)
#define FA_SPST (2*64*68 + 2*64*72)
#define FA_SMEM_WORDS (2*64*68 + 2*64*72 + 4*256)

__global__ __launch_bounds__(128, 2)
void flash_attn_kernel(const float* __restrict__ Q, const float* __restrict__ K,
                       const float* __restrict__ V, unsigned* __restrict__ O16)
{
    extern __shared__ unsigned fsm[];
    unsigned* sQ  = fsm + FA_SQ;
    unsigned* sK  = fsm + FA_SK;
    unsigned* sVh = fsm + FA_SVH;
    unsigned* sVl = fsm + FA_SVL;

    const int tid  = threadIdx.x;
    const int lane = tid & 31;
    const int w    = tid >> 5;
    const int lr   = lane >> 2;
    const int lq   = lane & 3;
    const int it   = (SS / 64 - 1) - blockIdx.x;
    const int bh   = blockIdx.y;
    const int b    = bh / HH, h = bh % HH;
    const int i0   = it * 64;

    unsigned* myP = fsm + FA_SPST + w * 256;

    const float* Qb = Q + (size_t)(b * SS + i0) * DD + h * DKK;
    #pragma unroll
    for (int p = 0; p < 8; p++) {
        int idx = tid + p * 128;
        int r = idx >> 4, c4 = (idx & 15) * 4;
        float4 v = *(const float4*)(Qb + (size_t)r * DD + c4);
        unsigned* d = sQ + r * 68 + c4;
        d[0] = f2tf(v.x); d[1] = f2tf(v.y); d[2] = f2tf(v.z); d[3] = f2tf(v.w);
    }

    float oacc[8][4];
    #pragma unroll
    for (int nt = 0; nt < 8; nt++)
        #pragma unroll
        for (int e = 0; e < 4; e++) oacc[nt][e] = 0.0f;
    float m0 = -1e30f, m1 = -1e30f, l0 = 0.0f, l1 = 0.0f;

    for (int j0 = 0; j0 <= i0; j0 += 64) {
        __syncthreads();
        const float* Kb = K + (size_t)(b * SS + j0) * DD + h * DKK;
        const float* Vb = V + (size_t)(b * SS + j0) * DD + h * DKK;
        #pragma unroll
        for (int p = 0; p < 8; p++) {
            int idx = tid + p * 128;
            int r = idx >> 4, c4 = (idx & 15) * 4;
            float4 kv = *(const float4*)(Kb + (size_t)r * DD + c4);
            unsigned* dk = sK + r * 68 + c4;
            dk[0] = f2tf(kv.x); dk[1] = f2tf(kv.y); dk[2] = f2tf(kv.z); dk[3] = f2tf(kv.w);
            float4 vv = *(const float4*)(Vb + (size_t)r * DD + c4);
            unsigned* dh = sVh + r * 72 + c4;
            unsigned* dl = sVl + r * 72 + c4;
            unsigned h0 = f2tf(vv.x); dh[0] = h0; dl[0] = f2tf(vv.x - __uint_as_float(h0));
            unsigned h1 = f2tf(vv.y); dh[1] = h1; dl[1] = f2tf(vv.y - __uint_as_float(h1));
            unsigned h2 = f2tf(vv.z); dh[2] = h2; dl[2] = f2tf(vv.z - __uint_as_float(h2));
            unsigned h3 = f2tf(vv.w); dh[3] = h3; dl[3] = f2tf(vv.w - __uint_as_float(h3));
        }
        __syncthreads();

        float sacc[8][4];
        #pragma unroll
        for (int nt = 0; nt < 8; nt++)
            #pragma unroll
            for (int e = 0; e < 4; e++) sacc[nt][e] = 0.0f;

        #pragma unroll
        for (int kk = 0; kk < 8; kk++) {
            unsigned a[4];
            const unsigned* pa = sQ + (w * 16 + lr) * 68 + kk * 8 + lq;
            a[0] = pa[0]; a[1] = pa[8 * 68]; a[2] = pa[4]; a[3] = pa[8 * 68 + 4];
            #pragma unroll
            for (int nt = 0; nt < 8; nt++) {
                unsigned bf[2];
                const unsigned* pb = sK + (nt * 8 + lr) * 68 + kk * 8 + lq;
                bf[0] = pb[0]; bf[1] = pb[4];
                mma8(sacc[nt], a, bf);
            }
        }

        #pragma unroll
        for (int nt = 0; nt < 8; nt++)
            #pragma unroll
            for (int e = 0; e < 4; e++) sacc[nt][e] *= 0.125f;
        if (j0 == i0) {
            int ii0 = w * 16 + lr, ii1 = ii0 + 8;
            #pragma unroll
            for (int nt = 0; nt < 8; nt++) {
                int jj = nt * 8 + 2 * lq;
                if (jj     > ii0) sacc[nt][0] = -1e30f;
                if (jj + 1 > ii0) sacc[nt][1] = -1e30f;
                if (jj     > ii1) sacc[nt][2] = -1e30f;
                if (jj + 1 > ii1) sacc[nt][3] = -1e30f;
            }
        }

        float rm0 = -1e30f, rm1 = -1e30f;
        #pragma unroll
        for (int nt = 0; nt < 8; nt++) {
            rm0 = fmaxf(rm0, fmaxf(sacc[nt][0], sacc[nt][1]));
            rm1 = fmaxf(rm1, fmaxf(sacc[nt][2], sacc[nt][3]));
        }
        rm0 = fmaxf(rm0, __shfl_xor_sync(0xffffffffu, rm0, 1));
        rm0 = fmaxf(rm0, __shfl_xor_sync(0xffffffffu, rm0, 2));
        rm1 = fmaxf(rm1, __shfl_xor_sync(0xffffffffu, rm1, 1));
        rm1 = fmaxf(rm1, __shfl_xor_sync(0xffffffffu, rm1, 2));
        float mn0 = fmaxf(m0, rm0), mn1 = fmaxf(m1, rm1);
        float f0 = __expf(m0 - mn0), f1 = __expf(m1 - mn1);
        float ps0 = 0.0f, ps1 = 0.0f;
        #pragma unroll
        for (int nt = 0; nt < 8; nt++) {
            float p0 = __expf(sacc[nt][0] - mn0); sacc[nt][0] = p0; ps0 += p0;
            float p1 = __expf(sacc[nt][1] - mn0); sacc[nt][1] = p1; ps0 += p1;
            float p2 = __expf(sacc[nt][2] - mn1); sacc[nt][2] = p2; ps1 += p2;
            float p3 = __expf(sacc[nt][3] - mn1); sacc[nt][3] = p3; ps1 += p3;
        }
        ps0 += __shfl_xor_sync(0xffffffffu, ps0, 1);
        ps0 += __shfl_xor_sync(0xffffffffu, ps0, 2);
        ps1 += __shfl_xor_sync(0xffffffffu, ps1, 1);
        ps1 += __shfl_xor_sync(0xffffffffu, ps1, 2);
        l0 = l0 * f0 + ps0;
        l1 = l1 * f1 + ps1;
        m0 = mn0; m1 = mn1;
        #pragma unroll
        for (int nt = 0; nt < 8; nt++) {
            oacc[nt][0] *= f0; oacc[nt][1] *= f0;
            oacc[nt][2] *= f1; oacc[nt][3] *= f1;
        }

        #pragma unroll
        for (int kk = 0; kk < 8; kk++) {
            float p0 = sacc[kk][0], p1 = sacc[kk][1], p2 = sacc[kk][2], p3 = sacc[kk][3];
            unsigned h0 = f2tf(p0), h1 = f2tf(p1), h2 = f2tf(p2), h3 = f2tf(p3);
            unsigned e0 = f2tf(p0 - __uint_as_float(h0));
            unsigned e1 = f2tf(p1 - __uint_as_float(h1));
            unsigned e2 = f2tf(p2 - __uint_as_float(h2));
            unsigned e3 = f2tf(p3 - __uint_as_float(h3));
            myP[lr * 8 + 2 * lq]             = h0;
            myP[lr * 8 + 2 * lq + 1]         = h1;
            myP[(lr + 8) * 8 + 2 * lq]       = h2;
            myP[(lr + 8) * 8 + 2 * lq + 1]   = h3;
            myP[128 + lr * 8 + 2 * lq]           = e0;
            myP[128 + lr * 8 + 2 * lq + 1]       = e1;
            myP[128 + (lr + 8) * 8 + 2 * lq]     = e2;
            myP[128 + (lr + 8) * 8 + 2 * lq + 1] = e3;
            __syncwarp();
            unsigned ah[4], al[4];
            ah[0] = myP[lr * 8 + lq];
            ah[1] = myP[(lr + 8) * 8 + lq];
            ah[2] = myP[lr * 8 + lq + 4];
            ah[3] = myP[(lr + 8) * 8 + lq + 4];
            al[0] = myP[128 + lr * 8 + lq];
            al[1] = myP[128 + (lr + 8) * 8 + lq];
            al[2] = myP[128 + lr * 8 + lq + 4];
            al[3] = myP[128 + (lr + 8) * 8 + lq + 4];
            __syncwarp();
            #pragma unroll
            for (int nt = 0; nt < 8; nt++) {
                unsigned bhv[2], blv[2];
                const unsigned* pvh = sVh + (kk * 8 + lq) * 72 + nt * 8 + lr;
                bhv[0] = pvh[0]; bhv[1] = pvh[4 * 72];
                const unsigned* pvl = sVl + (kk * 8 + lq) * 72 + nt * 8 + lr;
                blv[0] = pvl[0]; blv[1] = pvl[4 * 72];
                mma8(oacc[nt], ah, bhv);
                mma8(oacc[nt], al, bhv);
                mma8(oacc[nt], ah, blv);
            }
        }
    }

    // packed fp16 output: word = row*384 + h*32 + nt*4 + lq
    float inv0 = 1.0f / l0, inv1 = 1.0f / l1;
    int row0 = b * SS + i0 + w * 16 + lr;
    unsigned* Ob = O16 + (size_t)row0 * KPD + h * 32;
    #pragma unroll
    for (int nt = 0; nt < 8; nt++) {
        Ob[nt * 4 + lq] = packh2(oacc[nt][0] * inv0, oacc[nt][1] * inv0);
        Ob[(size_t)8 * KPD + nt * 4 + lq] = packh2(oacc[nt][2] * inv1, oacc[nt][3] * inv1);
    }
}

// ---------------- host launcher ----------------
extern "C" void kernel_launch(void* const* d_in, const int* in_sizes, int n_in,
                              void* d_out, int out_size)
{
    const int*   idx   = (const int*)  d_in[0];
    const float* wte   = (const float*)d_in[1];
    const float* wpe   = (const float*)d_in[2];
    const float* ln1_w = (const float*)d_in[3];
    const float* ln1_b = (const float*)d_in[4];
    const float* wq    = (const float*)d_in[5];
    const float* wk    = (const float*)d_in[6];
    const float* wv    = (const float*)d_in[7];
    const float* wo    = (const float*)d_in[8];
    const float* ln2_w = (const float*)d_in[9];
    const float* ln2_b = (const float*)d_in[10];
    const float* fc1   = (const float*)d_in[11];
    const float* fc2   = (const float*)d_in[12];
    const float* lnf_w = (const float*)d_in[13];
    const float* lnf_b = (const float*)d_in[14];
    float* out = (float*)d_out;

    float *x, *q, *k, *v;
    unsigned *h16, *tmp16, *ff16;
    unsigned *wq16, *wk16, *wv16, *wo16, *fc116, *fc216, *wte16;
    cudaGetSymbolAddress((void**)&x,     g_x);
    cudaGetSymbolAddress((void**)&q,     g_q);
    cudaGetSymbolAddress((void**)&k,     g_k);
    cudaGetSymbolAddress((void**)&v,     g_v);
    cudaGetSymbolAddress((void**)&h16,   g_h16);
    cudaGetSymbolAddress((void**)&tmp16, g_tmp16);
    cudaGetSymbolAddress((void**)&ff16,  g_ff16);
    cudaGetSymbolAddress((void**)&wq16,  g_wq16);
    cudaGetSymbolAddress((void**)&wk16,  g_wk16);
    cudaGetSymbolAddress((void**)&wv16,  g_wv16);
    cudaGetSymbolAddress((void**)&wo16,  g_wo16);
    cudaGetSymbolAddress((void**)&fc116, g_fc116);
    cudaGetSymbolAddress((void**)&fc216, g_fc216);
    cudaGetSymbolAddress((void**)&wte16, g_wte16);

    const int faSmem = FA_SMEM_WORDS * 4;
    const int gsN = 3 * STG_N * 4;   // 56832
    const int gsT = 3 * STG_T * 4;   // 61440
    cudaFuncSetAttribute(flash_attn_kernel,
                         cudaFuncAttributeMaxDynamicSharedMemorySize, faSmem);
    cudaFuncSetAttribute(mma_gemm<0,false>, cudaFuncAttributeMaxDynamicSharedMemorySize, gsN);
    cudaFuncSetAttribute(mma_gemm<1,false>, cudaFuncAttributeMaxDynamicSharedMemorySize, gsN);
    cudaFuncSetAttribute(mma_gemm<2,false>, cudaFuncAttributeMaxDynamicSharedMemorySize, gsN);
    cudaFuncSetAttribute(mma_gemm<0,true>,  cudaFuncAttributeMaxDynamicSharedMemorySize, gsT);

    // ---- pack weights to fp16 (once per replay) ----
    {
        int tQ = LL * KPD * DD;
        pack_kn<<<(tQ + 255) / 256, 256>>>(wq, wq16, KPD, DD, tQ);
        pack_kn<<<(tQ + 255) / 256, 256>>>(wk, wk16, KPD, DD, tQ);
        pack_kn<<<(tQ + 255) / 256, 256>>>(wv, wv16, KPD, DD, tQ);
        pack_kn<<<(tQ + 255) / 256, 256>>>(wo, wo16, KPD, DD, tQ);
        int t1 = LL * KPD * DFF;
        pack_kn<<<(t1 + 255) / 256, 256>>>(fc1, fc116, KPD, DFF, t1);
        int t2 = LL * KPF * DD;
        pack_kn<<<(t2 + 255) / 256, 256>>>(fc2, fc216, KPF, DD, t2);
        int tE = VV * KPD;
        pack_nk<<<(tE + 255) / 256, 256>>>(wte, wte16, tE);
    }

    embed_kernel<<<NTOK, 256>>>(idx, wte, wpe, x);

    dim3 gQKV(DD / 128, NTOK / 128, 3);
    dim3 gD  (DD / 128, NTOK / 128, 1);
    dim3 gF  (DFF / 128, NTOK / 128, 1);

    for (int l = 0; l < LL; l++) {
        unsigned* Wq = wq16 + (size_t)l * KPD * DD;
        unsigned* Wk = wk16 + (size_t)l * KPD * DD;
        unsigned* Wv = wv16 + (size_t)l * KPD * DD;
        unsigned* Wo = wo16 + (size_t)l * KPD * DD;
        unsigned* W1 = fc116 + (size_t)l * KPD * DFF;
        unsigned* W2 = fc216 + (size_t)l * KPF * DD;

        layernorm_kernel<<<NTOK, 256>>>(x, ln1_w + l * DD, ln1_b + l * DD, h16);

        mma_gemm<0,false><<<gQKV, 256, gsN>>>(h16, Wq, Wk, Wv, nullptr,
                                              q, k, v, DD, DD);

        flash_attn_kernel<<<dim3(SS / 64, BB * HH), 128, faSmem>>>(q, k, v, tmp16);

        mma_gemm<1,false><<<gD, 256, gsN>>>(tmp16, Wo, Wo, Wo, x, x,
                                            nullptr, nullptr, DD, DD);

        layernorm_kernel<<<NTOK, 256>>>(x, ln2_w + l * DD, ln2_b + l * DD, h16);
        mma_gemm<2,false><<<gF, 256, gsN>>>(h16, W1, W1, W1, nullptr, ff16,
                                            nullptr, nullptr, DFF, DD);
        mma_gemm<1,false><<<gD, 256, gsN>>>(ff16, W2, W2, W2, x, x,
                                            nullptr, nullptr, DD, DFF);
    }

    layernorm_kernel<<<NTOK, 256>>>(x, lnf_w, lnf_b, h16);
    mma_gemm<0,true><<<dim3((VV + 127) / 128, NTOK / 128, 1), 256, gsT>>>(
        h16, wte16, wte16, wte16, nullptr, out, nullptr, nullptr, VV, DD);
}

// round 8
// speedup vs baseline: 1.6969x; 1.0025x over previous
#include <cuda_runtime.h>
#include <cuda_bf16.h>
#include <cuda_fp16.h>
#include <math.h>
#include <stdint.h>

// ---------------- problem constants ----------------
#define BB 4
#define SS 1024
#define LL 12
#define DD 768
#define HH 12
#define DKK 64
#define DFF 3072
#define VV 50257
#define NTOK (BB*SS)          // 4096
#define KPD (DD/2)            // 384
#define KPF (DFF/2)           // 1536

// ---------------- scratch (device globals; no allocs allowed) --------------
__device__ float g_x [(size_t)NTOK * DD];
__device__ float g_q [(size_t)NTOK * DD];
__device__ float g_k [(size_t)NTOK * DD];
__device__ float g_v [(size_t)NTOK * DD];
__device__ unsigned g_h16  [(size_t)NTOK * KPD];
__device__ unsigned g_tmp16[(size_t)NTOK * KPD];
__device__ unsigned g_ff16 [(size_t)NTOK * KPF];
// packed fp16 weights, K-major: [L][N][K/2] half2 words
__device__ unsigned g_wq16 [(size_t)LL * DD * KPD];
__device__ unsigned g_wk16 [(size_t)LL * DD * KPD];
__device__ unsigned g_wv16 [(size_t)LL * DD * KPD];
__device__ unsigned g_wo16 [(size_t)LL * DD * KPD];
__device__ unsigned g_fc116[(size_t)LL * DFF * KPD];
__device__ unsigned g_fc216[(size_t)LL * DD * KPF];
__device__ unsigned g_wte16[(size_t)VV * KPD];

// ---------------- helpers ----------------
__device__ __forceinline__ uint32_t smem_u32(const void* p) {
    uint32_t a;
    asm("{ .reg .u64 t; cvta.to.shared.u64 t, %1; cvt.u32.u64 %0, t; }"
        : "=r"(a) : "l"(p));
    return a;
}
__device__ __forceinline__ unsigned f2tf(float f) {
    unsigned u;
    asm("cvt.rna.tf32.f32 %0, %1;" : "=r"(u) : "f"(f));
    return u;
}
__device__ __forceinline__ void mma8(float* d, const unsigned* a, const unsigned* b) {
    asm volatile(
        "mma.sync.aligned.m16n8k8.row.col.f32.tf32.tf32.f32 "
        "{%0,%1,%2,%3},{%4,%5,%6,%7},{%8,%9},{%0,%1,%2,%3};"
        : "+f"(d[0]), "+f"(d[1]), "+f"(d[2]), "+f"(d[3])
        : "r"(a[0]), "r"(a[1]), "r"(a[2]), "r"(a[3]), "r"(b[0]), "r"(b[1]));
}
__device__ __forceinline__ void mma16(float* d, const unsigned* a, const unsigned* b) {
    asm volatile(
        "mma.sync.aligned.m16n8k16.row.col.f32.f16.f16.f32 "
        "{%0,%1,%2,%3},{%4,%5,%6,%7},{%8,%9},{%0,%1,%2,%3};"
        : "+f"(d[0]), "+f"(d[1]), "+f"(d[2]), "+f"(d[3])
        : "r"(a[0]), "r"(a[1]), "r"(a[2]), "r"(a[3]), "r"(b[0]), "r"(b[1]));
}
#define LDSM4(r0, r1, r2, r3, addr) \
    asm volatile("ldmatrix.sync.aligned.m8n8.x4.shared.b16 {%0,%1,%2,%3}, [%4];" \
                 : "=r"(r0), "=r"(r1), "=r"(r2), "=r"(r3) : "r"(addr))
__device__ __forceinline__ unsigned packh2(float lo, float hi) {
    __half2 h = __floats2half2_rn(lo, hi);
    return *reinterpret_cast<unsigned*>(&h);
}
__device__ __forceinline__ void cp16(uint32_t d, const void* g) {
    asm volatile("cp.async.cg.shared.global [%0], [%1], 16;" :: "r"(d), "l"(g));
}
__device__ __forceinline__ void cp16g(uint32_t d, const void* g, int sz) {
    asm volatile("cp.async.cg.shared.global [%0], [%1], 16, %2;"
                 :: "r"(d), "l"(g), "r"(sz));
}

// ---------------- weight packing (once per replay) ----------------
// W [L][K][N] f32 -> out [L][N][K/2] half2 (transpose via smem)
// grid (N/64, K/64, L), block 256
__global__ void pack_t(const float* __restrict__ W, unsigned* __restrict__ out,
                       int K, int N)
{
    __shared__ float t[64][65];
    const int n0 = blockIdx.x * 64, k0 = blockIdx.y * 64, l = blockIdx.z;
    const float* Wl = W + (size_t)l * K * N;
    unsigned* ol = out + (size_t)l * N * (K >> 1);
    const int tid = threadIdx.x;
    #pragma unroll
    for (int p = 0; p < 16; p++) {
        int idx = tid + p * 256;          // 0..4095
        int kk = idx >> 6, nn = idx & 63;
        t[kk][nn] = Wl[(size_t)(k0 + kk) * N + n0 + nn];
    }
    __syncthreads();
    #pragma unroll
    for (int p = 0; p < 8; p++) {
        int idx = tid + p * 256;          // 0..2047
        int nn = idx >> 5, kp = idx & 31;
        ol[(size_t)(n0 + nn) * (K >> 1) + (k0 >> 1) + kp] =
            packh2(t[2 * kp][nn], t[2 * kp + 1][nn]);
    }
}
// wte [V][K] f32 -> [V][K/2] half2
__global__ void pack_nk(const float* __restrict__ W, unsigned* __restrict__ out,
                        int total)
{
    int i = blockIdx.x * 256 + threadIdx.x;
    if (i >= total) return;
    int v = i / KPD, kp = i - v * KPD;
    float2 f = *(const float2*)(W + (size_t)v * DD + 2 * kp);
    out[i] = packh2(f.x, f.y);
}

// ---------------- fp16 NT GEMM: ldmatrix + cp.async pipeline ----------------
// C[4096 x N] = A16[M][K/2] @ B16[N][K/2]^T (+ epilogue)
// EPI: 0 none->f32, 1 +Cin->f32, 2 GELU->packed fp16
// NG: guard N (head gemm, N not multiple of 128)
// 256 threads, 8 warps (2x4), warp tile 64x32, BK=32, 3-stage cp.async.
#define APAD 20                      // words per tile row (16 used + 4 pad)
#define AW (128 * APAD)              // 2560 words per operand tile
#define STG (2 * AW)                 // 5120 words per stage

template<int EPI, bool NG>
__global__ __launch_bounds__(256, 2)
void mma_gemm(const unsigned* __restrict__ A,
              const unsigned* __restrict__ B0, const unsigned* __restrict__ B1,
              const unsigned* __restrict__ B2,
              const float* __restrict__ Cin, void* __restrict__ Cv,
              float* __restrict__ C1f, float* __restrict__ C2f,
              int N, int K)
{
    extern __shared__ unsigned gsm[];

    const unsigned* B = (blockIdx.z == 0) ? B0 : ((blockIdx.z == 1) ? B1 : B2);
    float* Cf = (blockIdx.z == 0) ? (float*)Cv : ((blockIdx.z == 1) ? C1f : C2f);
    unsigned* C16 = (unsigned*)Cv;

    const int tid  = threadIdx.x;
    const int lane = tid & 31;
    const int warp = tid >> 5;
    const int wm = warp >> 2, wn = warp & 3;       // 2 x 4
    const int lr = lane >> 2, lq = lane & 3;
    const int m0 = blockIdx.y * 128;
    const int n0 = blockIdx.x * 128;
    const int KA = K >> 1;

    const uint32_t sbase = smem_u32(gsm);

    // ldmatrix per-lane addressing
    const int lrow = lane & 7, lg = lane >> 3;
    // A: matrices (m+0..7,k0-7),(m+8..15,k0-7),(m+0..7,k8-15),(m+8..15,k8-15)
    const uint32_t aoff = (uint32_t)(((wm * 64 + (lg & 1) * 8 + lrow) * APAD
                                      + (lg >> 1) * 4) * 4);
    // B: matrices (n+0..7,k0-7),(n+0..7,k8-15),(n+8..15,k0-7),(n+8..15,k8-15)
    const uint32_t boff = (uint32_t)(((wn * 32 + (lg >> 1) * 8 + lrow) * APAD
                                      + (lg & 1) * 4) * 4);

    float acc[4][4][4];
    #pragma unroll
    for (int i = 0; i < 4; i++)
        #pragma unroll
        for (int j = 0; j < 4; j++)
            #pragma unroll
            for (int t = 0; t < 4; t++) acc[i][j][t] = 0.0f;

    auto load_stage = [&](int stg) {
        const int slot = stg % 3;
        const uint32_t sa = sbase + (uint32_t)(slot * STG) * 4u;
        const uint32_t sb = sa + (uint32_t)AW * 4u;
        const int kp0 = stg * 16;
        #pragma unroll
        for (int p = 0; p < 2; p++) {
            int s = tid * 2 + p;                   // 0..511
            int r = s >> 2, c4 = (s & 3) * 4;
            cp16(sa + (uint32_t)(r * APAD + c4) * 4u,
                 A + (size_t)(m0 + r) * KA + kp0 + c4);
        }
        #pragma unroll
        for (int p = 0; p < 2; p++) {
            int s = tid * 2 + p;
            int r = s >> 2, c4 = (s & 3) * 4;
            if (NG) {
                int n = n0 + r;
                int ok = (n < N);
                cp16g(sb + (uint32_t)(r * APAD + c4) * 4u,
                      B + (size_t)(ok ? n : 0) * KA + kp0 + c4, ok ? 16 : 0);
            } else {
                cp16(sb + (uint32_t)(r * APAD + c4) * 4u,
                     B + (size_t)(n0 + r) * KA + kp0 + c4);
            }
        }
        asm volatile("cp.async.commit_group;" ::: "memory");
    };

    auto compute = [&](int slot) {
        const uint32_t sa = sbase + (uint32_t)(slot * STG) * 4u;
        const uint32_t sb = sa + (uint32_t)AW * 4u;
        #pragma unroll
        for (int ks = 0; ks < 2; ks++) {
            const uint32_t kbb = (uint32_t)(ks * 32);      // 8 words
            unsigned af[4][4];
            #pragma unroll
            for (int mt = 0; mt < 4; mt++) {
                uint32_t addr = sa + aoff + kbb + (uint32_t)(mt * 16 * APAD * 4);
                LDSM4(af[mt][0], af[mt][1], af[mt][2], af[mt][3], addr);
            }
            unsigned bf[4][2];
            #pragma unroll
            for (int np = 0; np < 2; np++) {
                uint32_t addr = sb + boff + kbb + (uint32_t)(np * 16 * APAD * 4);
                unsigned r0, r1, r2, r3;
                LDSM4(r0, r1, r2, r3, addr);
                bf[np * 2][0] = r0;     bf[np * 2][1] = r1;
                bf[np * 2 + 1][0] = r2; bf[np * 2 + 1][1] = r3;
            }
            #pragma unroll
            for (int mt = 0; mt < 4; mt++)
                #pragma unroll
                for (int nt = 0; nt < 4; nt++)
                    mma16(acc[mt][nt], af[mt], bf[nt]);
        }
    };

    const int nIter = K >> 5;
    load_stage(0);
    load_stage(1);
    for (int it = 0; it < nIter; it++) {
        if (it + 1 < nIter) asm volatile("cp.async.wait_group 1;" ::: "memory");
        else                asm volatile("cp.async.wait_group 0;" ::: "memory");
        __syncthreads();
        if (it + 2 < nIter) load_stage(it + 2);
        compute(it % 3);
    }

    // ---- epilogue ----
    #pragma unroll
    for (int mt = 0; mt < 4; mt++) {
        int r0 = m0 + wm * 64 + mt * 16 + lr;
        #pragma unroll
        for (int nt = 0; nt < 4; nt++) {
            int col = n0 + wn * 32 + nt * 8 + lq * 2;
            float* a4 = acc[mt][nt];
            float v00 = a4[0], v01 = a4[1], v10 = a4[2], v11 = a4[3];
            if (EPI == 2) {
                v00 = 0.5f * v00 * (1.0f + erff(v00 * 0.70710678118654752f));
                v01 = 0.5f * v01 * (1.0f + erff(v01 * 0.70710678118654752f));
                v10 = 0.5f * v10 * (1.0f + erff(v10 * 0.70710678118654752f));
                v11 = 0.5f * v11 * (1.0f + erff(v11 * 0.70710678118654752f));
                int nw = N >> 1;
                C16[(size_t)r0 * nw + (col >> 1)]       = packh2(v00, v01);
                C16[(size_t)(r0 + 8) * nw + (col >> 1)] = packh2(v10, v11);
            } else {
                size_t o0 = (size_t)r0 * N + col;
                size_t o1 = (size_t)(r0 + 8) * N + col;
                if (EPI == 1) {
                    float2 c0 = *(const float2*)(Cin + o0);
                    float2 c1 = *(const float2*)(Cin + o1);
                    v00 += c0.x; v01 += c0.y; v10 += c1.x; v11 += c1.y;
                }
                if (!NG) {
                    *(float2*)(Cf + o0) = make_float2(v00, v01);
                    *(float2*)(Cf + o1) = make_float2(v10, v11);
                } else {
                    if (col < N)     { Cf[o0] = v00;     Cf[o1] = v10; }
                    if (col + 1 < N) { Cf[o0 + 1] = v01; Cf[o1 + 1] = v11; }
                }
            }
        }
    }
}

// ---------------- embedding ----------------
__global__ void embed_kernel(const int* __restrict__ idx,
                             const float* __restrict__ wte,
                             const float* __restrict__ wpe,
                             float* __restrict__ x)
{
    int row = blockIdx.x;
    int s   = row & (SS - 1);
    int tok = idx[row];
    int tid = threadIdx.x;
    #pragma unroll
    for (int l = 0; l < 3; l++) {
        int d = tid + l * 256;
        x[(size_t)row * DD + d] = wte[(size_t)tok * DD + d] + wpe[(size_t)s * DD + d];
    }
}

// ---------------- layernorm -> packed fp16 ----------------
__global__ void layernorm_kernel(const float* __restrict__ x,
                                 const float* __restrict__ w,
                                 const float* __restrict__ b,
                                 unsigned* __restrict__ y16)
{
    int row = blockIdx.x;
    const float2* p2 = (const float2*)(x + (size_t)row * DD);
    int tid = threadIdx.x;                 // 256
    float2 f1 = p2[tid];
    float2 f2 = (tid < 128) ? p2[tid + 256] : make_float2(0.f, 0.f);
    __shared__ float red[256];
    red[tid] = f1.x + f1.y + f2.x + f2.y;
    __syncthreads();
    for (int st = 128; st > 0; st >>= 1) {
        if (tid < st) red[tid] += red[tid + st];
        __syncthreads();
    }
    float mean = red[0] * (1.0f / DD);
    __syncthreads();
    float a0 = f1.x - mean, a1 = f1.y - mean;
    float a2 = f2.x - mean, a3 = f2.y - mean;
    red[tid] = a0 * a0 + a1 * a1 + ((tid < 128) ? (a2 * a2 + a3 * a3) : 0.f);
    __syncthreads();
    for (int st = 128; st > 0; st >>= 1) {
        if (tid < st) red[tid] += red[tid + st];
        __syncthreads();
    }
    float rstd = rsqrtf(red[0] * (1.0f / DD) + 1e-5f);
    const float2* w2 = (const float2*)w;
    const float2* b2 = (const float2*)b;
    unsigned* yr = y16 + (size_t)row * KPD;
    {
        float2 ww = w2[tid], bb = b2[tid];
        yr[tid] = packh2(a0 * rstd * ww.x + bb.x, a1 * rstd * ww.y + bb.y);
    }
    if (tid < 128) {
        float2 ww = w2[tid + 256], bb = b2[tid + 256];
        yr[tid + 256] = packh2(a2 * rstd * ww.x + bb.x, a3 * rstd * ww.y + bb.y);
    }
}

// ---------------- fused flash attention (tf32; fp16-packed output) ---------
#define FA_SQ   0
#define FA_SK   (64*68)
#define FA_SVH  (2*64*68)
#define FA_SVL  (2*64*68 + 64*72)
#define FA_SPST (2*64*68 + 2*64*72)
#define FA_SMEM_WORDS (2*64*68 + 2*64*72 + 4*256)

__global__ __launch_bounds__(128, 2)
void flash_attn_kernel(const float* __restrict__ Q, const float* __restrict__ K,
                       const float* __restrict__ V, unsigned* __restrict__ O16)
{
    extern __shared__ unsigned fsm[];
    unsigned* sQ  = fsm + FA_SQ;
    unsigned* sK  = fsm + FA_SK;
    unsigned* sVh = fsm + FA_SVH;
    unsigned* sVl = fsm + FA_SVL;

    const int tid  = threadIdx.x;
    const int lane = tid & 31;
    const int w    = tid >> 5;
    const int lr   = lane >> 2;
    const int lq   = lane & 3;
    const int it   = (SS / 64 - 1) - blockIdx.x;
    const int bh   = blockIdx.y;
    const int b    = bh / HH, h = bh % HH;
    const int i0   = it * 64;

    unsigned* myP = fsm + FA_SPST + w * 256;

    const float* Qb = Q + (size_t)(b * SS + i0) * DD + h * DKK;
    #pragma unroll
    for (int p = 0; p < 8; p++) {
        int idx = tid + p * 128;
        int r = idx >> 4, c4 = (idx & 15) * 4;
        float4 v = *(const float4*)(Qb + (size_t)r * DD + c4);
        unsigned* d = sQ + r * 68 + c4;
        d[0] = f2tf(v.x); d[1] = f2tf(v.y); d[2] = f2tf(v.z); d[3] = f2tf(v.w);
    }

    float oacc[8][4];
    #pragma unroll
    for (int nt = 0; nt < 8; nt++)
        #pragma unroll
        for (int e = 0; e < 4; e++) oacc[nt][e] = 0.0f;
    float m0 = -1e30f, m1 = -1e30f, l0 = 0.0f, l1 = 0.0f;

    for (int j0 = 0; j0 <= i0; j0 += 64) {
        __syncthreads();
        const float* Kb = K + (size_t)(b * SS + j0) * DD + h * DKK;
        const float* Vb = V + (size_t)(b * SS + j0) * DD + h * DKK;
        #pragma unroll
        for (int p = 0; p < 8; p++) {
            int idx = tid + p * 128;
            int r = idx >> 4, c4 = (idx & 15) * 4;
            float4 kv = *(const float4*)(Kb + (size_t)r * DD + c4);
            unsigned* dk = sK + r * 68 + c4;
            dk[0] = f2tf(kv.x); dk[1] = f2tf(kv.y); dk[2] = f2tf(kv.z); dk[3] = f2tf(kv.w);
            float4 vv = *(const float4*)(Vb + (size_t)r * DD + c4);
            unsigned* dh = sVh + r * 72 + c4;
            unsigned* dl = sVl + r * 72 + c4;
            unsigned h0 = f2tf(vv.x); dh[0] = h0; dl[0] = f2tf(vv.x - __uint_as_float(h0));
            unsigned h1 = f2tf(vv.y); dh[1] = h1; dl[1] = f2tf(vv.y - __uint_as_float(h1));
            unsigned h2 = f2tf(vv.z); dh[2] = h2; dl[2] = f2tf(vv.z - __uint_as_float(h2));
            unsigned h3 = f2tf(vv.w); dh[3] = h3; dl[3] = f2tf(vv.w - __uint_as_float(h3));
        }
        __syncthreads();

        float sacc[8][4];
        #pragma unroll
        for (int nt = 0; nt < 8; nt++)
            #pragma unroll
            for (int e = 0; e < 4; e++) sacc[nt][e] = 0.0f;

        #pragma unroll
        for (int kk = 0; kk < 8; kk++) {
            unsigned a[4];
            const unsigned* pa = sQ + (w * 16 + lr) * 68 + kk * 8 + lq;
            a[0] = pa[0]; a[1] = pa[8 * 68]; a[2] = pa[4]; a[3] = pa[8 * 68 + 4];
            #pragma unroll
            for (int nt = 0; nt < 8; nt++) {
                unsigned bf[2];
                const unsigned* pb = sK + (nt * 8 + lr) * 68 + kk * 8 + lq;
                bf[0] = pb[0]; bf[1] = pb[4];
                mma8(sacc[nt], a, bf);
            }
        }

        #pragma unroll
        for (int nt = 0; nt < 8; nt++)
            #pragma unroll
            for (int e = 0; e < 4; e++) sacc[nt][e] *= 0.125f;
        if (j0 == i0) {
            int ii0 = w * 16 + lr, ii1 = ii0 + 8;
            #pragma unroll
            for (int nt = 0; nt < 8; nt++) {
                int jj = nt * 8 + 2 * lq;
                if (jj     > ii0) sacc[nt][0] = -1e30f;
                if (jj + 1 > ii0) sacc[nt][1] = -1e30f;
                if (jj     > ii1) sacc[nt][2] = -1e30f;
                if (jj + 1 > ii1) sacc[nt][3] = -1e30f;
            }
        }

        float rm0 = -1e30f, rm1 = -1e30f;
        #pragma unroll
        for (int nt = 0; nt < 8; nt++) {
            rm0 = fmaxf(rm0, fmaxf(sacc[nt][0], sacc[nt][1]));
            rm1 = fmaxf(rm1, fmaxf(sacc[nt][2], sacc[nt][3]));
        }
        rm0 = fmaxf(rm0, __shfl_xor_sync(0xffffffffu, rm0, 1));
        rm0 = fmaxf(rm0, __shfl_xor_sync(0xffffffffu, rm0, 2));
        rm1 = fmaxf(rm1, __shfl_xor_sync(0xffffffffu, rm1, 1));
        rm1 = fmaxf(rm1, __shfl_xor_sync(0xffffffffu, rm1, 2));
        float mn0 = fmaxf(m0, rm0), mn1 = fmaxf(m1, rm1);
        float f0 = __expf(m0 - mn0), f1 = __expf(m1 - mn1);
        float ps0 = 0.0f, ps1 = 0.0f;
        #pragma unroll
        for (int nt = 0; nt < 8; nt++) {
            float p0 = __expf(sacc[nt][0] - mn0); sacc[nt][0] = p0; ps0 += p0;
            float p1 = __expf(sacc[nt][1] - mn0); sacc[nt][1] = p1; ps0 += p1;
            float p2 = __expf(sacc[nt][2] - mn1); sacc[nt][2] = p2; ps1 += p2;
            float p3 = __expf(sacc[nt][3] - mn1); sacc[nt][3] = p3; ps1 += p3;
        }
        ps0 += __shfl_xor_sync(0xffffffffu, ps0, 1);
        ps0 += __shfl_xor_sync(0xffffffffu, ps0, 2);
        ps1 += __shfl_xor_sync(0xffffffffu, ps1, 1);
        ps1 += __shfl_xor_sync(0xffffffffu, ps1, 2);
        l0 = l0 * f0 + ps0;
        l1 = l1 * f1 + ps1;
        m0 = mn0; m1 = mn1;
        #pragma unroll
        for (int nt = 0; nt < 8; nt++) {
            oacc[nt][0] *= f0; oacc[nt][1] *= f0;
            oacc[nt][2] *= f1; oacc[nt][3] *= f1;
        }

        #pragma unroll
        for (int kk = 0; kk < 8; kk++) {
            float p0 = sacc[kk][0], p1 = sacc[kk][1], p2 = sacc[kk][2], p3 = sacc[kk][3];
            unsigned h0 = f2tf(p0), h1 = f2tf(p1), h2 = f2tf(p2), h3 = f2tf(p3);
            unsigned e0 = f2tf(p0 - __uint_as_float(h0));
            unsigned e1 = f2tf(p1 - __uint_as_float(h1));
            unsigned e2 = f2tf(p2 - __uint_as_float(h2));
            unsigned e3 = f2tf(p3 - __uint_as_float(h3));
            myP[lr * 8 + 2 * lq]             = h0;
            myP[lr * 8 + 2 * lq + 1]         = h1;
            myP[(lr + 8) * 8 + 2 * lq]       = h2;
            myP[(lr + 8) * 8 + 2 * lq + 1]   = h3;
            myP[128 + lr * 8 + 2 * lq]           = e0;
            myP[128 + lr * 8 + 2 * lq + 1]       = e1;
            myP[128 + (lr + 8) * 8 + 2 * lq]     = e2;
            myP[128 + (lr + 8) * 8 + 2 * lq + 1] = e3;
            __syncwarp();
            unsigned ah[4], al[4];
            ah[0] = myP[lr * 8 + lq];
            ah[1] = myP[(lr + 8) * 8 + lq];
            ah[2] = myP[lr * 8 + lq + 4];
            ah[3] = myP[(lr + 8) * 8 + lq + 4];
            al[0] = myP[128 + lr * 8 + lq];
            al[1] = myP[128 + (lr + 8) * 8 + lq];
            al[2] = myP[128 + lr * 8 + lq + 4];
            al[3] = myP[128 + (lr + 8) * 8 + lq + 4];
            __syncwarp();
            #pragma unroll
            for (int nt = 0; nt < 8; nt++) {
                unsigned bhv[2], blv[2];
                const unsigned* pvh = sVh + (kk * 8 + lq) * 72 + nt * 8 + lr;
                bhv[0] = pvh[0]; bhv[1] = pvh[4 * 72];
                const unsigned* pvl = sVl + (kk * 8 + lq) * 72 + nt * 8 + lr;
                blv[0] = pvl[0]; blv[1] = pvl[4 * 72];
                mma8(oacc[nt], ah, bhv);
                mma8(oacc[nt], al, bhv);
                mma8(oacc[nt], ah, blv);
            }
        }
    }

    float inv0 = 1.0f / l0, inv1 = 1.0f / l1;
    int row0 = b * SS + i0 + w * 16 + lr;
    unsigned* Ob = O16 + (size_t)row0 * KPD + h * 32;
    #pragma unroll
    for (int nt = 0; nt < 8; nt++) {
        Ob[nt * 4 + lq] = packh2(oacc[nt][0] * inv0, oacc[nt][1] * inv0);
        Ob[(size_t)8 * KPD + nt * 4 + lq] = packh2(oacc[nt][2] * inv1, oacc[nt][3] * inv1);
    }
}

// ---------------- host launcher ----------------
extern "C" void kernel_launch(void* const* d_in, const int* in_sizes, int n_in,
                              void* d_out, int out_size)
{
    const int*   idx   = (const int*)  d_in[0];
    const float* wte   = (const float*)d_in[1];
    const float* wpe   = (const float*)d_in[2];
    const float* ln1_w = (const float*)d_in[3];
    const float* ln1_b = (const float*)d_in[4];
    const float* wq    = (const float*)d_in[5];
    const float* wk    = (const float*)d_in[6];
    const float* wv    = (const float*)d_in[7];
    const float* wo    = (const float*)d_in[8];
    const float* ln2_w = (const float*)d_in[9];
    const float* ln2_b = (const float*)d_in[10];
    const float* fc1   = (const float*)d_in[11];
    const float* fc2   = (const float*)d_in[12];
    const float* lnf_w = (const float*)d_in[13];
    const float* lnf_b = (const float*)d_in[14];
    float* out = (float*)d_out;

    float *x, *q, *k, *v;
    unsigned *h16, *tmp16, *ff16;
    unsigned *wq16, *wk16, *wv16, *wo16, *fc116, *fc216, *wte16;
    cudaGetSymbolAddress((void**)&x,     g_x);
    cudaGetSymbolAddress((void**)&q,     g_q);
    cudaGetSymbolAddress((void**)&k,     g_k);
    cudaGetSymbolAddress((void**)&v,     g_v);
    cudaGetSymbolAddress((void**)&h16,   g_h16);
    cudaGetSymbolAddress((void**)&tmp16, g_tmp16);
    cudaGetSymbolAddress((void**)&ff16,  g_ff16);
    cudaGetSymbolAddress((void**)&wq16,  g_wq16);
    cudaGetSymbolAddress((void**)&wk16,  g_wk16);
    cudaGetSymbolAddress((void**)&wv16,  g_wv16);
    cudaGetSymbolAddress((void**)&wo16,  g_wo16);
    cudaGetSymbolAddress((void**)&fc116, g_fc116);
    cudaGetSymbolAddress((void**)&fc216, g_fc216);
    cudaGetSymbolAddress((void**)&wte16, g_wte16);

    const int faSmem = FA_SMEM_WORDS * 4;
    const int gs = 3 * STG * 4;      // 61440
    cudaFuncSetAttribute(flash_attn_kernel,
                         cudaFuncAttributeMaxDynamicSharedMemorySize, faSmem);
    cudaFuncSetAttribute(mma_gemm<0,false>, cudaFuncAttributeMaxDynamicSharedMemorySize, gs);
    cudaFuncSetAttribute(mma_gemm<1,false>, cudaFuncAttributeMaxDynamicSharedMemorySize, gs);
    cudaFuncSetAttribute(mma_gemm<2,false>, cudaFuncAttributeMaxDynamicSharedMemorySize, gs);
    cudaFuncSetAttribute(mma_gemm<0,true>,  cudaFuncAttributeMaxDynamicSharedMemorySize, gs);

    // ---- pack weights to fp16 K-major [L][N][K/2] ----
    pack_t<<<dim3(DD / 64, DD / 64, LL), 256>>>(wq, wq16, DD, DD);
    pack_t<<<dim3(DD / 64, DD / 64, LL), 256>>>(wk, wk16, DD, DD);
    pack_t<<<dim3(DD / 64, DD / 64, LL), 256>>>(wv, wv16, DD, DD);
    pack_t<<<dim3(DD / 64, DD / 64, LL), 256>>>(wo, wo16, DD, DD);
    pack_t<<<dim3(DFF / 64, DD / 64, LL), 256>>>(fc1, fc116, DD, DFF);
    pack_t<<<dim3(DD / 64, DFF / 64, LL), 256>>>(fc2, fc216, DFF, DD);
    {
        int tE = VV * KPD;
        pack_nk<<<(tE + 255) / 256, 256>>>(wte, wte16, tE);
    }

    embed_kernel<<<NTOK, 256>>>(idx, wte, wpe, x);

    dim3 gQKV(DD / 128, NTOK / 128, 3);
    dim3 gD  (DD / 128, NTOK / 128, 1);
    dim3 gF  (DFF / 128, NTOK / 128, 1);

    for (int l = 0; l < LL; l++) {
        unsigned* Wq = wq16 + (size_t)l * DD * KPD;
        unsigned* Wk = wk16 + (size_t)l * DD * KPD;
        unsigned* Wv = wv16 + (size_t)l * DD * KPD;
        unsigned* Wo = wo16 + (size_t)l * DD * KPD;
        unsigned* W1 = fc116 + (size_t)l * DFF * KPD;
        unsigned* W2 = fc216 + (size_t)l * DD * KPF;

        layernorm_kernel<<<NTOK, 256>>>(x, ln1_w + l * DD, ln1_b + l * DD, h16);

        mma_gemm<0,false><<<gQKV, 256, gs>>>(h16, Wq, Wk, Wv, nullptr,
                                             q, k, v, DD, DD);

        flash_attn_kernel<<<dim3(SS / 64, BB * HH), 128, faSmem>>>(q, k, v, tmp16);

        mma_gemm<1,false><<<gD, 256, gs>>>(tmp16, Wo, Wo, Wo, x, x,
                                           nullptr, nullptr, DD, DD);

        layernorm_kernel<<<NTOK, 256>>>(x, ln2_w + l * DD, ln2_b + l * DD, h16);
        mma_gemm<2,false><<<gF, 256, gs>>>(h16, W1, W1, W1, nullptr, ff16,
                                           nullptr, nullptr, DFF, DD);
        mma_gemm<1,false><<<gD, 256, gs>>>(ff16, W2, W2, W2, x, x,
                                           nullptr, nullptr, DD, DFF);
    }

    layernorm_kernel<<<NTOK, 256>>>(x, lnf_w, lnf_b, h16);
    mma_gemm<0,true><<<dim3((VV + 127) / 128, NTOK / 128, 1), 256, gs>>>(
        h16, wte16, wte16, wte16, nullptr, out, nullptr, nullptr, VV, DD);
}

// round 9
// speedup vs baseline: 1.8822x; 1.1092x over previous
#include <cuda_runtime.h>
#include <cuda_bf16.h>
#include <cuda_fp16.h>
#include <math.h>
#include <stdint.h>

// ---------------- problem constants ----------------
#define BB 4
#define SS 1024
#define LL 12
#define DD 768
#define HH 12
#define DKK 64
#define DFF 3072
#define VV 50257
#define NTOK (BB*SS)          // 4096
#define KPD (DD/2)            // 384
#define KPF (DFF/2)           // 1536

// ---------------- scratch (device globals; no allocs allowed) --------------
__device__ float g_x [(size_t)NTOK * DD];
__device__ float g_v [(size_t)NTOK * DD];
__device__ unsigned g_q16 [(size_t)NTOK * KPD];
__device__ unsigned g_k16 [(size_t)NTOK * KPD];
__device__ unsigned g_h16 [(size_t)NTOK * KPD];
__device__ unsigned g_tmp16[(size_t)NTOK * KPD];
__device__ unsigned g_ff16 [(size_t)NTOK * KPF];
__device__ unsigned g_vph [(size_t)BB * HH * DKK * (SS/2)];
__device__ unsigned g_vpl [(size_t)BB * HH * DKK * (SS/2)];
// packed fp16 weights, K-major: [L][N][K/2] half2 words
__device__ unsigned g_wq16 [(size_t)LL * DD * KPD];
__device__ unsigned g_wk16 [(size_t)LL * DD * KPD];
__device__ unsigned g_wv16 [(size_t)LL * DD * KPD];
__device__ unsigned g_wo16 [(size_t)LL * DD * KPD];
__device__ unsigned g_fc116[(size_t)LL * DFF * KPD];
__device__ unsigned g_fc216[(size_t)LL * DD * KPF];
__device__ unsigned g_wte16[(size_t)VV * KPD];

// ---------------- helpers ----------------
__device__ __forceinline__ uint32_t smem_u32(const void* p) {
    uint32_t a;
    asm("{ .reg .u64 t; cvta.to.shared.u64 t, %1; cvt.u32.u64 %0, t; }"
        : "=r"(a) : "l"(p));
    return a;
}
__device__ __forceinline__ void mma16(float* d, const unsigned* a, const unsigned* b) {
    asm volatile(
        "mma.sync.aligned.m16n8k16.row.col.f32.f16.f16.f32 "
        "{%0,%1,%2,%3},{%4,%5,%6,%7},{%8,%9},{%0,%1,%2,%3};"
        : "+f"(d[0]), "+f"(d[1]), "+f"(d[2]), "+f"(d[3])
        : "r"(a[0]), "r"(a[1]), "r"(a[2]), "r"(a[3]), "r"(b[0]), "r"(b[1]));
}
#define LDSM4(r0, r1, r2, r3, addr) \
    asm volatile("ldmatrix.sync.aligned.m8n8.x4.shared.b16 {%0,%1,%2,%3}, [%4];" \
                 : "=r"(r0), "=r"(r1), "=r"(r2), "=r"(r3) : "r"(addr))
__device__ __forceinline__ unsigned packh2(float lo, float hi) {
    __half2 h = __floats2half2_rn(lo, hi);
    return *reinterpret_cast<unsigned*>(&h);
}
__device__ __forceinline__ void cp16(uint32_t d, const void* g) {
    asm volatile("cp.async.cg.shared.global [%0], [%1], 16;" :: "r"(d), "l"(g));
}
__device__ __forceinline__ void cp16g(uint32_t d, const void* g, int sz) {
    asm volatile("cp.async.cg.shared.global [%0], [%1], 16, %2;"
                 :: "r"(d), "l"(g), "r"(sz));
}

// ---------------- weight packing (once per replay) ----------------
__global__ void pack_t(const float* __restrict__ W, unsigned* __restrict__ out,
                       int K, int N)
{
    __shared__ float t[64][65];
    const int n0 = blockIdx.x * 64, k0 = blockIdx.y * 64, l = blockIdx.z;
    const float* Wl = W + (size_t)l * K * N;
    unsigned* ol = out + (size_t)l * N * (K >> 1);
    const int tid = threadIdx.x;
    #pragma unroll
    for (int p = 0; p < 16; p++) {
        int idx = tid + p * 256;
        int kk = idx >> 6, nn = idx & 63;
        t[kk][nn] = Wl[(size_t)(k0 + kk) * N + n0 + nn];
    }
    __syncthreads();
    #pragma unroll
    for (int p = 0; p < 8; p++) {
        int idx = tid + p * 256;
        int nn = idx >> 5, kp = idx & 31;
        ol[(size_t)(n0 + nn) * (K >> 1) + (k0 >> 1) + kp] =
            packh2(t[2 * kp][nn], t[2 * kp + 1][nn]);
    }
}
__global__ void pack_nk(const float* __restrict__ W, unsigned* __restrict__ out,
                        int total)
{
    int i = blockIdx.x * 256 + threadIdx.x;
    if (i >= total) return;
    int v = i / KPD, kp = i - v * KPD;
    float2 f = *(const float2*)(W + (size_t)v * DD + 2 * kp);
    out[i] = packh2(f.x, f.y);
}

// ---------------- V transpose: f32 [row][D] -> fp16 hi/lo [bh*64+dk][jpair] --
__global__ void vtrans_kernel(const float* __restrict__ v,
                              unsigned* __restrict__ vph,
                              unsigned* __restrict__ vpl)
{
    __shared__ float t[64][65];
    const int j0 = blockIdx.x * 64;
    const int bh = blockIdx.y;
    const int b = bh / HH, h = bh % HH;
    const int tid = threadIdx.x;
    #pragma unroll
    for (int p = 0; p < 16; p++) {
        int idx = tid + p * 256;
        int j = idx >> 6, dk = idx & 63;
        t[j][dk] = v[(size_t)(b * SS + j0 + j) * DD + h * DKK + dk];
    }
    __syncthreads();
    #pragma unroll
    for (int p = 0; p < 8; p++) {
        int idx = tid + p * 256;
        int dk = idx >> 5, jp = idx & 31;
        float v0 = t[2 * jp][dk], v1 = t[2 * jp + 1][dk];
        __half h0 = __float2half_rn(v0), h1 = __float2half_rn(v1);
        float l0 = v0 - __half2float(h0), l1 = v1 - __half2float(h1);
        __half2 hh = __halves2half2(h0, h1);
        size_t o = ((size_t)bh * DKK + dk) * (SS / 2) + (j0 >> 1) + jp;
        vph[o] = *reinterpret_cast<unsigned*>(&hh);
        vpl[o] = packh2(l0, l1);
    }
}

// ---------------- fp16 NT GEMM: ldmatrix + cp.async pipeline ----------------
// EPI: 0 none->f32, 1 +Cin->f32, 2 GELU->packed fp16, 3 QKV (z<2 fp16, z=2 f32)
// NG: guard N (head gemm)
#define APAD 20
#define AW (128 * APAD)
#define STG (2 * AW)

template<int EPI, bool NG>
__global__ __launch_bounds__(256, 2)
void mma_gemm(const unsigned* __restrict__ A,
              const unsigned* __restrict__ B0, const unsigned* __restrict__ B1,
              const unsigned* __restrict__ B2,
              const float* __restrict__ Cin, void* __restrict__ Cv,
              float* __restrict__ C1f, float* __restrict__ C2f,
              int N, int K)
{
    extern __shared__ unsigned gsm[];

    const unsigned* B = (blockIdx.z == 0) ? B0 : ((blockIdx.z == 1) ? B1 : B2);
    float* Cf = (blockIdx.z == 0) ? (float*)Cv : ((blockIdx.z == 1) ? C1f : C2f);
    unsigned* C16 = (unsigned*)Cv;

    const int tid  = threadIdx.x;
    const int lane = tid & 31;
    const int warp = tid >> 5;
    const int wm = warp >> 2, wn = warp & 3;
    const int lr = lane >> 2, lq = lane & 3;
    const int m0 = blockIdx.y * 128;
    const int n0 = blockIdx.x * 128;
    const int KA = K >> 1;

    const uint32_t sbase = smem_u32(gsm);
    const int lrow = lane & 7, lg = lane >> 3;
    const uint32_t aoff = (uint32_t)(((wm * 64 + (lg & 1) * 8 + lrow) * APAD
                                      + (lg >> 1) * 4) * 4);
    const uint32_t boff = (uint32_t)(((wn * 32 + (lg >> 1) * 8 + lrow) * APAD
                                      + (lg & 1) * 4) * 4);

    float acc[4][4][4];
    #pragma unroll
    for (int i = 0; i < 4; i++)
        #pragma unroll
        for (int j = 0; j < 4; j++)
            #pragma unroll
            for (int t = 0; t < 4; t++) acc[i][j][t] = 0.0f;

    auto load_stage = [&](int stg) {
        const int slot = stg % 3;
        const uint32_t sa = sbase + (uint32_t)(slot * STG) * 4u;
        const uint32_t sb = sa + (uint32_t)AW * 4u;
        const int kp0 = stg * 16;
        #pragma unroll
        for (int p = 0; p < 2; p++) {
            int s = tid * 2 + p;
            int r = s >> 2, c4 = (s & 3) * 4;
            cp16(sa + (uint32_t)(r * APAD + c4) * 4u,
                 A + (size_t)(m0 + r) * KA + kp0 + c4);
        }
        #pragma unroll
        for (int p = 0; p < 2; p++) {
            int s = tid * 2 + p;
            int r = s >> 2, c4 = (s & 3) * 4;
            if (NG) {
                int n = n0 + r;
                int ok = (n < N);
                cp16g(sb + (uint32_t)(r * APAD + c4) * 4u,
                      B + (size_t)(ok ? n : 0) * KA + kp0 + c4, ok ? 16 : 0);
            } else {
                cp16(sb + (uint32_t)(r * APAD + c4) * 4u,
                     B + (size_t)(n0 + r) * KA + kp0 + c4);
            }
        }
        asm volatile("cp.async.commit_group;" ::: "memory");
    };

    auto compute = [&](int slot) {
        const uint32_t sa = sbase + (uint32_t)(slot * STG) * 4u;
        const uint32_t sb = sa + (uint32_t)AW * 4u;
        #pragma unroll
        for (int ks = 0; ks < 2; ks++) {
            const uint32_t kbb = (uint32_t)(ks * 32);
            unsigned af[4][4];
            #pragma unroll
            for (int mt = 0; mt < 4; mt++) {
                uint32_t addr = sa + aoff + kbb + (uint32_t)(mt * 16 * APAD * 4);
                LDSM4(af[mt][0], af[mt][1], af[mt][2], af[mt][3], addr);
            }
            unsigned bf[4][2];
            #pragma unroll
            for (int np = 0; np < 2; np++) {
                uint32_t addr = sb + boff + kbb + (uint32_t)(np * 16 * APAD * 4);
                unsigned r0, r1, r2, r3;
                LDSM4(r0, r1, r2, r3, addr);
                bf[np * 2][0] = r0;     bf[np * 2][1] = r1;
                bf[np * 2 + 1][0] = r2; bf[np * 2 + 1][1] = r3;
            }
            #pragma unroll
            for (int mt = 0; mt < 4; mt++)
                #pragma unroll
                for (int nt = 0; nt < 4; nt++)
                    mma16(acc[mt][nt], af[mt], bf[nt]);
        }
    };

    const int nIter = K >> 5;
    load_stage(0);
    load_stage(1);
    for (int it = 0; it < nIter; it++) {
        if (it + 1 < nIter) asm volatile("cp.async.wait_group 1;" ::: "memory");
        else                asm volatile("cp.async.wait_group 0;" ::: "memory");
        __syncthreads();
        if (it + 2 < nIter) load_stage(it + 2);
        compute(it % 3);
    }

    // ---- epilogue ----
    #pragma unroll
    for (int mt = 0; mt < 4; mt++) {
        int r0 = m0 + wm * 64 + mt * 16 + lr;
        #pragma unroll
        for (int nt = 0; nt < 4; nt++) {
            int col = n0 + wn * 32 + nt * 8 + lq * 2;
            float* a4 = acc[mt][nt];
            float v00 = a4[0], v01 = a4[1], v10 = a4[2], v11 = a4[3];
            if (EPI == 2) {
                v00 = 0.5f * v00 * (1.0f + erff(v00 * 0.70710678118654752f));
                v01 = 0.5f * v01 * (1.0f + erff(v01 * 0.70710678118654752f));
                v10 = 0.5f * v10 * (1.0f + erff(v10 * 0.70710678118654752f));
                v11 = 0.5f * v11 * (1.0f + erff(v11 * 0.70710678118654752f));
                int nw = N >> 1;
                C16[(size_t)r0 * nw + (col >> 1)]       = packh2(v00, v01);
                C16[(size_t)(r0 + 8) * nw + (col >> 1)] = packh2(v10, v11);
            } else if (EPI == 3) {
                if (blockIdx.z == 2) {
                    size_t o0 = (size_t)r0 * N + col;
                    size_t o1 = (size_t)(r0 + 8) * N + col;
                    *(float2*)(C2f + o0) = make_float2(v00, v01);
                    *(float2*)(C2f + o1) = make_float2(v10, v11);
                } else {
                    unsigned* o = (blockIdx.z == 0) ? (unsigned*)Cv : (unsigned*)C1f;
                    int nw = N >> 1;
                    o[(size_t)r0 * nw + (col >> 1)]       = packh2(v00, v01);
                    o[(size_t)(r0 + 8) * nw + (col >> 1)] = packh2(v10, v11);
                }
            } else {
                size_t o0 = (size_t)r0 * N + col;
                size_t o1 = (size_t)(r0 + 8) * N + col;
                if (EPI == 1) {
                    float2 c0 = *(const float2*)(Cin + o0);
                    float2 c1 = *(const float2*)(Cin + o1);
                    v00 += c0.x; v01 += c0.y; v10 += c1.x; v11 += c1.y;
                }
                if (!NG) {
                    *(float2*)(Cf + o0) = make_float2(v00, v01);
                    *(float2*)(Cf + o1) = make_float2(v10, v11);
                } else {
                    if (col < N)     { Cf[o0] = v00;     Cf[o1] = v10; }
                    if (col + 1 < N) { Cf[o0 + 1] = v01; Cf[o1 + 1] = v11; }
                }
            }
        }
    }
}

// ---------------- embedding ----------------
__global__ void embed_kernel(const int* __restrict__ idx,
                             const float* __restrict__ wte,
                             const float* __restrict__ wpe,
                             float* __restrict__ x)
{
    int row = blockIdx.x;
    int s   = row & (SS - 1);
    int tok = idx[row];
    int tid = threadIdx.x;
    #pragma unroll
    for (int l = 0; l < 3; l++) {
        int d = tid + l * 256;
        x[(size_t)row * DD + d] = wte[(size_t)tok * DD + d] + wpe[(size_t)s * DD + d];
    }
}

// ---------------- layernorm -> packed fp16 ----------------
__global__ void layernorm_kernel(const float* __restrict__ x,
                                 const float* __restrict__ w,
                                 const float* __restrict__ b,
                                 unsigned* __restrict__ y16)
{
    int row = blockIdx.x;
    const float2* p2 = (const float2*)(x + (size_t)row * DD);
    int tid = threadIdx.x;
    float2 f1 = p2[tid];
    float2 f2 = (tid < 128) ? p2[tid + 256] : make_float2(0.f, 0.f);
    __shared__ float red[256];
    red[tid] = f1.x + f1.y + f2.x + f2.y;
    __syncthreads();
    for (int st = 128; st > 0; st >>= 1) {
        if (tid < st) red[tid] += red[tid + st];
        __syncthreads();
    }
    float mean = red[0] * (1.0f / DD);
    __syncthreads();
    float a0 = f1.x - mean, a1 = f1.y - mean;
    float a2 = f2.x - mean, a3 = f2.y - mean;
    red[tid] = a0 * a0 + a1 * a1 + ((tid < 128) ? (a2 * a2 + a3 * a3) : 0.f);
    __syncthreads();
    for (int st = 128; st > 0; st >>= 1) {
        if (tid < st) red[tid] += red[tid + st];
        __syncthreads();
    }
    float rstd = rsqrtf(red[0] * (1.0f / DD) + 1e-5f);
    const float2* w2 = (const float2*)w;
    const float2* b2 = (const float2*)b;
    unsigned* yr = y16 + (size_t)row * KPD;
    {
        float2 ww = w2[tid], bb = b2[tid];
        yr[tid] = packh2(a0 * rstd * ww.x + bb.x, a1 * rstd * ww.y + bb.y);
    }
    if (tid < 128) {
        float2 ww = w2[tid + 256], bb = b2[tid + 256];
        yr[tid + 256] = packh2(a2 * rstd * ww.x + bb.x, a3 * rstd * ww.y + bb.y);
    }
}

// ---------------- fused flash attention (fp16 tensor cores) ----------------
// grid (16, 48), block 128 (4 warps, 16 query rows each).
// Q,K fp16 packed [row][KPD]; V^T hi/lo fp16 [bh*64+dk][jpair].
// QK: mma16. PV: compensated fp16 (PhiVhi + PloVhi + PhiVlo), P frags from regs.
#define FST 36   // smem row stride (32 words + 4 pad)

__global__ __launch_bounds__(128, 3)
void flash_attn_kernel(const unsigned* __restrict__ q16,
                       const unsigned* __restrict__ k16,
                       const unsigned* __restrict__ vph,
                       const unsigned* __restrict__ vpl,
                       unsigned* __restrict__ O16)
{
    __shared__ unsigned sQ[64 * FST], sK[64 * FST], sVh[64 * FST], sVl[64 * FST];

    const int tid  = threadIdx.x;
    const int lane = tid & 31;
    const int w    = tid >> 5;
    const int lr   = lane >> 2;
    const int lq   = lane & 3;
    const int it   = (SS / 64 - 1) - blockIdx.x;   // heavy tiles first
    const int bh   = blockIdx.y;
    const int b    = bh / HH, h = bh % HH;
    const int i0   = it * 64;
    const int lrow = lane & 7, lg = lane >> 3;

    const uint32_t sQb = smem_u32(sQ), sKb = smem_u32(sK);
    const uint32_t sVhb = smem_u32(sVh), sVlb = smem_u32(sVl);
    const uint32_t aoff = (uint32_t)(((w * 16 + (lg & 1) * 8 + lrow) * FST
                                      + (lg >> 1) * 4) * 4);
    const uint32_t boff = (uint32_t)((((lg >> 1) * 8 + lrow) * FST
                                      + (lg & 1) * 4) * 4);

    // ---- load Q tile (64 x 32 words) ----
    #pragma unroll
    for (int p = 0; p < 4; p++) {
        int s = tid + p * 128;
        int r = s >> 3, c4 = (s & 7) * 4;
        cp16(sQb + (uint32_t)(r * FST + c4) * 4u,
             q16 + (size_t)(b * SS + i0 + r) * KPD + h * 32 + c4);
    }
    asm volatile("cp.async.commit_group;" ::: "memory");
    asm volatile("cp.async.wait_group 0;" ::: "memory");
    __syncthreads();

    // Q fragments (loop-invariant)
    unsigned qf[4][4];
    #pragma unroll
    for (int kc = 0; kc < 4; kc++)
        LDSM4(qf[kc][0], qf[kc][1], qf[kc][2], qf[kc][3], sQb + aoff + kc * 32);

    float oacc[8][4];
    #pragma unroll
    for (int nt = 0; nt < 8; nt++)
        #pragma unroll
        for (int e = 0; e < 4; e++) oacc[nt][e] = 0.0f;
    float m0 = -1e30f, m1 = -1e30f, l0 = 0.0f, l1 = 0.0f;

    for (int j0 = 0; j0 <= i0; j0 += 64) {
        __syncthreads();   // all warps done with previous tile
        #pragma unroll
        for (int p = 0; p < 4; p++) {
            int s = tid + p * 128;
            int r = s >> 3, c4 = (s & 7) * 4;
            cp16(sKb + (uint32_t)(r * FST + c4) * 4u,
                 k16 + (size_t)(b * SS + j0 + r) * KPD + h * 32 + c4);
            size_t vo = ((size_t)bh * DKK + r) * (SS / 2) + (j0 >> 1) + c4;
            cp16(sVhb + (uint32_t)(r * FST + c4) * 4u, vph + vo);
            cp16(sVlb + (uint32_t)(r * FST + c4) * 4u, vpl + vo);
        }
        asm volatile("cp.async.commit_group;" ::: "memory");
        asm volatile("cp.async.wait_group 0;" ::: "memory");
        __syncthreads();

        // ---- S = Q @ K^T ----
        float sacc[8][4];
        #pragma unroll
        for (int nt = 0; nt < 8; nt++)
            #pragma unroll
            for (int e = 0; e < 4; e++) sacc[nt][e] = 0.0f;
        #pragma unroll
        for (int kc = 0; kc < 4; kc++) {
            #pragma unroll
            for (int nb = 0; nb < 4; nb++) {
                unsigned r0, r1, r2, r3;
                LDSM4(r0, r1, r2, r3,
                      sKb + boff + (uint32_t)(nb * 16 * FST * 4) + kc * 32);
                unsigned b0[2] = {r0, r1}, b1[2] = {r2, r3};
                mma16(sacc[nb * 2],     qf[kc], b0);
                mma16(sacc[nb * 2 + 1], qf[kc], b1);
            }
        }

        // ---- scale + causal mask ----
        #pragma unroll
        for (int nt = 0; nt < 8; nt++)
            #pragma unroll
            for (int e = 0; e < 4; e++) sacc[nt][e] *= 0.125f;
        if (j0 == i0) {
            int ii0 = w * 16 + lr, ii1 = ii0 + 8;
            #pragma unroll
            for (int nt = 0; nt < 8; nt++) {
                int jj = nt * 8 + 2 * lq;
                if (jj     > ii0) sacc[nt][0] = -1e30f;
                if (jj + 1 > ii0) sacc[nt][1] = -1e30f;
                if (jj     > ii1) sacc[nt][2] = -1e30f;
                if (jj + 1 > ii1) sacc[nt][3] = -1e30f;
            }
        }

        // ---- online softmax ----
        float rm0 = -1e30f, rm1 = -1e30f;
        #pragma unroll
        for (int nt = 0; nt < 8; nt++) {
            rm0 = fmaxf(rm0, fmaxf(sacc[nt][0], sacc[nt][1]));
            rm1 = fmaxf(rm1, fmaxf(sacc[nt][2], sacc[nt][3]));
        }
        rm0 = fmaxf(rm0, __shfl_xor_sync(0xffffffffu, rm0, 1));
        rm0 = fmaxf(rm0, __shfl_xor_sync(0xffffffffu, rm0, 2));
        rm1 = fmaxf(rm1, __shfl_xor_sync(0xffffffffu, rm1, 1));
        rm1 = fmaxf(rm1, __shfl_xor_sync(0xffffffffu, rm1, 2));
        float mn0 = fmaxf(m0, rm0), mn1 = fmaxf(m1, rm1);
        float f0 = __expf(m0 - mn0), f1 = __expf(m1 - mn1);
        float ps0 = 0.0f, ps1 = 0.0f;
        #pragma unroll
        for (int nt = 0; nt < 8; nt++) {
            float p0 = __expf(sacc[nt][0] - mn0); sacc[nt][0] = p0; ps0 += p0;
            float p1 = __expf(sacc[nt][1] - mn0); sacc[nt][1] = p1; ps0 += p1;
            float p2 = __expf(sacc[nt][2] - mn1); sacc[nt][2] = p2; ps1 += p2;
            float p3 = __expf(sacc[nt][3] - mn1); sacc[nt][3] = p3; ps1 += p3;
        }
        ps0 += __shfl_xor_sync(0xffffffffu, ps0, 1);
        ps0 += __shfl_xor_sync(0xffffffffu, ps0, 2);
        ps1 += __shfl_xor_sync(0xffffffffu, ps1, 1);
        ps1 += __shfl_xor_sync(0xffffffffu, ps1, 2);
        l0 = l0 * f0 + ps0;
        l1 = l1 * f1 + ps1;
        m0 = mn0; m1 = mn1;
        #pragma unroll
        for (int nt = 0; nt < 8; nt++) {
            oacc[nt][0] *= f0; oacc[nt][1] *= f0;
            oacc[nt][2] *= f1; oacc[nt][3] *= f1;
        }

        // ---- O += P @ V (compensated fp16; P frags direct from regs) ----
        #pragma unroll
        for (int kc = 0; kc < 4; kc++) {
            unsigned ah[4], al[4];
            #pragma unroll
            for (int hsel = 0; hsel < 2; hsel++) {
                const float* s0 = sacc[2 * kc + hsel];
                unsigned hi0 = packh2(s0[0], s0[1]);
                unsigned hi1 = packh2(s0[2], s0[3]);
                __half2 h2a = *reinterpret_cast<__half2*>(&hi0);
                __half2 h2b = *reinterpret_cast<__half2*>(&hi1);
                float2 fa = __half22float2(h2a);
                float2 fb = __half22float2(h2b);
                ah[hsel * 2]     = hi0;
                ah[hsel * 2 + 1] = hi1;
                al[hsel * 2]     = packh2(s0[0] - fa.x, s0[1] - fa.y);
                al[hsel * 2 + 1] = packh2(s0[2] - fb.x, s0[3] - fb.y);
            }
            // NB: A-frag order is a0:(m,k0-7 pair), a1:(m+8,k0-7), a2:(m,k8-15), a3:(m+8,k8-15)
            // sacc[2kc] covers k = 16kc+2lq (first k8), sacc[2kc+1] = +8 → order matches:
            // ah[0]=P(m,klo), ah[1]=P(m+8,klo), ah[2]=P(m,khi), ah[3]=P(m+8,khi)
            #pragma unroll
            for (int nb = 0; nb < 4; nb++) {
                uint32_t va = boff + (uint32_t)(nb * 16 * FST * 4) + kc * 32;
                unsigned h0, h1, h2, h3, g0, g1, g2, g3;
                LDSM4(h0, h1, h2, h3, sVhb + va);
                LDSM4(g0, g1, g2, g3, sVlb + va);
                unsigned bh0[2] = {h0, h1}, bh1[2] = {h2, h3};
                unsigned bl0[2] = {g0, g1}, bl1[2] = {g2, g3};
                mma16(oacc[nb * 2],     ah, bh0);
                mma16(oacc[nb * 2],     al, bh0);
                mma16(oacc[nb * 2],     ah, bl0);
                mma16(oacc[nb * 2 + 1], ah, bh1);
                mma16(oacc[nb * 2 + 1], al, bh1);
                mma16(oacc[nb * 2 + 1], ah, bl1);
            }
        }
    }

    // ---- epilogue: packed fp16 output ----
    float inv0 = 1.0f / l0, inv1 = 1.0f / l1;
    int row0 = b * SS + i0 + w * 16 + lr;
    unsigned* Ob = O16 + (size_t)row0 * KPD + h * 32;
    #pragma unroll
    for (int nt = 0; nt < 8; nt++) {
        Ob[nt * 4 + lq] = packh2(oacc[nt][0] * inv0, oacc[nt][1] * inv0);
        Ob[(size_t)8 * KPD + nt * 4 + lq] = packh2(oacc[nt][2] * inv1, oacc[nt][3] * inv1);
    }
}

// ---------------- host launcher ----------------
extern "C" void kernel_launch(void* const* d_in, const int* in_sizes, int n_in,
                              void* d_out, int out_size)
{
    const int*   idx   = (const int*)  d_in[0];
    const float* wte   = (const float*)d_in[1];
    const float* wpe   = (const float*)d_in[2];
    const float* ln1_w = (const float*)d_in[3];
    const float* ln1_b = (const float*)d_in[4];
    const float* wq    = (const float*)d_in[5];
    const float* wk    = (const float*)d_in[6];
    const float* wv    = (const float*)d_in[7];
    const float* wo    = (const float*)d_in[8];
    const float* ln2_w = (const float*)d_in[9];
    const float* ln2_b = (const float*)d_in[10];
    const float* fc1   = (const float*)d_in[11];
    const float* fc2   = (const float*)d_in[12];
    const float* lnf_w = (const float*)d_in[13];
    const float* lnf_b = (const float*)d_in[14];
    float* out = (float*)d_out;

    float *x, *v;
    unsigned *q16, *k16, *h16, *tmp16, *ff16, *vph, *vpl;
    unsigned *wq16, *wk16, *wv16, *wo16, *fc116, *fc216, *wte16;
    cudaGetSymbolAddress((void**)&x,     g_x);
    cudaGetSymbolAddress((void**)&v,     g_v);
    cudaGetSymbolAddress((void**)&q16,   g_q16);
    cudaGetSymbolAddress((void**)&k16,   g_k16);
    cudaGetSymbolAddress((void**)&h16,   g_h16);
    cudaGetSymbolAddress((void**)&tmp16, g_tmp16);
    cudaGetSymbolAddress((void**)&ff16,  g_ff16);
    cudaGetSymbolAddress((void**)&vph,   g_vph);
    cudaGetSymbolAddress((void**)&vpl,   g_vpl);
    cudaGetSymbolAddress((void**)&wq16,  g_wq16);
    cudaGetSymbolAddress((void**)&wk16,  g_wk16);
    cudaGetSymbolAddress((void**)&wv16,  g_wv16);
    cudaGetSymbolAddress((void**)&wo16,  g_wo16);
    cudaGetSymbolAddress((void**)&fc116, g_fc116);
    cudaGetSymbolAddress((void**)&fc216, g_fc216);
    cudaGetSymbolAddress((void**)&wte16, g_wte16);

    const int gs = 3 * STG * 4;      // 61440
    cudaFuncSetAttribute(mma_gemm<0,false>, cudaFuncAttributeMaxDynamicSharedMemorySize, gs);
    cudaFuncSetAttribute(mma_gemm<1,false>, cudaFuncAttributeMaxDynamicSharedMemorySize, gs);
    cudaFuncSetAttribute(mma_gemm<2,false>, cudaFuncAttributeMaxDynamicSharedMemorySize, gs);
    cudaFuncSetAttribute(mma_gemm<3,false>, cudaFuncAttributeMaxDynamicSharedMemorySize, gs);
    cudaFuncSetAttribute(mma_gemm<0,true>,  cudaFuncAttributeMaxDynamicSharedMemorySize, gs);

    // ---- pack weights to fp16 K-major [L][N][K/2] ----
    pack_t<<<dim3(DD / 64, DD / 64, LL), 256>>>(wq, wq16, DD, DD);
    pack_t<<<dim3(DD / 64, DD / 64, LL), 256>>>(wk, wk16, DD, DD);
    pack_t<<<dim3(DD / 64, DD / 64, LL), 256>>>(wv, wv16, DD, DD);
    pack_t<<<dim3(DD / 64, DD / 64, LL), 256>>>(wo, wo16, DD, DD);
    pack_t<<<dim3(DFF / 64, DD / 64, LL), 256>>>(fc1, fc116, DD, DFF);
    pack_t<<<dim3(DD / 64, DFF / 64, LL), 256>>>(fc2, fc216, DFF, DD);
    {
        int tE = VV * KPD;
        pack_nk<<<(tE + 255) / 256, 256>>>(wte, wte16, tE);
    }

    embed_kernel<<<NTOK, 256>>>(idx, wte, wpe, x);

    dim3 gQKV(DD / 128, NTOK / 128, 3);
    dim3 gD  (DD / 128, NTOK / 128, 1);
    dim3 gF  (DFF / 128, NTOK / 128, 1);

    for (int l = 0; l < LL; l++) {
        unsigned* Wq = wq16 + (size_t)l * DD * KPD;
        unsigned* Wk = wk16 + (size_t)l * DD * KPD;
        unsigned* Wv = wv16 + (size_t)l * DD * KPD;
        unsigned* Wo = wo16 + (size_t)l * DD * KPD;
        unsigned* W1 = fc116 + (size_t)l * DFF * KPD;
        unsigned* W2 = fc216 + (size_t)l * DD * KPF;

        layernorm_kernel<<<NTOK, 256>>>(x, ln1_w + l * DD, ln1_b + l * DD, h16);

        // q,k -> packed fp16; v -> f32
        mma_gemm<3,false><<<gQKV, 256, gs>>>(h16, Wq, Wk, Wv, nullptr,
                                             q16, (float*)k16, v, DD, DD);

        vtrans_kernel<<<dim3(SS / 64, BB * HH), 256>>>(v, vph, vpl);

        flash_attn_kernel<<<dim3(SS / 64, BB * HH), 128>>>(q16, k16, vph, vpl, tmp16);

        mma_gemm<1,false><<<gD, 256, gs>>>(tmp16, Wo, Wo, Wo, x, x,
                                           nullptr, nullptr, DD, DD);

        layernorm_kernel<<<NTOK, 256>>>(x, ln2_w + l * DD, ln2_b + l * DD, h16);
        mma_gemm<2,false><<<gF, 256, gs>>>(h16, W1, W1, W1, nullptr, ff16,
                                           nullptr, nullptr, DFF, DD);
        mma_gemm<1,false><<<gD, 256, gs>>>(ff16, W2, W2, W2, x, x,
                                           nullptr, nullptr, DD, DFF);
    }

    layernorm_kernel<<<NTOK, 256>>>(x, lnf_w, lnf_b, h16);
    mma_gemm<0,true><<<dim3((VV + 127) / 128, NTOK / 128, 1), 256, gs>>>(
        h16, wte16, wte16, wte16, nullptr, out, nullptr, nullptr, VV, DD);
}

// round 10
// speedup vs baseline: 2.3575x; 1.2525x over previous
#include <cuda_runtime.h>
#include <cuda_bf16.h>
#include <cuda_fp16.h>
#include <math.h>
#include <stdint.h>

// ---------------- problem constants ----------------
#define BB 4
#define SS 1024
#define LL 12
#define DD 768
#define HH 12
#define DKK 64
#define DFF 3072
#define VV 50257
#define NTOK (BB*SS)          // 4096
#define KPD (DD/2)            // 384
#define KPF (DFF/2)           // 1536

// ---------------- scratch (device globals; no allocs allowed) --------------
__device__ float g_x [(size_t)NTOK * DD];
__device__ float g_v [(size_t)NTOK * DD];
__device__ unsigned g_q16 [(size_t)NTOK * KPD];
__device__ unsigned g_k16 [(size_t)NTOK * KPD];
__device__ unsigned g_h16 [(size_t)NTOK * KPD];
__device__ unsigned g_tmp16[(size_t)NTOK * KPD];
__device__ unsigned g_ff16 [(size_t)NTOK * KPF];
__device__ unsigned g_vph [(size_t)BB * HH * DKK * (SS/2)];
__device__ unsigned g_vpl [(size_t)BB * HH * DKK * (SS/2)];
// packed fp16 weights, K-major: [L][N][K/2] half2 words
__device__ unsigned g_wq16 [(size_t)LL * DD * KPD];
__device__ unsigned g_wk16 [(size_t)LL * DD * KPD];
__device__ unsigned g_wv16 [(size_t)LL * DD * KPD];
__device__ unsigned g_wo16 [(size_t)LL * DD * KPD];
__device__ unsigned g_fc116[(size_t)LL * DFF * KPD];
__device__ unsigned g_fc216[(size_t)LL * DD * KPF];
__device__ unsigned g_wte16[(size_t)VV * KPD];

// ---------------- helpers ----------------
__device__ __forceinline__ uint32_t smem_u32(const void* p) {
    uint32_t a;
    asm("{ .reg .u64 t; cvta.to.shared.u64 t, %1; cvt.u32.u64 %0, t; }"
        : "=r"(a) : "l"(p));
    return a;
}
__device__ __forceinline__ void mma16(float* d, const unsigned* a, const unsigned* b) {
    asm volatile(
        "mma.sync.aligned.m16n8k16.row.col.f32.f16.f16.f32 "
        "{%0,%1,%2,%3},{%4,%5,%6,%7},{%8,%9},{%0,%1,%2,%3};"
        : "+f"(d[0]), "+f"(d[1]), "+f"(d[2]), "+f"(d[3])
        : "r"(a[0]), "r"(a[1]), "r"(a[2]), "r"(a[3]), "r"(b[0]), "r"(b[1]));
}
#define LDSM4(r0, r1, r2, r3, addr) \
    asm volatile("ldmatrix.sync.aligned.m8n8.x4.shared.b16 {%0,%1,%2,%3}, [%4];" \
                 : "=r"(r0), "=r"(r1), "=r"(r2), "=r"(r3) : "r"(addr))
__device__ __forceinline__ unsigned packh2(float lo, float hi) {
    __half2 h = __floats2half2_rn(lo, hi);
    return *reinterpret_cast<unsigned*>(&h);
}
__device__ __forceinline__ void cp16(uint32_t d, const void* g) {
    asm volatile("cp.async.cg.shared.global [%0], [%1], 16;" :: "r"(d), "l"(g));
}
__device__ __forceinline__ void cp16g(uint32_t d, const void* g, int sz) {
    asm volatile("cp.async.cg.shared.global [%0], [%1], 16, %2;"
                 :: "r"(d), "l"(g), "r"(sz));
}

// ---------------- weight packing (once per replay) ----------------
__global__ void pack_t(const float* __restrict__ W, unsigned* __restrict__ out,
                       int K, int N)
{
    __shared__ float t[64][65];
    const int n0 = blockIdx.x * 64, k0 = blockIdx.y * 64, l = blockIdx.z;
    const float* Wl = W + (size_t)l * K * N;
    unsigned* ol = out + (size_t)l * N * (K >> 1);
    const int tid = threadIdx.x;
    #pragma unroll
    for (int p = 0; p < 16; p++) {
        int idx = tid + p * 256;
        int kk = idx >> 6, nn = idx & 63;
        t[kk][nn] = Wl[(size_t)(k0 + kk) * N + n0 + nn];
    }
    __syncthreads();
    #pragma unroll
    for (int p = 0; p < 8; p++) {
        int idx = tid + p * 256;
        int nn = idx >> 5, kp = idx & 31;
        ol[(size_t)(n0 + nn) * (K >> 1) + (k0 >> 1) + kp] =
            packh2(t[2 * kp][nn], t[2 * kp + 1][nn]);
    }
}
__global__ void pack_nk(const float* __restrict__ W, unsigned* __restrict__ out,
                        int total)
{
    int i = blockIdx.x * 256 + threadIdx.x;
    if (i >= total) return;
    int v = i / KPD, kp = i - v * KPD;
    float2 f = *(const float2*)(W + (size_t)v * DD + 2 * kp);
    out[i] = packh2(f.x, f.y);
}

// ---------------- V transpose: f32 [row][D] -> fp16 hi/lo [bh*64+dk][jpair] --
__global__ void vtrans_kernel(const float* __restrict__ v,
                              unsigned* __restrict__ vph,
                              unsigned* __restrict__ vpl)
{
    __shared__ float t[64][65];
    const int j0 = blockIdx.x * 64;
    const int bh = blockIdx.y;
    const int b = bh / HH, h = bh % HH;
    const int tid = threadIdx.x;
    #pragma unroll
    for (int p = 0; p < 16; p++) {
        int idx = tid + p * 256;
        int j = idx >> 6, dk = idx & 63;
        t[j][dk] = v[(size_t)(b * SS + j0 + j) * DD + h * DKK + dk];
    }
    __syncthreads();
    #pragma unroll
    for (int p = 0; p < 8; p++) {
        int idx = tid + p * 256;
        int dk = idx >> 5, jp = idx & 31;
        float v0 = t[2 * jp][dk], v1 = t[2 * jp + 1][dk];
        __half h0 = __float2half_rn(v0), h1 = __float2half_rn(v1);
        float l0 = v0 - __half2float(h0), l1 = v1 - __half2float(h1);
        __half2 hh = __halves2half2(h0, h1);
        size_t o = ((size_t)bh * DKK + dk) * (SS / 2) + (j0 >> 1) + jp;
        vph[o] = *reinterpret_cast<unsigned*>(&hh);
        vpl[o] = packh2(l0, l1);
    }
}

// ---------------- fp16 NT GEMM: ldmatrix + cp.async, BK=64, 3-stage --------
// EPI: 0 none->f32, 1 +Cin->f32, 2 GELU->packed fp16, 3 QKV (z<2 fp16, z=2 f32)
// NG: guard N (head gemm)
#define APAD 36                      // words per tile row (32 used + 4 pad)
#define AW (128 * APAD)              // 4608 words per operand tile
#define STG (2 * AW)                 // 9216 words per stage

template<int EPI, bool NG>
__global__ __launch_bounds__(256, 2)
void mma_gemm(const unsigned* __restrict__ A,
              const unsigned* __restrict__ B0, const unsigned* __restrict__ B1,
              const unsigned* __restrict__ B2,
              const float* __restrict__ Cin, void* __restrict__ Cv,
              float* __restrict__ C1f, float* __restrict__ C2f,
              int N, int K)
{
    extern __shared__ unsigned gsm[];

    const unsigned* B = (blockIdx.z == 0) ? B0 : ((blockIdx.z == 1) ? B1 : B2);
    float* Cf = (blockIdx.z == 0) ? (float*)Cv : ((blockIdx.z == 1) ? C1f : C2f);
    unsigned* C16 = (unsigned*)Cv;

    const int tid  = threadIdx.x;
    const int lane = tid & 31;
    const int warp = tid >> 5;
    const int wm = warp >> 2, wn = warp & 3;
    const int lr = lane >> 2, lq = lane & 3;
    const int m0 = blockIdx.y * 128;
    const int n0 = blockIdx.x * 128;
    const int KA = K >> 1;

    const uint32_t sbase = smem_u32(gsm);
    const int lrow = lane & 7, lg = lane >> 3;
    const uint32_t aoff = (uint32_t)(((wm * 64 + (lg & 1) * 8 + lrow) * APAD
                                      + (lg >> 1) * 4) * 4);
    const uint32_t boff = (uint32_t)(((wn * 32 + (lg >> 1) * 8 + lrow) * APAD
                                      + (lg & 1) * 4) * 4);

    float acc[4][4][4];
    #pragma unroll
    for (int i = 0; i < 4; i++)
        #pragma unroll
        for (int j = 0; j < 4; j++)
            #pragma unroll
            for (int t = 0; t < 4; t++) acc[i][j][t] = 0.0f;

    // per stage: 128 rows x 32 words per operand; 4 cp16/thread/operand
    auto load_stage = [&](int stg) {
        const int slot = stg % 3;
        const uint32_t sa = sbase + (uint32_t)(slot * STG) * 4u;
        const uint32_t sb = sa + (uint32_t)AW * 4u;
        const int kp0 = stg * 32;
        #pragma unroll
        for (int p = 0; p < 4; p++) {
            int s = tid + p * 256;                 // 0..1023
            int r = s >> 3, c4 = (s & 7) * 4;
            cp16(sa + (uint32_t)(r * APAD + c4) * 4u,
                 A + (size_t)(m0 + r) * KA + kp0 + c4);
        }
        #pragma unroll
        for (int p = 0; p < 4; p++) {
            int s = tid + p * 256;
            int r = s >> 3, c4 = (s & 7) * 4;
            if (NG) {
                int n = n0 + r;
                int ok = (n < N);
                cp16g(sb + (uint32_t)(r * APAD + c4) * 4u,
                      B + (size_t)(ok ? n : 0) * KA + kp0 + c4, ok ? 16 : 0);
            } else {
                cp16(sb + (uint32_t)(r * APAD + c4) * 4u,
                     B + (size_t)(n0 + r) * KA + kp0 + c4);
            }
        }
        asm volatile("cp.async.commit_group;" ::: "memory");
    };

    auto compute = [&](int slot) {
        const uint32_t sa = sbase + (uint32_t)(slot * STG) * 4u;
        const uint32_t sb = sa + (uint32_t)AW * 4u;
        #pragma unroll
        for (int kc = 0; kc < 4; kc++) {
            const uint32_t kbb = (uint32_t)(kc * 32);      // 8 words per chunk
            unsigned af[4][4];
            #pragma unroll
            for (int mt = 0; mt < 4; mt++) {
                uint32_t addr = sa + aoff + kbb + (uint32_t)(mt * 16 * APAD * 4);
                LDSM4(af[mt][0], af[mt][1], af[mt][2], af[mt][3], addr);
            }
            unsigned bf[4][2];
            #pragma unroll
            for (int np = 0; np < 2; np++) {
                uint32_t addr = sb + boff + kbb + (uint32_t)(np * 16 * APAD * 4);
                unsigned r0, r1, r2, r3;
                LDSM4(r0, r1, r2, r3, addr);
                bf[np * 2][0] = r0;     bf[np * 2][1] = r1;
                bf[np * 2 + 1][0] = r2; bf[np * 2 + 1][1] = r3;
            }
            #pragma unroll
            for (int mt = 0; mt < 4; mt++)
                #pragma unroll
                for (int nt = 0; nt < 4; nt++)
                    mma16(acc[mt][nt], af[mt], bf[nt]);
        }
    };

    const int nIter = K >> 6;                      // BK = 64
    load_stage(0);
    load_stage(1);
    for (int it = 0; it < nIter; it++) {
        if (it + 1 < nIter) asm volatile("cp.async.wait_group 1;" ::: "memory");
        else                asm volatile("cp.async.wait_group 0;" ::: "memory");
        __syncthreads();
        if (it + 2 < nIter) load_stage(it + 2);
        compute(it % 3);
    }

    // ---- epilogue ----
    #pragma unroll
    for (int mt = 0; mt < 4; mt++) {
        int r0 = m0 + wm * 64 + mt * 16 + lr;
        #pragma unroll
        for (int nt = 0; nt < 4; nt++) {
            int col = n0 + wn * 32 + nt * 8 + lq * 2;
            float* a4 = acc[mt][nt];
            float v00 = a4[0], v01 = a4[1], v10 = a4[2], v11 = a4[3];
            if (EPI == 2) {
                v00 = 0.5f * v00 * (1.0f + erff(v00 * 0.70710678118654752f));
                v01 = 0.5f * v01 * (1.0f + erff(v01 * 0.70710678118654752f));
                v10 = 0.5f * v10 * (1.0f + erff(v10 * 0.70710678118654752f));
                v11 = 0.5f * v11 * (1.0f + erff(v11 * 0.70710678118654752f));
                int nw = N >> 1;
                C16[(size_t)r0 * nw + (col >> 1)]       = packh2(v00, v01);
                C16[(size_t)(r0 + 8) * nw + (col >> 1)] = packh2(v10, v11);
            } else if (EPI == 3) {
                if (blockIdx.z == 2) {
                    size_t o0 = (size_t)r0 * N + col;
                    size_t o1 = (size_t)(r0 + 8) * N + col;
                    *(float2*)(C2f + o0) = make_float2(v00, v01);
                    *(float2*)(C2f + o1) = make_float2(v10, v11);
                } else {
                    unsigned* o = (blockIdx.z == 0) ? (unsigned*)Cv : (unsigned*)C1f;
                    int nw = N >> 1;
                    o[(size_t)r0 * nw + (col >> 1)]       = packh2(v00, v01);
                    o[(size_t)(r0 + 8) * nw + (col >> 1)] = packh2(v10, v11);
                }
            } else {
                size_t o0 = (size_t)r0 * N + col;
                size_t o1 = (size_t)(r0 + 8) * N + col;
                if (EPI == 1) {
                    float2 c0 = *(const float2*)(Cin + o0);
                    float2 c1 = *(const float2*)(Cin + o1);
                    v00 += c0.x; v01 += c0.y; v10 += c1.x; v11 += c1.y;
                }
                if (!NG) {
                    *(float2*)(Cf + o0) = make_float2(v00, v01);
                    *(float2*)(Cf + o1) = make_float2(v10, v11);
                } else {
                    if (col < N)     { Cf[o0] = v00;     Cf[o1] = v10; }
                    if (col + 1 < N) { Cf[o0 + 1] = v01; Cf[o1 + 1] = v11; }
                }
            }
        }
    }
}

// ---------------- embedding ----------------
__global__ void embed_kernel(const int* __restrict__ idx,
                             const float* __restrict__ wte,
                             const float* __restrict__ wpe,
                             float* __restrict__ x)
{
    int row = blockIdx.x;
    int s   = row & (SS - 1);
    int tok = idx[row];
    int tid = threadIdx.x;
    #pragma unroll
    for (int l = 0; l < 3; l++) {
        int d = tid + l * 256;
        x[(size_t)row * DD + d] = wte[(size_t)tok * DD + d] + wpe[(size_t)s * DD + d];
    }
}

// ---------------- layernorm -> packed fp16 ----------------
__global__ void layernorm_kernel(const float* __restrict__ x,
                                 const float* __restrict__ w,
                                 const float* __restrict__ b,
                                 unsigned* __restrict__ y16)
{
    int row = blockIdx.x;
    const float2* p2 = (const float2*)(x + (size_t)row * DD);
    int tid = threadIdx.x;
    float2 f1 = p2[tid];
    float2 f2 = (tid < 128) ? p2[tid + 256] : make_float2(0.f, 0.f);
    __shared__ float red[256];
    red[tid] = f1.x + f1.y + f2.x + f2.y;
    __syncthreads();
    for (int st = 128; st > 0; st >>= 1) {
        if (tid < st) red[tid] += red[tid + st];
        __syncthreads();
    }
    float mean = red[0] * (1.0f / DD);
    __syncthreads();
    float a0 = f1.x - mean, a1 = f1.y - mean;
    float a2 = f2.x - mean, a3 = f2.y - mean;
    red[tid] = a0 * a0 + a1 * a1 + ((tid < 128) ? (a2 * a2 + a3 * a3) : 0.f);
    __syncthreads();
    for (int st = 128; st > 0; st >>= 1) {
        if (tid < st) red[tid] += red[tid + st];
        __syncthreads();
    }
    float rstd = rsqrtf(red[0] * (1.0f / DD) + 1e-5f);
    const float2* w2 = (const float2*)w;
    const float2* b2 = (const float2*)b;
    unsigned* yr = y16 + (size_t)row * KPD;
    {
        float2 ww = w2[tid], bb = b2[tid];
        yr[tid] = packh2(a0 * rstd * ww.x + bb.x, a1 * rstd * ww.y + bb.y);
    }
    if (tid < 128) {
        float2 ww = w2[tid + 256], bb = b2[tid + 256];
        yr[tid + 256] = packh2(a2 * rstd * ww.x + bb.x, a3 * rstd * ww.y + bb.y);
    }
}

// ---------------- fused flash attention (fp16 tensor cores) ----------------
#define FST 36   // smem row stride (32 words + 4 pad)

__global__ __launch_bounds__(128, 3)
void flash_attn_kernel(const unsigned* __restrict__ q16,
                       const unsigned* __restrict__ k16,
                       const unsigned* __restrict__ vph,
                       const unsigned* __restrict__ vpl,
                       unsigned* __restrict__ O16)
{
    __shared__ unsigned sQ[64 * FST], sK[64 * FST], sVh[64 * FST], sVl[64 * FST];

    const int tid  = threadIdx.x;
    const int lane = tid & 31;
    const int w    = tid >> 5;
    const int lr   = lane >> 2;
    const int lq   = lane & 3;
    const int it   = (SS / 64 - 1) - blockIdx.x;
    const int bh   = blockIdx.y;
    const int b    = bh / HH, h = bh % HH;
    const int i0   = it * 64;
    const int lrow = lane & 7, lg = lane >> 3;

    const uint32_t sQb = smem_u32(sQ), sKb = smem_u32(sK);
    const uint32_t sVhb = smem_u32(sVh), sVlb = smem_u32(sVl);
    const uint32_t aoff = (uint32_t)(((w * 16 + (lg & 1) * 8 + lrow) * FST
                                      + (lg >> 1) * 4) * 4);
    const uint32_t boff = (uint32_t)((((lg >> 1) * 8 + lrow) * FST
                                      + (lg & 1) * 4) * 4);

    #pragma unroll
    for (int p = 0; p < 4; p++) {
        int s = tid + p * 128;
        int r = s >> 3, c4 = (s & 7) * 4;
        cp16(sQb + (uint32_t)(r * FST + c4) * 4u,
             q16 + (size_t)(b * SS + i0 + r) * KPD + h * 32 + c4);
    }
    asm volatile("cp.async.commit_group;" ::: "memory");
    asm volatile("cp.async.wait_group 0;" ::: "memory");
    __syncthreads();

    unsigned qf[4][4];
    #pragma unroll
    for (int kc = 0; kc < 4; kc++)
        LDSM4(qf[kc][0], qf[kc][1], qf[kc][2], qf[kc][3], sQb + aoff + kc * 32);

    float oacc[8][4];
    #pragma unroll
    for (int nt = 0; nt < 8; nt++)
        #pragma unroll
        for (int e = 0; e < 4; e++) oacc[nt][e] = 0.0f;
    float m0 = -1e30f, m1 = -1e30f, l0 = 0.0f, l1 = 0.0f;

    for (int j0 = 0; j0 <= i0; j0 += 64) {
        __syncthreads();
        #pragma unroll
        for (int p = 0; p < 4; p++) {
            int s = tid + p * 128;
            int r = s >> 3, c4 = (s & 7) * 4;
            cp16(sKb + (uint32_t)(r * FST + c4) * 4u,
                 k16 + (size_t)(b * SS + j0 + r) * KPD + h * 32 + c4);
            size_t vo = ((size_t)bh * DKK + r) * (SS / 2) + (j0 >> 1) + c4;
            cp16(sVhb + (uint32_t)(r * FST + c4) * 4u, vph + vo);
            cp16(sVlb + (uint32_t)(r * FST + c4) * 4u, vpl + vo);
        }
        asm volatile("cp.async.commit_group;" ::: "memory");
        asm volatile("cp.async.wait_group 0;" ::: "memory");
        __syncthreads();

        float sacc[8][4];
        #pragma unroll
        for (int nt = 0; nt < 8; nt++)
            #pragma unroll
            for (int e = 0; e < 4; e++) sacc[nt][e] = 0.0f;
        #pragma unroll
        for (int kc = 0; kc < 4; kc++) {
            #pragma unroll
            for (int nb = 0; nb < 4; nb++) {
                unsigned r0, r1, r2, r3;
                LDSM4(r0, r1, r2, r3,
                      sKb + boff + (uint32_t)(nb * 16 * FST * 4) + kc * 32);
                unsigned b0[2] = {r0, r1}, b1[2] = {r2, r3};
                mma16(sacc[nb * 2],     qf[kc], b0);
                mma16(sacc[nb * 2 + 1], qf[kc], b1);
            }
        }

        #pragma unroll
        for (int nt = 0; nt < 8; nt++)
            #pragma unroll
            for (int e = 0; e < 4; e++) sacc[nt][e] *= 0.125f;
        if (j0 == i0) {
            int ii0 = w * 16 + lr, ii1 = ii0 + 8;
            #pragma unroll
            for (int nt = 0; nt < 8; nt++) {
                int jj = nt * 8 + 2 * lq;
                if (jj     > ii0) sacc[nt][0] = -1e30f;
                if (jj + 1 > ii0) sacc[nt][1] = -1e30f;
                if (jj     > ii1) sacc[nt][2] = -1e30f;
                if (jj + 1 > ii1) sacc[nt][3] = -1e30f;
            }
        }

        float rm0 = -1e30f, rm1 = -1e30f;
        #pragma unroll
        for (int nt = 0; nt < 8; nt++) {
            rm0 = fmaxf(rm0, fmaxf(sacc[nt][0], sacc[nt][1]));
            rm1 = fmaxf(rm1, fmaxf(sacc[nt][2], sacc[nt][3]));
        }
        rm0 = fmaxf(rm0, __shfl_xor_sync(0xffffffffu, rm0, 1));
        rm0 = fmaxf(rm0, __shfl_xor_sync(0xffffffffu, rm0, 2));
        rm1 = fmaxf(rm1, __shfl_xor_sync(0xffffffffu, rm1, 1));
        rm1 = fmaxf(rm1, __shfl_xor_sync(0xffffffffu, rm1, 2));
        float mn0 = fmaxf(m0, rm0), mn1 = fmaxf(m1, rm1);
        float f0 = __expf(m0 - mn0), f1 = __expf(m1 - mn1);
        float ps0 = 0.0f, ps1 = 0.0f;
        #pragma unroll
        for (int nt = 0; nt < 8; nt++) {
            float p0 = __expf(sacc[nt][0] - mn0); sacc[nt][0] = p0; ps0 += p0;
            float p1 = __expf(sacc[nt][1] - mn0); sacc[nt][1] = p1; ps0 += p1;
            float p2 = __expf(sacc[nt][2] - mn1); sacc[nt][2] = p2; ps1 += p2;
            float p3 = __expf(sacc[nt][3] - mn1); sacc[nt][3] = p3; ps1 += p3;
        }
        ps0 += __shfl_xor_sync(0xffffffffu, ps0, 1);
        ps0 += __shfl_xor_sync(0xffffffffu, ps0, 2);
        ps1 += __shfl_xor_sync(0xffffffffu, ps1, 1);
        ps1 += __shfl_xor_sync(0xffffffffu, ps1, 2);
        l0 = l0 * f0 + ps0;
        l1 = l1 * f1 + ps1;
        m0 = mn0; m1 = mn1;
        #pragma unroll
        for (int nt = 0; nt < 8; nt++) {
            oacc[nt][0] *= f0; oacc[nt][1] *= f0;
            oacc[nt][2] *= f1; oacc[nt][3] *= f1;
        }

        #pragma unroll
        for (int kc = 0; kc < 4; kc++) {
            unsigned ah[4], al[4];
            #pragma unroll
            for (int hsel = 0; hsel < 2; hsel++) {
                const float* s0 = sacc[2 * kc + hsel];
                unsigned hi0 = packh2(s0[0], s0[1]);
                unsigned hi1 = packh2(s0[2], s0[3]);
                __half2 h2a = *reinterpret_cast<__half2*>(&hi0);
                __half2 h2b = *reinterpret_cast<__half2*>(&hi1);
                float2 fa = __half22float2(h2a);
                float2 fb = __half22float2(h2b);
                ah[hsel * 2]     = hi0;
                ah[hsel * 2 + 1] = hi1;
                al[hsel * 2]     = packh2(s0[0] - fa.x, s0[1] - fa.y);
                al[hsel * 2 + 1] = packh2(s0[2] - fb.x, s0[3] - fb.y);
            }
            #pragma unroll
            for (int nb = 0; nb < 4; nb++) {
                uint32_t va = boff + (uint32_t)(nb * 16 * FST * 4) + kc * 32;
                unsigned h0, h1, h2, h3, g0, g1, g2, g3;
                LDSM4(h0, h1, h2, h3, sVhb + va);
                LDSM4(g0, g1, g2, g3, sVlb + va);
                unsigned bh0[2] = {h0, h1}, bh1[2] = {h2, h3};
                unsigned bl0[2] = {g0, g1}, bl1[2] = {g2, g3};
                mma16(oacc[nb * 2],     ah, bh0);
                mma16(oacc[nb * 2],     al, bh0);
                mma16(oacc[nb * 2],     ah, bl0);
                mma16(oacc[nb * 2 + 1], ah, bh1);
                mma16(oacc[nb * 2 + 1], al, bh1);
                mma16(oacc[nb * 2 + 1], ah, bl1);
            }
        }
    }

    float inv0 = 1.0f / l0, inv1 = 1.0f / l1;
    int row0 = b * SS + i0 + w * 16 + lr;
    unsigned* Ob = O16 + (size_t)row0 * KPD + h * 32;
    #pragma unroll
    for (int nt = 0; nt < 8; nt++) {
        Ob[nt * 4 + lq] = packh2(oacc[nt][0] * inv0, oacc[nt][1] * inv0);
        Ob[(size_t)8 * KPD + nt * 4 + lq] = packh2(oacc[nt][2] * inv1, oacc[nt][3] * inv1);
    }
}

// ---------------- host launcher ----------------
extern "C" void kernel_launch(void* const* d_in, const int* in_sizes, int n_in,
                              void* d_out, int out_size)
{
    const int*   idx   = (const int*)  d_in[0];
    const float* wte   = (const float*)d_in[1];
    const float* wpe   = (const float*)d_in[2];
    const float* ln1_w = (const float*)d_in[3];
    const float* ln1_b = (const float*)d_in[4];
    const float* wq    = (const float*)d_in[5];
    const float* wk    = (const float*)d_in[6];
    const float* wv    = (const float*)d_in[7];
    const float* wo    = (const float*)d_in[8];
    const float* ln2_w = (const float*)d_in[9];
    const float* ln2_b = (const float*)d_in[10];
    const float* fc1   = (const float*)d_in[11];
    const float* fc2   = (const float*)d_in[12];
    const float* lnf_w = (const float*)d_in[13];
    const float* lnf_b = (const float*)d_in[14];
    float* out = (float*)d_out;

    float *x, *v;
    unsigned *q16, *k16, *h16, *tmp16, *ff16, *vph, *vpl;
    unsigned *wq16, *wk16, *wv16, *wo16, *fc116, *fc216, *wte16;
    cudaGetSymbolAddress((void**)&x,     g_x);
    cudaGetSymbolAddress((void**)&v,     g_v);
    cudaGetSymbolAddress((void**)&q16,   g_q16);
    cudaGetSymbolAddress((void**)&k16,   g_k16);
    cudaGetSymbolAddress((void**)&h16,   g_h16);
    cudaGetSymbolAddress((void**)&tmp16, g_tmp16);
    cudaGetSymbolAddress((void**)&ff16,  g_ff16);
    cudaGetSymbolAddress((void**)&vph,   g_vph);
    cudaGetSymbolAddress((void**)&vpl,   g_vpl);
    cudaGetSymbolAddress((void**)&wq16,  g_wq16);
    cudaGetSymbolAddress((void**)&wk16,  g_wk16);
    cudaGetSymbolAddress((void**)&wv16,  g_wv16);
    cudaGetSymbolAddress((void**)&wo16,  g_wo16);
    cudaGetSymbolAddress((void**)&fc116, g_fc116);
    cudaGetSymbolAddress((void**)&fc216, g_fc216);
    cudaGetSymbolAddress((void**)&wte16, g_wte16);

    const int gs = 3 * STG * 4;      // 110592 bytes
    cudaFuncSetAttribute(mma_gemm<0,false>, cudaFuncAttributeMaxDynamicSharedMemorySize, gs);
    cudaFuncSetAttribute(mma_gemm<1,false>, cudaFuncAttributeMaxDynamicSharedMemorySize, gs);
    cudaFuncSetAttribute(mma_gemm<2,false>, cudaFuncAttributeMaxDynamicSharedMemorySize, gs);
    cudaFuncSetAttribute(mma_gemm<3,false>, cudaFuncAttributeMaxDynamicSharedMemorySize, gs);
    cudaFuncSetAttribute(mma_gemm<0,true>,  cudaFuncAttributeMaxDynamicSharedMemorySize, gs);

    pack_t<<<dim3(DD / 64, DD / 64, LL), 256>>>(wq, wq16, DD, DD);
    pack_t<<<dim3(DD / 64, DD / 64, LL), 256>>>(wk, wk16, DD, DD);
    pack_t<<<dim3(DD / 64, DD / 64, LL), 256>>>(wv, wv16, DD, DD);
    pack_t<<<dim3(DD / 64, DD / 64, LL), 256>>>(wo, wo16, DD, DD);
    pack_t<<<dim3(DFF / 64, DD / 64, LL), 256>>>(fc1, fc116, DD, DFF);
    pack_t<<<dim3(DD / 64, DFF / 64, LL), 256>>>(fc2, fc216, DFF, DD);
    {
        int tE = VV * KPD;
        pack_nk<<<(tE + 255) / 256, 256>>>(wte, wte16, tE);
    }

    embed_kernel<<<NTOK, 256>>>(idx, wte, wpe, x);

    dim3 gQKV(DD / 128, NTOK / 128, 3);
    dim3 gD  (DD / 128, NTOK / 128, 1);
    dim3 gF  (DFF / 128, NTOK / 128, 1);

    for (int l = 0; l < LL; l++) {
        unsigned* Wq = wq16 + (size_t)l * DD * KPD;
        unsigned* Wk = wk16 + (size_t)l * DD * KPD;
        unsigned* Wv = wv16 + (size_t)l * DD * KPD;
        unsigned* Wo = wo16 + (size_t)l * DD * KPD;
        unsigned* W1 = fc116 + (size_t)l * DFF * KPD;
        unsigned* W2 = fc216 + (size_t)l * DD * KPF;

        layernorm_kernel<<<NTOK, 256>>>(x, ln1_w + l * DD, ln1_b + l * DD, h16);

        mma_gemm<3,false><<<gQKV, 256, gs>>>(h16, Wq, Wk, Wv, nullptr,
                                             q16, (float*)k16, v, DD, DD);

        vtrans_kernel<<<dim3(SS / 64, BB * HH), 256>>>(v, vph, vpl);

        flash_attn_kernel<<<dim3(SS / 64, BB * HH), 128>>>(q16, k16, vph, vpl, tmp16);

        mma_gemm<1,false><<<gD, 256, gs>>>(tmp16, Wo, Wo, Wo, x, x,
                                           nullptr, nullptr, DD, DD);

        layernorm_kernel<<<NTOK, 256>>>(x, ln2_w + l * DD, ln2_b + l * DD, h16);
        mma_gemm<2,false><<<gF, 256, gs>>>(h16, W1, W1, W1, nullptr, ff16,
                                           nullptr, nullptr, DFF, DD);
        mma_gemm<1,false><<<gD, 256, gs>>>(ff16, W2, W2, W2, x, x,
                                           nullptr, nullptr, DD, DFF);
    }

    layernorm_kernel<<<NTOK, 256>>>(x, lnf_w, lnf_b, h16);
    mma_gemm<0,true><<<dim3((VV + 127) / 128, NTOK / 128, 1), 256, gs>>>(
        h16, wte16, wte16, wte16, nullptr, out, nullptr, nullptr, VV, DD);
}

// round 11
// speedup vs baseline: 2.4275x; 1.0297x over previous
#include <cuda_runtime.h>
#include <cuda_bf16.h>
#include <cuda_fp16.h>
#include <math.h>
#include <stdint.h>

// ---------------- problem constants ----------------
#define BB 4
#define SS 1024
#define LL 12
#define DD 768
#define HH 12
#define DKK 64
#define DFF 3072
#define VV 50257
#define NTOK (BB*SS)          // 4096
#define KPD (DD/2)            // 384
#define KPF (DFF/2)           // 1536

// ---------------- scratch (device globals; no allocs allowed) --------------
__device__ float g_x [(size_t)NTOK * DD];
__device__ float g_v [(size_t)NTOK * DD];
__device__ unsigned g_q16 [(size_t)NTOK * KPD];
__device__ unsigned g_k16 [(size_t)NTOK * KPD];
__device__ unsigned g_h16 [(size_t)NTOK * KPD];
__device__ unsigned g_tmp16[(size_t)NTOK * KPD];
__device__ unsigned g_ff16 [(size_t)NTOK * KPF];
__device__ unsigned g_vph [(size_t)BB * HH * DKK * (SS/2)];
__device__ unsigned g_vpl [(size_t)BB * HH * DKK * (SS/2)];
// packed fp16 weights, K-major: [L][N][K/2] half2 words
__device__ unsigned g_wq16 [(size_t)LL * DD * KPD];
__device__ unsigned g_wk16 [(size_t)LL * DD * KPD];
__device__ unsigned g_wv16 [(size_t)LL * DD * KPD];
__device__ unsigned g_wo16 [(size_t)LL * DD * KPD];
__device__ unsigned g_fc116[(size_t)LL * DFF * KPD];
__device__ unsigned g_fc216[(size_t)LL * DD * KPF];
__device__ unsigned g_wte16[(size_t)VV * KPD];

// ---------------- helpers ----------------
__device__ __forceinline__ uint32_t smem_u32(const void* p) {
    uint32_t a;
    asm("{ .reg .u64 t; cvta.to.shared.u64 t, %1; cvt.u32.u64 %0, t; }"
        : "=r"(a) : "l"(p));
    return a;
}
__device__ __forceinline__ void mma16(float* d, const unsigned* a, const unsigned* b) {
    asm volatile(
        "mma.sync.aligned.m16n8k16.row.col.f32.f16.f16.f32 "
        "{%0,%1,%2,%3},{%4,%5,%6,%7},{%8,%9},{%0,%1,%2,%3};"
        : "+f"(d[0]), "+f"(d[1]), "+f"(d[2]), "+f"(d[3])
        : "r"(a[0]), "r"(a[1]), "r"(a[2]), "r"(a[3]), "r"(b[0]), "r"(b[1]));
}
#define LDSM4(r0, r1, r2, r3, addr) \
    asm volatile("ldmatrix.sync.aligned.m8n8.x4.shared.b16 {%0,%1,%2,%3}, [%4];" \
                 : "=r"(r0), "=r"(r1), "=r"(r2), "=r"(r3) : "r"(addr))
__device__ __forceinline__ unsigned packh2(float lo, float hi) {
    __half2 h = __floats2half2_rn(lo, hi);
    return *reinterpret_cast<unsigned*>(&h);
}
__device__ __forceinline__ void cp16(uint32_t d, const void* g) {
    asm volatile("cp.async.cg.shared.global [%0], [%1], 16;" :: "r"(d), "l"(g));
}
__device__ __forceinline__ void cp16g(uint32_t d, const void* g, int sz) {
    asm volatile("cp.async.cg.shared.global [%0], [%1], 16, %2;"
                 :: "r"(d), "l"(g), "r"(sz));
}

// ---------------- weight packing (once per replay) ----------------
__global__ void pack_t(const float* __restrict__ W, unsigned* __restrict__ out,
                       int K, int N)
{
    __shared__ float t[64][65];
    const int n0 = blockIdx.x * 64, k0 = blockIdx.y * 64, l = blockIdx.z;
    const float* Wl = W + (size_t)l * K * N;
    unsigned* ol = out + (size_t)l * N * (K >> 1);
    const int tid = threadIdx.x;
    #pragma unroll
    for (int p = 0; p < 16; p++) {
        int idx = tid + p * 256;
        int kk = idx >> 6, nn = idx & 63;
        t[kk][nn] = Wl[(size_t)(k0 + kk) * N + n0 + nn];
    }
    __syncthreads();
    #pragma unroll
    for (int p = 0; p < 8; p++) {
        int idx = tid + p * 256;
        int nn = idx >> 5, kp = idx & 31;
        ol[(size_t)(n0 + nn) * (K >> 1) + (k0 >> 1) + kp] =
            packh2(t[2 * kp][nn], t[2 * kp + 1][nn]);
    }
}
__global__ void pack_nk(const float* __restrict__ W, unsigned* __restrict__ out,
                        int total)
{
    int i = blockIdx.x * 256 + threadIdx.x;
    if (i >= total) return;
    int v = i / KPD, kp = i - v * KPD;
    float2 f = *(const float2*)(W + (size_t)v * DD + 2 * kp);
    out[i] = packh2(f.x, f.y);
}

// ---------------- V transpose: f32 [row][D] -> fp16 hi/lo [bh*64+dk][jpair] --
__global__ void vtrans_kernel(const float* __restrict__ v,
                              unsigned* __restrict__ vph,
                              unsigned* __restrict__ vpl)
{
    __shared__ float t[64][65];
    const int j0 = blockIdx.x * 64;
    const int bh = blockIdx.y;
    const int b = bh / HH, h = bh % HH;
    const int tid = threadIdx.x;
    #pragma unroll
    for (int p = 0; p < 16; p++) {
        int idx = tid + p * 256;
        int j = idx >> 6, dk = idx & 63;
        t[j][dk] = v[(size_t)(b * SS + j0 + j) * DD + h * DKK + dk];
    }
    __syncthreads();
    #pragma unroll
    for (int p = 0; p < 8; p++) {
        int idx = tid + p * 256;
        int dk = idx >> 5, jp = idx & 31;
        float v0 = t[2 * jp][dk], v1 = t[2 * jp + 1][dk];
        __half h0 = __float2half_rn(v0), h1 = __float2half_rn(v1);
        float l0 = v0 - __half2float(h0), l1 = v1 - __half2float(h1);
        __half2 hh = __halves2half2(h0, h1);
        size_t o = ((size_t)bh * DKK + dk) * (SS / 2) + (j0 >> 1) + jp;
        vph[o] = *reinterpret_cast<unsigned*>(&hh);
        vpl[o] = packh2(l0, l1);
    }
}

// ---------------- fp16 NT GEMM: ldmatrix + cp.async, BK=64, 3-stage --------
// (unchanged from R10)
#define APAD 36
#define AW (128 * APAD)
#define STG (2 * AW)

template<int EPI, bool NG>
__global__ __launch_bounds__(256, 2)
void mma_gemm(const unsigned* __restrict__ A,
              const unsigned* __restrict__ B0, const unsigned* __restrict__ B1,
              const unsigned* __restrict__ B2,
              const float* __restrict__ Cin, void* __restrict__ Cv,
              float* __restrict__ C1f, float* __restrict__ C2f,
              int N, int K)
{
    extern __shared__ unsigned gsm[];

    const unsigned* B = (blockIdx.z == 0) ? B0 : ((blockIdx.z == 1) ? B1 : B2);
    float* Cf = (blockIdx.z == 0) ? (float*)Cv : ((blockIdx.z == 1) ? C1f : C2f);
    unsigned* C16 = (unsigned*)Cv;

    const int tid  = threadIdx.x;
    const int lane = tid & 31;
    const int warp = tid >> 5;
    const int wm = warp >> 2, wn = warp & 3;
    const int lr = lane >> 2, lq = lane & 3;
    const int m0 = blockIdx.y * 128;
    const int n0 = blockIdx.x * 128;
    const int KA = K >> 1;

    const uint32_t sbase = smem_u32(gsm);
    const int lrow = lane & 7, lg = lane >> 3;
    const uint32_t aoff = (uint32_t)(((wm * 64 + (lg & 1) * 8 + lrow) * APAD
                                      + (lg >> 1) * 4) * 4);
    const uint32_t boff = (uint32_t)(((wn * 32 + (lg >> 1) * 8 + lrow) * APAD
                                      + (lg & 1) * 4) * 4);

    float acc[4][4][4];
    #pragma unroll
    for (int i = 0; i < 4; i++)
        #pragma unroll
        for (int j = 0; j < 4; j++)
            #pragma unroll
            for (int t = 0; t < 4; t++) acc[i][j][t] = 0.0f;

    auto load_stage = [&](int stg) {
        const int slot = stg % 3;
        const uint32_t sa = sbase + (uint32_t)(slot * STG) * 4u;
        const uint32_t sb = sa + (uint32_t)AW * 4u;
        const int kp0 = stg * 32;
        #pragma unroll
        for (int p = 0; p < 4; p++) {
            int s = tid + p * 256;
            int r = s >> 3, c4 = (s & 7) * 4;
            cp16(sa + (uint32_t)(r * APAD + c4) * 4u,
                 A + (size_t)(m0 + r) * KA + kp0 + c4);
        }
        #pragma unroll
        for (int p = 0; p < 4; p++) {
            int s = tid + p * 256;
            int r = s >> 3, c4 = (s & 7) * 4;
            if (NG) {
                int n = n0 + r;
                int ok = (n < N);
                cp16g(sb + (uint32_t)(r * APAD + c4) * 4u,
                      B + (size_t)(ok ? n : 0) * KA + kp0 + c4, ok ? 16 : 0);
            } else {
                cp16(sb + (uint32_t)(r * APAD + c4) * 4u,
                     B + (size_t)(n0 + r) * KA + kp0 + c4);
            }
        }
        asm volatile("cp.async.commit_group;" ::: "memory");
    };

    auto compute = [&](int slot) {
        const uint32_t sa = sbase + (uint32_t)(slot * STG) * 4u;
        const uint32_t sb = sa + (uint32_t)AW * 4u;
        #pragma unroll
        for (int kc = 0; kc < 4; kc++) {
            const uint32_t kbb = (uint32_t)(kc * 32);
            unsigned af[4][4];
            #pragma unroll
            for (int mt = 0; mt < 4; mt++) {
                uint32_t addr = sa + aoff + kbb + (uint32_t)(mt * 16 * APAD * 4);
                LDSM4(af[mt][0], af[mt][1], af[mt][2], af[mt][3], addr);
            }
            unsigned bf[4][2];
            #pragma unroll
            for (int np = 0; np < 2; np++) {
                uint32_t addr = sb + boff + kbb + (uint32_t)(np * 16 * APAD * 4);
                unsigned r0, r1, r2, r3;
                LDSM4(r0, r1, r2, r3, addr);
                bf[np * 2][0] = r0;     bf[np * 2][1] = r1;
                bf[np * 2 + 1][0] = r2; bf[np * 2 + 1][1] = r3;
            }
            #pragma unroll
            for (int mt = 0; mt < 4; mt++)
                #pragma unroll
                for (int nt = 0; nt < 4; nt++)
                    mma16(acc[mt][nt], af[mt], bf[nt]);
        }
    };

    const int nIter = K >> 6;
    load_stage(0);
    load_stage(1);
    for (int it = 0; it < nIter; it++) {
        if (it + 1 < nIter) asm volatile("cp.async.wait_group 1;" ::: "memory");
        else                asm volatile("cp.async.wait_group 0;" ::: "memory");
        __syncthreads();
        if (it + 2 < nIter) load_stage(it + 2);
        compute(it % 3);
    }

    #pragma unroll
    for (int mt = 0; mt < 4; mt++) {
        int r0 = m0 + wm * 64 + mt * 16 + lr;
        #pragma unroll
        for (int nt = 0; nt < 4; nt++) {
            int col = n0 + wn * 32 + nt * 8 + lq * 2;
            float* a4 = acc[mt][nt];
            float v00 = a4[0], v01 = a4[1], v10 = a4[2], v11 = a4[3];
            if (EPI == 2) {
                v00 = 0.5f * v00 * (1.0f + erff(v00 * 0.70710678118654752f));
                v01 = 0.5f * v01 * (1.0f + erff(v01 * 0.70710678118654752f));
                v10 = 0.5f * v10 * (1.0f + erff(v10 * 0.70710678118654752f));
                v11 = 0.5f * v11 * (1.0f + erff(v11 * 0.70710678118654752f));
                int nw = N >> 1;
                C16[(size_t)r0 * nw + (col >> 1)]       = packh2(v00, v01);
                C16[(size_t)(r0 + 8) * nw + (col >> 1)] = packh2(v10, v11);
            } else if (EPI == 3) {
                if (blockIdx.z == 2) {
                    size_t o0 = (size_t)r0 * N + col;
                    size_t o1 = (size_t)(r0 + 8) * N + col;
                    *(float2*)(C2f + o0) = make_float2(v00, v01);
                    *(float2*)(C2f + o1) = make_float2(v10, v11);
                } else {
                    unsigned* o = (blockIdx.z == 0) ? (unsigned*)Cv : (unsigned*)C1f;
                    int nw = N >> 1;
                    o[(size_t)r0 * nw + (col >> 1)]       = packh2(v00, v01);
                    o[(size_t)(r0 + 8) * nw + (col >> 1)] = packh2(v10, v11);
                }
            } else {
                size_t o0 = (size_t)r0 * N + col;
                size_t o1 = (size_t)(r0 + 8) * N + col;
                if (EPI == 1) {
                    float2 c0 = *(const float2*)(Cin + o0);
                    float2 c1 = *(const float2*)(Cin + o1);
                    v00 += c0.x; v01 += c0.y; v10 += c1.x; v11 += c1.y;
                }
                if (!NG) {
                    *(float2*)(Cf + o0) = make_float2(v00, v01);
                    *(float2*)(Cf + o1) = make_float2(v10, v11);
                } else {
                    if (col < N)     { Cf[o0] = v00;     Cf[o1] = v10; }
                    if (col + 1 < N) { Cf[o0 + 1] = v01; Cf[o1 + 1] = v11; }
                }
            }
        }
    }
}

// ---------------- embedding ----------------
__global__ void embed_kernel(const int* __restrict__ idx,
                             const float* __restrict__ wte,
                             const float* __restrict__ wpe,
                             float* __restrict__ x)
{
    int row = blockIdx.x;
    int s   = row & (SS - 1);
    int tok = idx[row];
    int tid = threadIdx.x;
    #pragma unroll
    for (int l = 0; l < 3; l++) {
        int d = tid + l * 256;
        x[(size_t)row * DD + d] = wte[(size_t)tok * DD + d] + wpe[(size_t)s * DD + d];
    }
}

// ---------------- layernorm -> packed fp16 (shuffle reductions) ------------
__global__ void layernorm_kernel(const float* __restrict__ x,
                                 const float* __restrict__ w,
                                 const float* __restrict__ b,
                                 unsigned* __restrict__ y16)
{
    int row = blockIdx.x;
    const float2* p2 = (const float2*)(x + (size_t)row * DD);
    int tid = threadIdx.x;                 // 256
    int lane = tid & 31, wid = tid >> 5;
    float2 f1 = p2[tid];
    float2 f2 = (tid < 128) ? p2[tid + 256] : make_float2(0.f, 0.f);

    __shared__ float ws[8], ws2[8];
    float s = f1.x + f1.y + f2.x + f2.y;
    #pragma unroll
    for (int o = 16; o > 0; o >>= 1) s += __shfl_xor_sync(0xffffffffu, s, o);
    if (lane == 0) ws[wid] = s;
    __syncthreads();
    float mean = (ws[0] + ws[1] + ws[2] + ws[3] + ws[4] + ws[5] + ws[6] + ws[7])
                 * (1.0f / DD);

    float a0 = f1.x - mean, a1 = f1.y - mean;
    float a2 = f2.x - mean, a3 = f2.y - mean;
    float sq = a0 * a0 + a1 * a1 + ((tid < 128) ? (a2 * a2 + a3 * a3) : 0.f);
    #pragma unroll
    for (int o = 16; o > 0; o >>= 1) sq += __shfl_xor_sync(0xffffffffu, sq, o);
    if (lane == 0) ws2[wid] = sq;
    __syncthreads();
    float var = (ws2[0] + ws2[1] + ws2[2] + ws2[3] + ws2[4] + ws2[5] + ws2[6] + ws2[7])
                * (1.0f / DD);
    float rstd = rsqrtf(var + 1e-5f);

    const float2* w2 = (const float2*)w;
    const float2* b2 = (const float2*)b;
    unsigned* yr = y16 + (size_t)row * KPD;
    {
        float2 ww = w2[tid], bb = b2[tid];
        yr[tid] = packh2(a0 * rstd * ww.x + bb.x, a1 * rstd * ww.y + bb.y);
    }
    if (tid < 128) {
        float2 ww = w2[tid + 256], bb = b2[tid + 256];
        yr[tid + 256] = packh2(a2 * rstd * ww.x + bb.x, a3 * rstd * ww.y + bb.y);
    }
}

// ---------------- fused flash attention (fp16, double-buffered KV) ---------
#define FST 36   // smem row stride (32 words + 4 pad)
#define FQW (64 * FST)          // Q tile words
#define FBW (3 * 64 * FST)      // per-buffer words (K, Vh, Vl)
#define FA_SMEM_BYTES ((FQW + 2 * FBW) * 4)   // 64512

__global__ __launch_bounds__(128, 3)
void flash_attn_kernel(const unsigned* __restrict__ q16,
                       const unsigned* __restrict__ k16,
                       const unsigned* __restrict__ vph,
                       const unsigned* __restrict__ vpl,
                       unsigned* __restrict__ O16)
{
    extern __shared__ unsigned fsm[];

    const int tid  = threadIdx.x;
    const int lane = tid & 31;
    const int w    = tid >> 5;
    const int lr   = lane >> 2;
    const int lq   = lane & 3;
    const int it   = (SS / 64 - 1) - blockIdx.x;   // heavy tiles first
    const int bh   = blockIdx.y;
    const int b    = bh / HH, h = bh % HH;
    const int i0   = it * 64;
    const int lrow = lane & 7, lg = lane >> 3;

    const uint32_t sQb = smem_u32(fsm);
    const uint32_t aoff = (uint32_t)(((w * 16 + (lg & 1) * 8 + lrow) * FST
                                      + (lg >> 1) * 4) * 4);
    const uint32_t boff = (uint32_t)((((lg >> 1) * 8 + lrow) * FST
                                      + (lg & 1) * 4) * 4);

    auto load_tile = [&](int j0, int buf) {
        const uint32_t kb  = sQb + (uint32_t)(FQW + buf * FBW) * 4u;
        const uint32_t vhb = kb + (uint32_t)(64 * FST) * 4u;
        const uint32_t vlb = vhb + (uint32_t)(64 * FST) * 4u;
        #pragma unroll
        for (int p = 0; p < 4; p++) {
            int s = tid + p * 128;
            int r = s >> 3, c4 = (s & 7) * 4;
            cp16(kb + (uint32_t)(r * FST + c4) * 4u,
                 k16 + (size_t)(b * SS + j0 + r) * KPD + h * 32 + c4);
            size_t vo = ((size_t)bh * DKK + r) * (SS / 2) + (j0 >> 1) + c4;
            cp16(vhb + (uint32_t)(r * FST + c4) * 4u, vph + vo);
            cp16(vlb + (uint32_t)(r * FST + c4) * 4u, vpl + vo);
        }
        asm volatile("cp.async.commit_group;" ::: "memory");
    };

    // ---- load Q (group) then tile 0 (group) ----
    #pragma unroll
    for (int p = 0; p < 4; p++) {
        int s = tid + p * 128;
        int r = s >> 3, c4 = (s & 7) * 4;
        cp16(sQb + (uint32_t)(r * FST + c4) * 4u,
             q16 + (size_t)(b * SS + i0 + r) * KPD + h * 32 + c4);
    }
    asm volatile("cp.async.commit_group;" ::: "memory");
    load_tile(0, 0);
    asm volatile("cp.async.wait_group 1;" ::: "memory");   // Q ready
    __syncthreads();

    unsigned qf[4][4];
    #pragma unroll
    for (int kc = 0; kc < 4; kc++)
        LDSM4(qf[kc][0], qf[kc][1], qf[kc][2], qf[kc][3], sQb + aoff + kc * 32);

    float oacc[8][4];
    #pragma unroll
    for (int nt = 0; nt < 8; nt++)
        #pragma unroll
        for (int e = 0; e < 4; e++) oacc[nt][e] = 0.0f;
    float m0 = -1e30f, m1 = -1e30f, l0 = 0.0f, l1 = 0.0f;

    int buf = 0;
    for (int j0 = 0; j0 <= i0; j0 += 64) {
        __syncthreads();                       // prev compute done with buf^1
        const bool more = (j0 + 64 <= i0);
        if (more) load_tile(j0 + 64, buf ^ 1);
        if (more) asm volatile("cp.async.wait_group 1;" ::: "memory");
        else      asm volatile("cp.async.wait_group 0;" ::: "memory");
        __syncthreads();

        const uint32_t kb  = sQb + (uint32_t)(FQW + buf * FBW) * 4u;
        const uint32_t vhb = kb + (uint32_t)(64 * FST) * 4u;
        const uint32_t vlb = vhb + (uint32_t)(64 * FST) * 4u;

        // ---- S = Q @ K^T ----
        float sacc[8][4];
        #pragma unroll
        for (int nt = 0; nt < 8; nt++)
            #pragma unroll
            for (int e = 0; e < 4; e++) sacc[nt][e] = 0.0f;
        #pragma unroll
        for (int kc = 0; kc < 4; kc++) {
            #pragma unroll
            for (int nb = 0; nb < 4; nb++) {
                unsigned r0, r1, r2, r3;
                LDSM4(r0, r1, r2, r3,
                      kb + boff + (uint32_t)(nb * 16 * FST * 4) + kc * 32);
                unsigned b0[2] = {r0, r1}, b1[2] = {r2, r3};
                mma16(sacc[nb * 2],     qf[kc], b0);
                mma16(sacc[nb * 2 + 1], qf[kc], b1);
            }
        }

        // ---- scale + causal mask ----
        #pragma unroll
        for (int nt = 0; nt < 8; nt++)
            #pragma unroll
            for (int e = 0; e < 4; e++) sacc[nt][e] *= 0.125f;
        if (j0 == i0) {
            int ii0 = w * 16 + lr, ii1 = ii0 + 8;
            #pragma unroll
            for (int nt = 0; nt < 8; nt++) {
                int jj = nt * 8 + 2 * lq;
                if (jj     > ii0) sacc[nt][0] = -1e30f;
                if (jj + 1 > ii0) sacc[nt][1] = -1e30f;
                if (jj     > ii1) sacc[nt][2] = -1e30f;
                if (jj + 1 > ii1) sacc[nt][3] = -1e30f;
            }
        }

        // ---- online softmax ----
        float rm0 = -1e30f, rm1 = -1e30f;
        #pragma unroll
        for (int nt = 0; nt < 8; nt++) {
            rm0 = fmaxf(rm0, fmaxf(sacc[nt][0], sacc[nt][1]));
            rm1 = fmaxf(rm1, fmaxf(sacc[nt][2], sacc[nt][3]));
        }
        rm0 = fmaxf(rm0, __shfl_xor_sync(0xffffffffu, rm0, 1));
        rm0 = fmaxf(rm0, __shfl_xor_sync(0xffffffffu, rm0, 2));
        rm1 = fmaxf(rm1, __shfl_xor_sync(0xffffffffu, rm1, 1));
        rm1 = fmaxf(rm1, __shfl_xor_sync(0xffffffffu, rm1, 2));
        float mn0 = fmaxf(m0, rm0), mn1 = fmaxf(m1, rm1);
        float f0 = __expf(m0 - mn0), f1 = __expf(m1 - mn1);
        float ps0 = 0.0f, ps1 = 0.0f;
        #pragma unroll
        for (int nt = 0; nt < 8; nt++) {
            float p0 = __expf(sacc[nt][0] - mn0); sacc[nt][0] = p0; ps0 += p0;
            float p1 = __expf(sacc[nt][1] - mn0); sacc[nt][1] = p1; ps0 += p1;
            float p2 = __expf(sacc[nt][2] - mn1); sacc[nt][2] = p2; ps1 += p2;
            float p3 = __expf(sacc[nt][3] - mn1); sacc[nt][3] = p3; ps1 += p3;
        }
        ps0 += __shfl_xor_sync(0xffffffffu, ps0, 1);
        ps0 += __shfl_xor_sync(0xffffffffu, ps0, 2);
        ps1 += __shfl_xor_sync(0xffffffffu, ps1, 1);
        ps1 += __shfl_xor_sync(0xffffffffu, ps1, 2);
        l0 = l0 * f0 + ps0;
        l1 = l1 * f1 + ps1;
        m0 = mn0; m1 = mn1;
        #pragma unroll
        for (int nt = 0; nt < 8; nt++) {
            oacc[nt][0] *= f0; oacc[nt][1] *= f0;
            oacc[nt][2] *= f1; oacc[nt][3] *= f1;
        }

        // ---- O += P @ V (compensated fp16; P frags direct from regs) ----
        #pragma unroll
        for (int kc = 0; kc < 4; kc++) {
            unsigned ah[4], al[4];
            #pragma unroll
            for (int hsel = 0; hsel < 2; hsel++) {
                const float* s0 = sacc[2 * kc + hsel];
                unsigned hi0 = packh2(s0[0], s0[1]);
                unsigned hi1 = packh2(s0[2], s0[3]);
                __half2 h2a = *reinterpret_cast<__half2*>(&hi0);
                __half2 h2b = *reinterpret_cast<__half2*>(&hi1);
                float2 fa = __half22float2(h2a);
                float2 fb = __half22float2(h2b);
                ah[hsel * 2]     = hi0;
                ah[hsel * 2 + 1] = hi1;
                al[hsel * 2]     = packh2(s0[0] - fa.x, s0[1] - fa.y);
                al[hsel * 2 + 1] = packh2(s0[2] - fb.x, s0[3] - fb.y);
            }
            #pragma unroll
            for (int nb = 0; nb < 4; nb++) {
                uint32_t va = boff + (uint32_t)(nb * 16 * FST * 4) + kc * 32;
                unsigned h0, h1, h2, h3, g0, g1, g2, g3;
                LDSM4(h0, h1, h2, h3, vhb + va);
                LDSM4(g0, g1, g2, g3, vlb + va);
                unsigned bh0[2] = {h0, h1}, bh1[2] = {h2, h3};
                unsigned bl0[2] = {g0, g1}, bl1[2] = {g2, g3};
                mma16(oacc[nb * 2],     ah, bh0);
                mma16(oacc[nb * 2],     al, bh0);
                mma16(oacc[nb * 2],     ah, bl0);
                mma16(oacc[nb * 2 + 1], ah, bh1);
                mma16(oacc[nb * 2 + 1], al, bh1);
                mma16(oacc[nb * 2 + 1], ah, bl1);
            }
        }
        buf ^= 1;
    }

    // ---- epilogue: packed fp16 output ----
    float inv0 = 1.0f / l0, inv1 = 1.0f / l1;
    int row0 = b * SS + i0 + w * 16 + lr;
    unsigned* Ob = O16 + (size_t)row0 * KPD + h * 32;
    #pragma unroll
    for (int nt = 0; nt < 8; nt++) {
        Ob[nt * 4 + lq] = packh2(oacc[nt][0] * inv0, oacc[nt][1] * inv0);
        Ob[(size_t)8 * KPD + nt * 4 + lq] = packh2(oacc[nt][2] * inv1, oacc[nt][3] * inv1);
    }
}

// ---------------- host launcher ----------------
extern "C" void kernel_launch(void* const* d_in, const int* in_sizes, int n_in,
                              void* d_out, int out_size)
{
    const int*   idx   = (const int*)  d_in[0];
    const float* wte   = (const float*)d_in[1];
    const float* wpe   = (const float*)d_in[2];
    const float* ln1_w = (const float*)d_in[3];
    const float* ln1_b = (const float*)d_in[4];
    const float* wq    = (const float*)d_in[5];
    const float* wk    = (const float*)d_in[6];
    const float* wv    = (const float*)d_in[7];
    const float* wo    = (const float*)d_in[8];
    const float* ln2_w = (const float*)d_in[9];
    const float* ln2_b = (const float*)d_in[10];
    const float* fc1   = (const float*)d_in[11];
    const float* fc2   = (const float*)d_in[12];
    const float* lnf_w = (const float*)d_in[13];
    const float* lnf_b = (const float*)d_in[14];
    float* out = (float*)d_out;

    float *x, *v;
    unsigned *q16, *k16, *h16, *tmp16, *ff16, *vph, *vpl;
    unsigned *wq16, *wk16, *wv16, *wo16, *fc116, *fc216, *wte16;
    cudaGetSymbolAddress((void**)&x,     g_x);
    cudaGetSymbolAddress((void**)&v,     g_v);
    cudaGetSymbolAddress((void**)&q16,   g_q16);
    cudaGetSymbolAddress((void**)&k16,   g_k16);
    cudaGetSymbolAddress((void**)&h16,   g_h16);
    cudaGetSymbolAddress((void**)&tmp16, g_tmp16);
    cudaGetSymbolAddress((void**)&ff16,  g_ff16);
    cudaGetSymbolAddress((void**)&vph,   g_vph);
    cudaGetSymbolAddress((void**)&vpl,   g_vpl);
    cudaGetSymbolAddress((void**)&wq16,  g_wq16);
    cudaGetSymbolAddress((void**)&wk16,  g_wk16);
    cudaGetSymbolAddress((void**)&wv16,  g_wv16);
    cudaGetSymbolAddress((void**)&wo16,  g_wo16);
    cudaGetSymbolAddress((void**)&fc116, g_fc116);
    cudaGetSymbolAddress((void**)&fc216, g_fc216);
    cudaGetSymbolAddress((void**)&wte16, g_wte16);

    const int gs = 3 * STG * 4;      // 110592 bytes
    cudaFuncSetAttribute(mma_gemm<0,false>, cudaFuncAttributeMaxDynamicSharedMemorySize, gs);
    cudaFuncSetAttribute(mma_gemm<1,false>, cudaFuncAttributeMaxDynamicSharedMemorySize, gs);
    cudaFuncSetAttribute(mma_gemm<2,false>, cudaFuncAttributeMaxDynamicSharedMemorySize, gs);
    cudaFuncSetAttribute(mma_gemm<3,false>, cudaFuncAttributeMaxDynamicSharedMemorySize, gs);
    cudaFuncSetAttribute(mma_gemm<0,true>,  cudaFuncAttributeMaxDynamicSharedMemorySize, gs);
    cudaFuncSetAttribute(flash_attn_kernel,
                         cudaFuncAttributeMaxDynamicSharedMemorySize, FA_SMEM_BYTES);

    pack_t<<<dim3(DD / 64, DD / 64, LL), 256>>>(wq, wq16, DD, DD);
    pack_t<<<dim3(DD / 64, DD / 64, LL), 256>>>(wk, wk16, DD, DD);
    pack_t<<<dim3(DD / 64, DD / 64, LL), 256>>>(wv, wv16, DD, DD);
    pack_t<<<dim3(DD / 64, DD / 64, LL), 256>>>(wo, wo16, DD, DD);
    pack_t<<<dim3(DFF / 64, DD / 64, LL), 256>>>(fc1, fc116, DD, DFF);
    pack_t<<<dim3(DD / 64, DFF / 64, LL), 256>>>(fc2, fc216, DFF, DD);
    {
        int tE = VV * KPD;
        pack_nk<<<(tE + 255) / 256, 256>>>(wte, wte16, tE);
    }

    embed_kernel<<<NTOK, 256>>>(idx, wte, wpe, x);

    dim3 gQKV(DD / 128, NTOK / 128, 3);
    dim3 gD  (DD / 128, NTOK / 128, 1);
    dim3 gF  (DFF / 128, NTOK / 128, 1);

    for (int l = 0; l < LL; l++) {
        unsigned* Wq = wq16 + (size_t)l * DD * KPD;
        unsigned* Wk = wk16 + (size_t)l * DD * KPD;
        unsigned* Wv = wv16 + (size_t)l * DD * KPD;
        unsigned* Wo = wo16 + (size_t)l * DD * KPD;
        unsigned* W1 = fc116 + (size_t)l * DFF * KPD;
        unsigned* W2 = fc216 + (size_t)l * DD * KPF;

        layernorm_kernel<<<NTOK, 256>>>(x, ln1_w + l * DD, ln1_b + l * DD, h16);

        mma_gemm<3,false><<<gQKV, 256, gs>>>(h16, Wq, Wk, Wv, nullptr,
                                             q16, (float*)k16, v, DD, DD);

        vtrans_kernel<<<dim3(SS / 64, BB * HH), 256>>>(v, vph, vpl);

        flash_attn_kernel<<<dim3(SS / 64, BB * HH), 128, FA_SMEM_BYTES>>>(
            q16, k16, vph, vpl, tmp16);

        mma_gemm<1,false><<<gD, 256, gs>>>(tmp16, Wo, Wo, Wo, x, x,
                                           nullptr, nullptr, DD, DD);

        layernorm_kernel<<<NTOK, 256>>>(x, ln2_w + l * DD, ln2_b + l * DD, h16);
        mma_gemm<2,false><<<gF, 256, gs>>>(h16, W1, W1, W1, nullptr, ff16,
                                           nullptr, nullptr, DFF, DD);
        mma_gemm<1,false><<<gD, 256, gs>>>(ff16, W2, W2, W2, x, x,
                                           nullptr, nullptr, DD, DFF);
    }

    layernorm_kernel<<<NTOK, 256>>>(x, lnf_w, lnf_b, h16);
    mma_gemm<0,true><<<dim3((VV + 127) / 128, NTOK / 128, 1), 256, gs>>>(
        h16, wte16, wte16, wte16, nullptr, out, nullptr, nullptr, VV, DD);
}